// round 7
// baseline (speedup 1.0000x reference)
#include <cuda_runtime.h>
#include <cuda_bf16.h>
#include <stdint.h>
#include <math.h>

#define NN    100000
#define NE    1600000
#define NG    512
#define HID   200
#define H3    600
#define INDIM 205

#define KP    208      // padded K per section
#define K3    624      // 3*KP
#define NCH   78       // K3/8 chunks
#define NSTEP 39       // K3/16

// ---------------- scratch (device globals; no runtime alloc) ----------------
__device__ float g_h  [(size_t)NN * HID];
__device__ float g_m  [(size_t)NN * HID];
__device__ float g_agg[(size_t)NN * HID];
__device__ float g_gi [(size_t)NN * H3];
__device__ float g_gh [(size_t)NN * H3];
__device__ float g_pool[NG * 2 * HID];
__device__ float g_cnt [NG];
__device__ float g_fc1 [NG * HID];
__device__ float g_scale[3 * HID];
__device__ float g_shift[3 * HID];
__device__ int   g_src[NE];
__device__ int   g_dst[NE];
__device__ int   g_batch[NN];
__device__ int   g_flag_e;
__device__ int   g_flag_b;

// bf16 split buffers
__device__ __nv_bfloat16 g_xs[(size_t)NN * K3];
__device__ __nv_bfloat16 g_hs[(size_t)NN * K3];
__device__ __nv_bfloat16 g_as[(size_t)NN * K3];
__device__ __nv_bfloat16 g_Bproj[256 * K3];
__device__ __nv_bfloat16 g_Bggc [3][256 * K3];
__device__ __nv_bfloat16 g_Bwih [768 * K3];
__device__ __nv_bfloat16 g_Bwhh [768 * K3];

// ---------------- dtype detection (int64 vs int32), warp-parallel ----------
__global__ void k_detect(const int* __restrict__ ew, const int* __restrict__ bw) {
    int lane = threadIdx.x;
    int bad_e = 0, bad_b = 0;
    for (int w = 2 * NE - 255 + 2 * lane; w < 2 * NE; w += 64)
        if (ew[w] != 0) bad_e = 1;
    for (int w = NN - 255 + 2 * lane; w < NN; w += 64)
        if (bw[w] != 0) bad_b = 1;
    unsigned me = __ballot_sync(0xFFFFFFFFu, bad_e);
    unsigned mb = __ballot_sync(0xFFFFFFFFu, bad_b);
    if (lane == 0) { g_flag_e = (me == 0); g_flag_b = (mb == 0); }
}

__global__ void k_conv_edges(const void* __restrict__ e) {
    int i = blockIdx.x * blockDim.x + threadIdx.x;
    if (i >= 2 * NE) return;
    int v = g_flag_e ? (int)((const long long*)e)[i] : ((const int*)e)[i];
    if (i < NE) g_src[i] = v; else g_dst[i - NE] = v;
}

__global__ void k_conv_batch(const void* __restrict__ b) {
    int i = blockIdx.x * blockDim.x + threadIdx.x;
    if (i >= NN) return;
    g_batch[i] = g_flag_b ? (int)((const long long*)b)[i] : ((const int*)b)[i];
}

// ---------------- merged BN param prep ----------------
__global__ void k_bnprep_all(
    const float* g1, const float* b1, const float* m1, const float* v1,
    const float* g2, const float* b2, const float* m2, const float* v2,
    const float* gf, const float* bf, const float* mf, const float* vf) {
    int j = threadIdx.x;
    if (j >= 3 * HID) return;
    int which = j / HID, jj = j - which * HID;
    const float *g, *b, *m, *v;
    if (which == 0)      { g = g1; b = b1; m = m1; v = v1; }
    else if (which == 1) { g = g2; b = b2; m = m2; v = v2; }
    else                 { g = gf; b = bf; m = mf; v = vf; }
    float s = g[jj] * rsqrtf(v[jj] + 1e-5f);
    g_scale[j] = s;
    g_shift[j] = b[jj] - m[jj] * s;
}

// ---------------- bf16 split of activations ----------------
__global__ void k_splitA(const float* __restrict__ in, __nv_bfloat16* __restrict__ out,
                         int K) {
    int idx = blockIdx.x * blockDim.x + threadIdx.x;
    if (idx >= NN * NCH) return;
    int m = idx / NCH, ch = idx - (idx / NCH) * NCH;
    int s = ch / 26;
    int k0 = (ch - s * 26) * 8;
    const float* src = in + (size_t)m * K + k0;
    __nv_bfloat16 o[8];
#pragma unroll
    for (int i = 0; i < 8; i++) {
        float v = (k0 + i < K) ? src[i] : 0.f;
        __nv_bfloat16 hi = __float2bfloat16(v);
        o[i] = (s == 1) ? __float2bfloat16(v - __bfloat162float(hi)) : hi;
    }
    *(uint4*)(out + (size_t)m * K3 + ch * 8) = *(const uint4*)o;
}

// ---------------- bf16 split of weights ----------------
__global__ void k_splitB(const float* __restrict__ W, __nv_bfloat16* __restrict__ out,
                         int N, int Npad, int K, int trans) {
    int idx = blockIdx.x * blockDim.x + threadIdx.x;
    if (idx >= Npad * NCH) return;
    int n = idx / NCH, ch = idx - (idx / NCH) * NCH;
    int s = ch / 26;
    int k0 = (ch - s * 26) * 8;
    __nv_bfloat16 o[8];
#pragma unroll
    for (int i = 0; i < 8; i++) {
        int k = k0 + i;
        float v = 0.f;
        if (n < N && k < K) v = trans ? W[(size_t)n * K + k] : W[(size_t)k * N + n];
        __nv_bfloat16 hi = __float2bfloat16(v);
        o[i] = (s == 2) ? __float2bfloat16(v - __bfloat162float(hi)) : hi;
    }
    *(uint4*)(out + (size_t)n * K3 + ch * 8) = *(const uint4*)o;
}

// ---------------- tensor-core GEMM: 128x256 CTA tile ------------------------
// 8 warps (2 m x 4 n), warp tile 64x64 (4 mi x 8 ni m16n8k16), BK=16,
// 2-stage cp.async pipeline (single __syncthreads per step),
// stride-24 smem (48B rows: 16B-aligned for ldmatrix/cp.async, conflict-free).
#define SA_STRIDE 24
#define SB_STRIDE 24
#define NTILE     256

__global__ void __launch_bounds__(256, 1)
k_tgemm(const __nv_bfloat16* __restrict__ A, const __nv_bfloat16* __restrict__ B,
        float* __restrict__ C, int M, int N,
        const float* __restrict__ bias,
        const float* __restrict__ scale, const float* __restrict__ shift,
        int relu) {
    __shared__ __nv_bfloat16 sA[2][128 * SA_STRIDE];
    __shared__ __nv_bfloat16 sB[2][NTILE * SB_STRIDE];

    const int tid  = threadIdx.x;
    const int warp = tid >> 5, lane = tid & 31;
    const int wm = warp & 1, wn = warp >> 1;          // 2 x 4 warps
    const int m0 = blockIdx.y * 128;
    const int n0 = blockIdx.x * NTILE;

    const int arow = tid >> 1;
    const int akc  = (tid & 1) * 8;
    const int brow = tid;

    float acc[4][8][4];
#pragma unroll
    for (int mi = 0; mi < 4; mi++)
#pragma unroll
        for (int ni = 0; ni < 8; ni++)
#pragma unroll
            for (int j = 0; j < 4; j++) acc[mi][ni][j] = 0.f;

    const size_t a_off = (size_t)(m0 + arow) * K3 + akc;
    const size_t b_off = (size_t)(n0 + brow) * K3;
    const int a_valid = (m0 + arow < M) ? 16 : 0;

#define ISSUE_STAGE(st, ks)                                                     \
    do {                                                                        \
        uint32_t d_ = (uint32_t)__cvta_generic_to_shared(                       \
            &sA[st][arow * SA_STRIDE + akc]);                                   \
        asm volatile("cp.async.cg.shared.global [%0], [%1], 16, %2;\n"          \
                     :: "r"(d_), "l"(A + a_off + (ks) * 16), "r"(a_valid));     \
        uint32_t b0_ = (uint32_t)__cvta_generic_to_shared(                      \
            &sB[st][brow * SB_STRIDE]);                                         \
        asm volatile("cp.async.cg.shared.global [%0], [%1], 16, 16;\n"          \
                     :: "r"(b0_), "l"(B + b_off + (ks) * 16));                  \
        asm volatile("cp.async.cg.shared.global [%0], [%1], 16, 16;\n"          \
                     :: "r"(b0_ + 16), "l"(B + b_off + (ks) * 16 + 8));         \
    } while (0)

    ISSUE_STAGE(0, 0);
    asm volatile("cp.async.commit_group;\n");

    const int lr  = lane & 15;
    const int lcb = (lane >> 4) * 8;
    const int bn  = lane >> 2;
    const int bk  = (lane & 3) * 2;

    for (int ks = 0; ks < NSTEP; ks++) {
        // all committed groups complete -> stage ks data resident
        asm volatile("cp.async.wait_group 0;\n");
        __syncthreads();

        // issue stage ks+1 into the other buffer (its last readers were iter
        // ks-1, already past the barrier); overlaps with compute below
        if (ks + 1 < NSTEP) {
            ISSUE_STAGE((ks + 1) & 1, ks + 1);
            asm volatile("cp.async.commit_group;\n");
        }

        const int buf = ks & 1;
        uint32_t a[4][4];
        uint32_t b[8][2];
#pragma unroll
        for (int mi = 0; mi < 4; mi++) {
            uint32_t addr = (uint32_t)__cvta_generic_to_shared(
                &sA[buf][(wm * 64 + mi * 16 + lr) * SA_STRIDE + lcb]);
            asm volatile("ldmatrix.sync.aligned.m8n8.x4.shared.b16 {%0,%1,%2,%3}, [%4];"
                         : "=r"(a[mi][0]), "=r"(a[mi][1]), "=r"(a[mi][2]), "=r"(a[mi][3])
                         : "r"(addr));
        }
#pragma unroll
        for (int ni = 0; ni < 8; ni++) {
            const __nv_bfloat16* p = &sB[buf][(wn * 64 + ni * 8 + bn) * SB_STRIDE + bk];
            b[ni][0] = *(const uint32_t*)p;
            b[ni][1] = *(const uint32_t*)(p + 8);
        }
#pragma unroll
        for (int mi = 0; mi < 4; mi++)
#pragma unroll
            for (int ni = 0; ni < 8; ni++) {
                asm volatile(
                    "mma.sync.aligned.m16n8k16.row.col.f32.bf16.bf16.f32 "
                    "{%0,%1,%2,%3}, {%4,%5,%6,%7}, {%8,%9}, {%0,%1,%2,%3};"
                    : "+f"(acc[mi][ni][0]), "+f"(acc[mi][ni][1]),
                      "+f"(acc[mi][ni][2]), "+f"(acc[mi][ni][3])
                    : "r"(a[mi][0]), "r"(a[mi][1]), "r"(a[mi][2]), "r"(a[mi][3]),
                      "r"(b[ni][0]), "r"(b[ni][1]));
            }
        __syncthreads();   // protect buf before it is refilled at iter ks+2
    }
#undef ISSUE_STAGE

    // epilogue
    const int r = lane >> 2;
    const int c = (lane & 3) * 2;
#pragma unroll
    for (int mi = 0; mi < 4; mi++) {
#pragma unroll
        for (int ni = 0; ni < 8; ni++) {
            int n = n0 + wn * 64 + ni * 8 + c;
            if (n >= N) continue;
            float bia0 = 0.f, bia1 = 0.f, sc0 = 1.f, sc1 = 1.f, sh0 = 0.f, sh1 = 0.f;
            bool n1ok = (n + 1 < N);
            if (bias)  { bia0 = bias[n]; if (n1ok) bia1 = bias[n + 1]; }
            if (scale) { sc0 = scale[n]; sh0 = shift[n];
                         if (n1ok) { sc1 = scale[n + 1]; sh1 = shift[n + 1]; } }
#pragma unroll
            for (int half = 0; half < 2; half++) {
                int m = m0 + wm * 64 + mi * 16 + half * 8 + r;
                if (m >= M) continue;
                float v0 = acc[mi][ni][half * 2 + 0] + bia0;
                float v1 = acc[mi][ni][half * 2 + 1] + bia1;
                if (scale) { v0 = v0 * sc0 + sh0; v1 = v1 * sc1 + sh1; }
                if (relu)  { v0 = fmaxf(v0, 0.f); v1 = fmaxf(v1, 0.f); }
                float* p = C + (size_t)m * N + n;
                p[0] = v0;
                if (n1ok) p[1] = v1;
            }
        }
    }
}

// ---------------- small SIMT GEMM (fc1/fc2) ----------------
#define BM 64
#define BN 64
#define BK 16
__global__ void k_gemm(const float* __restrict__ A, const float* __restrict__ B,
                       float* __restrict__ C, int M, int N, int K, int transB,
                       const float* __restrict__ bias,
                       const float* __restrict__ scale,
                       const float* __restrict__ shift, int relu) {
    __shared__ float As[BK][BM];
    __shared__ float Bs[BK][BN + 4];
    const int m0 = blockIdx.y * BM;
    const int n0 = blockIdx.x * BN;
    const int tid = threadIdx.x;
    const int tm = tid >> 4;
    const int tn = tid & 15;
    float acc[4][4];
#pragma unroll
    for (int i = 0; i < 4; i++)
#pragma unroll
        for (int j = 0; j < 4; j++) acc[i][j] = 0.f;

    for (int k0 = 0; k0 < K; k0 += BK) {
        {
            int ar = tid >> 2;
            int ac = (tid & 3) * 4;
            int m = m0 + ar;
#pragma unroll
            for (int i = 0; i < 4; i++) {
                int k = k0 + ac + i;
                As[ac + i][ar] = (m < M && k < K) ? A[(size_t)m * K + k] : 0.f;
            }
        }
        if (!transB) {
            int br = tid >> 4;
            int bc = (tid & 15) * 4;
            int k = k0 + br;
#pragma unroll
            for (int i = 0; i < 4; i++) {
                int n = n0 + bc + i;
                Bs[br][bc + i] = (k < K && n < N) ? B[(size_t)k * N + n] : 0.f;
            }
        } else {
            int br = tid >> 2;
            int bc = (tid & 3) * 4;
            int n = n0 + br;
#pragma unroll
            for (int i = 0; i < 4; i++) {
                int k = k0 + bc + i;
                Bs[bc + i][br] = (n < N && k < K) ? B[(size_t)n * K + k] : 0.f;
            }
        }
        __syncthreads();
#pragma unroll
        for (int k = 0; k < BK; k++) {
            float a[4], b[4];
#pragma unroll
            for (int i = 0; i < 4; i++) a[i] = As[k][tm * 4 + i];
#pragma unroll
            for (int j = 0; j < 4; j++) b[j] = Bs[k][tn * 4 + j];
#pragma unroll
            for (int i = 0; i < 4; i++)
#pragma unroll
                for (int j = 0; j < 4; j++) acc[i][j] += a[i] * b[j];
        }
        __syncthreads();
    }
#pragma unroll
    for (int i = 0; i < 4; i++) {
        int m = m0 + tm * 4 + i;
        if (m >= M) continue;
#pragma unroll
        for (int j = 0; j < 4; j++) {
            int n = n0 + tn * 4 + j;
            if (n >= N) continue;
            float v = acc[i][j];
            if (bias)  v += bias[n];
            if (scale) v = v * scale[n] + shift[n];
            if (relu)  v = fmaxf(v, 0.f);
            C[(size_t)m * N + n] = v;
        }
    }
}

// ---------------- zero helper ----------------
__global__ void k_zero(float* __restrict__ p, int n) {
    int i = blockIdx.x * blockDim.x + threadIdx.x;
    if (i < n) p[i] = 0.f;
}

// ---------------- edge scatter-add ----------------
__global__ void k_scatter() {
    int t = blockIdx.x * blockDim.x + threadIdx.x;
    if (t >= NE * 50) return;
    int e = t / 50;
    int c = t - e * 50;
    int s = g_src[e];
    int d = g_dst[e];
    const float4 v = *reinterpret_cast<const float4*>(&g_m[(size_t)s * HID + c * 4]);
    float* p = &g_agg[(size_t)d * HID + c * 4];
    asm volatile("red.global.add.v4.f32 [%0], {%1,%2,%3,%4};"
                 :: "l"(p), "f"(v.x), "f"(v.y), "f"(v.z), "f"(v.w) : "memory");
}

// ---------------- GRU cell (vec4) + fused bf16 split write ------------------
__device__ __forceinline__ float sigm(float x) { return 1.f / (1.f + expf(-x)); }

__global__ void k_gru(int write_split) {
    int t = blockIdx.x * blockDim.x + threadIdx.x;
    if (t >= NN * 50) return;
    int n = t / 50, q = t - n * 50;
    int j = q * 4;
    const float* gi = g_gi + (size_t)n * H3;
    const float* gh = g_gh + (size_t)n * H3;
    float4 ir4 = *(const float4*)(gi + j);
    float4 iz4 = *(const float4*)(gi + j + 200);
    float4 in4 = *(const float4*)(gi + j + 400);
    float4 hr4 = *(const float4*)(gh + j);
    float4 hz4 = *(const float4*)(gh + j + 200);
    float4 hn4 = *(const float4*)(gh + j + 400);
    float* hp = g_h + (size_t)n * HID + j;
    float4 h4 = *(float4*)hp;

    float hv[4];
    {
        const float ir[4] = {ir4.x, ir4.y, ir4.z, ir4.w};
        const float iz[4] = {iz4.x, iz4.y, iz4.z, iz4.w};
        const float in_[4] = {in4.x, in4.y, in4.z, in4.w};
        const float hr[4] = {hr4.x, hr4.y, hr4.z, hr4.w};
        const float hz[4] = {hz4.x, hz4.y, hz4.z, hz4.w};
        const float hn[4] = {hn4.x, hn4.y, hn4.z, hn4.w};
        const float ho[4] = {h4.x, h4.y, h4.z, h4.w};
#pragma unroll
        for (int i = 0; i < 4; i++) {
            float r = sigm(ir[i] + hr[i]);
            float z = sigm(iz[i] + hz[i]);
            float nn = tanhf(in_[i] + r * hn[i]);
            hv[i] = (1.f - z) * nn + z * ho[i];
        }
    }
    *(float4*)hp = make_float4(hv[0], hv[1], hv[2], hv[3]);

    if (write_split) {
        __nv_bfloat16 hi[4], lo[4];
#pragma unroll
        for (int i = 0; i < 4; i++) {
            hi[i] = __float2bfloat16(hv[i]);
            lo[i] = __float2bfloat16(hv[i] - __bfloat162float(hi[i]));
        }
        __nv_bfloat16* o = g_hs + (size_t)n * K3 + j;
        ((uint32_t*)o)[0] = *(const uint32_t*)&hi[0];
        ((uint32_t*)o)[1] = *(const uint32_t*)&hi[2];
        ((uint32_t*)(o + 208))[0] = *(const uint32_t*)&lo[0];
        ((uint32_t*)(o + 208))[1] = *(const uint32_t*)&lo[2];
        ((uint32_t*)(o + 416))[0] = *(const uint32_t*)&hi[0];
        ((uint32_t*)(o + 416))[1] = *(const uint32_t*)&hi[2];
    }
}

__global__ void k_bn2relu() {
    int idx = blockIdx.x * blockDim.x + threadIdx.x;
    if (idx >= NN * HID) return;
    int j = idx % HID;
    g_h[idx] = fmaxf(g_h[idx] * g_scale[HID + j] + g_shift[HID + j], 0.f);
}

// ---------------- pooling ----------------
__global__ void k_pool() {
    int t = blockIdx.x * blockDim.x + threadIdx.x;
    if (t >= NN * 50) return;
    int node = t / 50;
    int c = t - node * 50;
    int b = g_batch[node];
    const float4 v = *reinterpret_cast<const float4*>(&g_h[(size_t)node * HID + c * 4]);
    float* mp = &g_pool[b * 400 + c * 4];
    atomicAdd(mp + 0, v.x); atomicAdd(mp + 1, v.y);
    atomicAdd(mp + 2, v.z); atomicAdd(mp + 3, v.w);
    int* xp = (int*)&g_pool[b * 400 + 200 + c * 4];
    atomicMax(xp + 0, __float_as_int(v.x));
    atomicMax(xp + 1, __float_as_int(v.y));
    atomicMax(xp + 2, __float_as_int(v.z));
    atomicMax(xp + 3, __float_as_int(v.w));
    if (c == 0) atomicAdd(&g_cnt[b], 1.0f);
}

__global__ void k_pool_fin() {
    int idx = blockIdx.x * blockDim.x + threadIdx.x;
    if (idx >= NG * HID) return;
    int g = idx / HID;
    int j = idx - g * HID;
    g_pool[g * 400 + j] *= 1.f / fmaxf(g_cnt[g], 1.f);
}

// ---------------- host launch ----------------
static inline int cdiv(int a, int b) { return (a + b - 1) / b; }

extern "C" void kernel_launch(void* const* d_in, const int* in_sizes, int n_in,
                              void* d_out, int out_size) {
    static bool init = false;
    static float *p_h, *p_m, *p_agg, *p_gi, *p_gh, *p_pool, *p_cnt, *p_fc1, *p_scale, *p_shift;
    static __nv_bfloat16 *p_xs, *p_hs, *p_as, *p_Bproj, *p_Bggc, *p_Bwih, *p_Bwhh;
    if (!init) {
        cudaGetSymbolAddress((void**)&p_h, g_h);
        cudaGetSymbolAddress((void**)&p_m, g_m);
        cudaGetSymbolAddress((void**)&p_agg, g_agg);
        cudaGetSymbolAddress((void**)&p_gi, g_gi);
        cudaGetSymbolAddress((void**)&p_gh, g_gh);
        cudaGetSymbolAddress((void**)&p_pool, g_pool);
        cudaGetSymbolAddress((void**)&p_cnt, g_cnt);
        cudaGetSymbolAddress((void**)&p_fc1, g_fc1);
        cudaGetSymbolAddress((void**)&p_scale, g_scale);
        cudaGetSymbolAddress((void**)&p_shift, g_shift);
        cudaGetSymbolAddress((void**)&p_xs, g_xs);
        cudaGetSymbolAddress((void**)&p_hs, g_hs);
        cudaGetSymbolAddress((void**)&p_as, g_as);
        cudaGetSymbolAddress((void**)&p_Bproj, g_Bproj);
        cudaGetSymbolAddress((void**)&p_Bggc, g_Bggc);
        cudaGetSymbolAddress((void**)&p_Bwih, g_Bwih);
        cudaGetSymbolAddress((void**)&p_Bwhh, g_Bwhh);
        init = true;
    }

    const float *x, *projW, *projb;
    const void  *edge, *batch;
    const float *bn1g, *bn1b, *bn1m, *bn1v;
    const float *bn2g, *bn2b, *bn2m, *bn2v;
    const float *bnfg, *bnfb, *bnfm, *bnfv;
    const float *ggcW, *wih, *whh, *bih, *bhh, *fc1W, *fc1b, *fc2W, *fc2b;

    x     = (const float*)d_in[0];
    edge  = d_in[1];
    batch = d_in[2];
    projW = (const float*)d_in[3];
    projb = (const float*)d_in[4];
    bn1g = (const float*)d_in[5]; bn1b = (const float*)d_in[6];
    bn1m = (const float*)d_in[7]; bn1v = (const float*)d_in[8];

    if (in_sizes[9] == 120000) {
        ggcW = (const float*)d_in[9];
        wih  = (const float*)d_in[10]; whh = (const float*)d_in[11];
        bih  = (const float*)d_in[12]; bhh = (const float*)d_in[13];
        bn2g = (const float*)d_in[14]; bn2b = (const float*)d_in[15];
        bn2m = (const float*)d_in[16]; bn2v = (const float*)d_in[17];
        fc1W = (const float*)d_in[18]; fc1b = (const float*)d_in[19];
        bnfg = (const float*)d_in[20]; bnfb = (const float*)d_in[21];
        bnfm = (const float*)d_in[22]; bnfv = (const float*)d_in[23];
        fc2W = (const float*)d_in[24]; fc2b = (const float*)d_in[25];
    } else {
        bn2g = (const float*)d_in[9];  bn2b = (const float*)d_in[10];
        bn2m = (const float*)d_in[11]; bn2v = (const float*)d_in[12];
        bnfg = (const float*)d_in[13]; bnfb = (const float*)d_in[14];
        bnfm = (const float*)d_in[15]; bnfv = (const float*)d_in[16];
        ggcW = (const float*)d_in[17];
        wih  = (const float*)d_in[18]; whh = (const float*)d_in[19];
        bih  = (const float*)d_in[20]; bhh = (const float*)d_in[21];
        fc1W = (const float*)d_in[22]; fc1b = (const float*)d_in[23];
        fc2W = (const float*)d_in[24]; fc2b = (const float*)d_in[25];
    }

    const int T = 256;
    const int MT = cdiv(NN, 128);  // 782

    // idx 0-3 arranged so an early ncu sample hits k_tgemm
    k_splitB<<<cdiv(256 * NCH, T), T>>>(projW, p_Bproj, HID, 256, INDIM, 1);   // 0
    k_bnprep_all<<<1, 640>>>(bn1g, bn1b, bn1m, bn1v,
                             bn2g, bn2b, bn2m, bn2v,
                             bnfg, bnfb, bnfm, bnfv);                           // 1
    k_splitA<<<cdiv(NN * NCH, T), T>>>(x, p_xs, INDIM);                         // 2
    // h = relu(bn1(x @ projW^T + projb))
    k_tgemm<<<dim3(1, MT), 256>>>(p_xs, p_Bproj, p_h, NN, HID,
                                  projb, p_scale, p_shift, 1);                  // 3
    k_splitA<<<cdiv(NN * NCH, T), T>>>(p_h, p_hs, HID);                         // 4
    k_splitB<<<cdiv(256 * NCH, T), T>>>(ggcW, p_Bggc, HID, 256, HID, 0);        // 5
    // m = h @ ggc_W[0]
    k_tgemm<<<dim3(1, MT), 256>>>(p_hs, p_Bggc, p_m, NN, HID,
                                  nullptr, nullptr, nullptr, 0);                // 6

    k_detect<<<1, 32>>>((const int*)edge, (const int*)batch);
    k_conv_edges<<<cdiv(2 * NE, T), T>>>(edge);
    k_conv_batch<<<cdiv(NN, T), T>>>(batch);
    for (int i = 1; i < 3; i++)
        k_splitB<<<cdiv(256 * NCH, T), T>>>(ggcW + (size_t)i * HID * HID,
                                            p_Bggc + (size_t)i * 256 * K3, HID, 256, HID, 0);
    k_splitB<<<cdiv(768 * NCH, T), T>>>(wih, p_Bwih, H3, 768, HID, 1);
    k_splitB<<<cdiv(768 * NCH, T), T>>>(whh, p_Bwhh, H3, 768, HID, 1);

    for (int it = 0; it < 3; it++) {
        if (it > 0) {
            k_tgemm<<<dim3(1, MT), 256>>>(p_hs, p_Bggc + (size_t)it * 256 * K3,
                                          p_m, NN, HID, nullptr, nullptr, nullptr, 0);
        }
        // agg = scatter_add(m[src] -> dst)
        k_zero<<<cdiv(NN * HID, T), T>>>(p_agg, NN * HID);
        k_scatter<<<cdiv(NE * 50, T), T>>>();
        k_splitA<<<cdiv(NN * NCH, T), T>>>(p_agg, p_as, HID);
        // gi = agg @ wih^T + bih ; gh = h @ whh^T + bhh
        k_tgemm<<<dim3(3, MT), 256>>>(p_as, p_Bwih, p_gi, NN, H3,
                                      bih, nullptr, nullptr, 0);
        k_tgemm<<<dim3(3, MT), 256>>>(p_hs, p_Bwhh, p_gh, NN, H3,
                                      bhh, nullptr, nullptr, 0);
        // h = GRU(...); write bf16 split for next iteration
        k_gru<<<cdiv(NN * 50, T), T>>>(it < 2 ? 1 : 0);
    }

    k_bn2relu<<<cdiv(NN * HID, T), T>>>();

    k_zero<<<cdiv(NG * 400, T), T>>>(p_pool, NG * 400);
    k_zero<<<cdiv(NG, T), T>>>(p_cnt, NG);
    k_pool<<<cdiv(NN * 50, T), T>>>();
    k_pool_fin<<<cdiv(NG * HID, T), T>>>();

    {
        dim3 grid(cdiv(HID, BN), cdiv(NG, BM));
        k_gemm<<<grid, T>>>(p_pool, fc1W, p_fc1, NG, HID, 2 * HID, 1,
                            fc1b, p_scale + 2 * HID, p_shift + 2 * HID, 1);
    }
    {
        dim3 grid(cdiv(2, BN), cdiv(NG, BM));
        k_gemm<<<grid, T>>>(p_fc1, fc2W, (float*)d_out, NG, 2, HID, 1,
                            fc2b, nullptr, nullptr, 0);
    }
}

// round 8
// speedup vs baseline: 1.2247x; 1.2247x over previous
#include <cuda_runtime.h>
#include <cuda_bf16.h>
#include <stdint.h>
#include <math.h>

#define NN    100000
#define NE    1600000
#define NG    512
#define HID   200
#define H3    600
#define INDIM 205

#define KP    208
#define K3    624
#define NCH   78        // chunks of 8 per logical row
#define NSTEP 39        // K3/16
#define MPAD  100096    // 782*128
#define RSTR  24        // halfwords per k-step row slot (48B, 16B-aligned, conflict-free)

// ---------------- scratch (device globals; no runtime alloc) ----------------
__device__ float g_h  [(size_t)NN * HID];
__device__ float g_m  [(size_t)NN * HID];
__device__ float g_agg[(size_t)NN * HID];
__device__ float g_gi [(size_t)NN * H3];
__device__ float g_gh [(size_t)NN * H3];
__device__ float g_pool[NG * 2 * HID];
__device__ float g_cnt [NG];
__device__ float g_fc1 [NG * HID];
__device__ float g_scale[3 * HID];
__device__ float g_shift[3 * HID];
__device__ int   g_src[NE];
__device__ int   g_dst[NE];
__device__ int   g_batch[NN];
__device__ int   g_flag_e;
__device__ int   g_flag_b;

// k-blocked bf16 split buffers: [NSTEP][rowpad][RSTR] (only first 16 of 24 used)
__device__ __nv_bfloat16 g_xs[(size_t)NSTEP * MPAD * RSTR];
__device__ __nv_bfloat16 g_hs[(size_t)NSTEP * MPAD * RSTR];
__device__ __nv_bfloat16 g_as[(size_t)NSTEP * MPAD * RSTR];
__device__ __nv_bfloat16 g_Bproj[(size_t)NSTEP * 256 * RSTR];
__device__ __nv_bfloat16 g_Bggc [3][(size_t)NSTEP * 256 * RSTR];
__device__ __nv_bfloat16 g_Bwih [(size_t)NSTEP * 768 * RSTR];
__device__ __nv_bfloat16 g_Bwhh [(size_t)NSTEP * 768 * RSTR];

// ---------------- dtype detection (int64 vs int32) ----------------
__global__ void k_detect(const int* __restrict__ ew, const int* __restrict__ bw) {
    int lane = threadIdx.x;
    int bad_e = 0, bad_b = 0;
    for (int w = 2 * NE - 255 + 2 * lane; w < 2 * NE; w += 64)
        if (ew[w] != 0) bad_e = 1;
    for (int w = NN - 255 + 2 * lane; w < NN; w += 64)
        if (bw[w] != 0) bad_b = 1;
    unsigned me = __ballot_sync(0xFFFFFFFFu, bad_e);
    unsigned mb = __ballot_sync(0xFFFFFFFFu, bad_b);
    if (lane == 0) { g_flag_e = (me == 0); g_flag_b = (mb == 0); }
}

__global__ void k_conv_edges(const void* __restrict__ e) {
    int i = blockIdx.x * blockDim.x + threadIdx.x;
    if (i >= 2 * NE) return;
    int v = g_flag_e ? (int)((const long long*)e)[i] : ((const int*)e)[i];
    if (i < NE) g_src[i] = v; else g_dst[i - NE] = v;
}

__global__ void k_conv_batch(const void* __restrict__ b) {
    int i = blockIdx.x * blockDim.x + threadIdx.x;
    if (i >= NN) return;
    g_batch[i] = g_flag_b ? (int)((const long long*)b)[i] : ((const int*)b)[i];
}

// ---------------- merged BN param prep ----------------
__global__ void k_bnprep_all(
    const float* g1, const float* b1, const float* m1, const float* v1,
    const float* g2, const float* b2, const float* m2, const float* v2,
    const float* gf, const float* bf, const float* mf, const float* vf) {
    int j = threadIdx.x;
    if (j >= 3 * HID) return;
    int which = j / HID, jj = j - which * HID;
    const float *g, *b, *m, *v;
    if (which == 0)      { g = g1; b = b1; m = m1; v = v1; }
    else if (which == 1) { g = g2; b = b2; m = m2; v = v2; }
    else                 { g = gf; b = bf; m = mf; v = vf; }
    float s = g[jj] * rsqrtf(v[jj] + 1e-5f);
    g_scale[j] = s;
    g_shift[j] = b[jj] - m[jj] * s;
}

// ---------------- bf16 split of activations into k-blocked layout -----------
// logical row layout per m: [hi(0..207) | lo(0..207) | hi(0..207)]
// chunk ch in [0,78): section s=ch/26, c=ch-s*26, k0=c*8
// dest: step ks = s*13 + c/2, slot halfword kk = (c&1)*8
__global__ void k_splitA(const float* __restrict__ in, __nv_bfloat16* __restrict__ out,
                         int K) {
    int idx = blockIdx.x * blockDim.x + threadIdx.x;
    if (idx >= NN * NCH) return;
    int m = idx / NCH, ch = idx - (idx / NCH) * NCH;
    int s = ch / 26, c = ch - s * 26;
    int k0 = c * 8;
    const float* src = in + (size_t)m * K + k0;
    __nv_bfloat16 o[8];
#pragma unroll
    for (int i = 0; i < 8; i++) {
        float v = (k0 + i < K) ? src[i] : 0.f;
        __nv_bfloat16 hi = __float2bfloat16(v);
        o[i] = (s == 1) ? __float2bfloat16(v - __bfloat162float(hi)) : hi;
    }
    int ks = s * 13 + (c >> 1);
    *(uint4*)(out + ((size_t)ks * MPAD + m) * RSTR + (c & 1) * 8) = *(const uint4*)o;
}

// ---------------- bf16 split of weights into k-blocked layout ---------------
// sections: s0=hi, s1=hi, s2=lo.  trans=1: W is [N,K] row-major.
__global__ void k_splitB(const float* __restrict__ W, __nv_bfloat16* __restrict__ out,
                         int N, int Npad, int K, int trans) {
    int idx = blockIdx.x * blockDim.x + threadIdx.x;
    if (idx >= Npad * NCH) return;
    int n = idx / NCH, ch = idx - (idx / NCH) * NCH;
    int s = ch / 26, c = ch - s * 26;
    int k0 = c * 8;
    __nv_bfloat16 o[8];
#pragma unroll
    for (int i = 0; i < 8; i++) {
        int k = k0 + i;
        float v = 0.f;
        if (n < N && k < K) v = trans ? W[(size_t)n * K + k] : W[(size_t)k * N + n];
        __nv_bfloat16 hi = __float2bfloat16(v);
        o[i] = (s == 2) ? __float2bfloat16(v - __bfloat162float(hi)) : hi;
    }
    int ks = s * 13 + (c >> 1);
    *(uint4*)(out + ((size_t)ks * Npad + n) * RSTR + (c & 1) * 8) = *(const uint4*)o;
}

// ---------------- tensor-core GEMM: 128x256 CTA tile, TMA-bulk pipeline -----
// 8 warps (2m x 4n), warp tile 64x64, mma.m16n8k16.bf16.
// 5-stage ring in dynamic smem, cp.async.bulk + mbarrier, single sync/step.
#define STAGES       5
#define STAGE_A_HW   (128 * RSTR)            // 3072 halfwords
#define STAGE_B_HW   (256 * RSTR)            // 6144
#define STAGE_HW     (STAGE_A_HW + STAGE_B_HW)
#define STAGE_BYTES  (STAGE_HW * 2)          // 18432
#define A_BYTES      (STAGE_A_HW * 2)        // 6144
#define B_BYTES      (STAGE_B_HW * 2)        // 12288
#define SMEM_DYN     (STAGES * STAGE_BYTES + 64)

__global__ void __launch_bounds__(256, 1)
k_tgemm(const __nv_bfloat16* __restrict__ A, const __nv_bfloat16* __restrict__ B,
        float* __restrict__ C, int M, int N, int NPADB,
        const float* __restrict__ bias,
        const float* __restrict__ scale, const float* __restrict__ shift,
        int relu) {
    extern __shared__ __align__(128) __nv_bfloat16 dsm[];

    const int tid  = threadIdx.x;
    const int warp = tid >> 5, lane = tid & 31;
    const int wm = warp & 1, wn = warp >> 1;
    const int m0 = blockIdx.y * 128;
    const int n0 = blockIdx.x * 256;

    const uint32_t smem_base = (uint32_t)__cvta_generic_to_shared(dsm);
    const uint32_t mbar_base = smem_base + STAGES * STAGE_BYTES;

    if (tid == 0) {
        for (int s = 0; s < STAGES; s++)
            asm volatile("mbarrier.init.shared.b64 [%0], 1;"
                         :: "r"(mbar_base + s * 8) : "memory");
        asm volatile("fence.proxy.async.shared::cta;" ::: "memory");
    }
    __syncthreads();

    float acc[4][8][4];
#pragma unroll
    for (int mi = 0; mi < 4; mi++)
#pragma unroll
        for (int ni = 0; ni < 8; ni++)
#pragma unroll
            for (int j = 0; j < 4; j++) acc[mi][ni][j] = 0.f;

#define ISSUE(kf)                                                                \
    do {                                                                         \
        int slot_ = (kf) % STAGES;                                               \
        uint32_t mb_ = mbar_base + slot_ * 8;                                    \
        asm volatile("mbarrier.arrive.expect_tx.shared.b64 _, [%0], %1;"         \
                     :: "r"(mb_), "r"((uint32_t)STAGE_BYTES) : "memory");        \
        uint32_t da_ = smem_base + slot_ * STAGE_BYTES;                          \
        const __nv_bfloat16* sa_ = A + ((size_t)(kf) * MPAD + m0) * RSTR;        \
        asm volatile("cp.async.bulk.shared::cta.global.mbarrier::complete_tx::bytes " \
                     "[%0], [%1], %2, [%3];"                                     \
                     :: "r"(da_), "l"(sa_), "r"((uint32_t)A_BYTES), "r"(mb_)     \
                     : "memory");                                                \
        uint32_t db_ = da_ + A_BYTES;                                            \
        const __nv_bfloat16* sb_ = B + ((size_t)(kf) * NPADB + n0) * RSTR;       \
        asm volatile("cp.async.bulk.shared::cta.global.mbarrier::complete_tx::bytes " \
                     "[%0], [%1], %2, [%3];"                                     \
                     :: "r"(db_), "l"(sb_), "r"((uint32_t)B_BYTES), "r"(mb_)     \
                     : "memory");                                                \
    } while (0)

    if (tid == 0) {
        for (int kf = 0; kf < STAGES - 1 && kf < NSTEP; kf++) ISSUE(kf);
    }

    const int lr  = lane & 15;
    const int lcb = (lane >> 4) * 8;
    const int bn  = lane >> 2;
    const int bk  = (lane & 3) * 2;

    for (int ks = 0; ks < NSTEP; ks++) {
        __syncthreads();   // all threads finished reading slot (ks-1)%STAGES
        if (tid == 0) {
            int kf = ks + STAGES - 1;
            if (kf < NSTEP) ISSUE(kf);     // fills slot (ks-1)%STAGES
        }
        const int slot = ks % STAGES;
        const uint32_t mb = mbar_base + slot * 8;
        const uint32_t parity = (uint32_t)((ks / STAGES) & 1);
        {
            uint32_t done = 0;
            while (!done) {
                asm volatile(
                    "{\n\t.reg .pred p;\n\t"
                    "mbarrier.try_wait.parity.acquire.cta.shared::cta.b64 p, [%1], %2;\n\t"
                    "selp.b32 %0, 1, 0, p;\n\t}"
                    : "=r"(done) : "r"(mb), "r"(parity) : "memory");
            }
        }

        const uint32_t aBase = smem_base + slot * STAGE_BYTES;
        const __nv_bfloat16* sBp = dsm + slot * STAGE_HW + STAGE_A_HW;

        uint32_t a[4][4];
        uint32_t b[8][2];
#pragma unroll
        for (int mi = 0; mi < 4; mi++) {
            uint32_t addr = aBase + ((wm * 64 + mi * 16 + lr) * RSTR + lcb) * 2;
            asm volatile("ldmatrix.sync.aligned.m8n8.x4.shared.b16 {%0,%1,%2,%3}, [%4];"
                         : "=r"(a[mi][0]), "=r"(a[mi][1]), "=r"(a[mi][2]), "=r"(a[mi][3])
                         : "r"(addr));
        }
#pragma unroll
        for (int ni = 0; ni < 8; ni++) {
            const __nv_bfloat16* p = sBp + (wn * 64 + ni * 8 + bn) * RSTR + bk;
            b[ni][0] = *(const uint32_t*)p;
            b[ni][1] = *(const uint32_t*)(p + 8);
        }
#pragma unroll
        for (int mi = 0; mi < 4; mi++)
#pragma unroll
            for (int ni = 0; ni < 8; ni++) {
                asm volatile(
                    "mma.sync.aligned.m16n8k16.row.col.f32.bf16.bf16.f32 "
                    "{%0,%1,%2,%3}, {%4,%5,%6,%7}, {%8,%9}, {%0,%1,%2,%3};"
                    : "+f"(acc[mi][ni][0]), "+f"(acc[mi][ni][1]),
                      "+f"(acc[mi][ni][2]), "+f"(acc[mi][ni][3])
                    : "r"(a[mi][0]), "r"(a[mi][1]), "r"(a[mi][2]), "r"(a[mi][3]),
                      "r"(b[ni][0]), "r"(b[ni][1]));
            }
    }
#undef ISSUE

    // epilogue
    const int r = lane >> 2;
    const int c = (lane & 3) * 2;
#pragma unroll
    for (int mi = 0; mi < 4; mi++) {
#pragma unroll
        for (int ni = 0; ni < 8; ni++) {
            int n = n0 + wn * 64 + ni * 8 + c;
            if (n >= N) continue;
            float bia0 = 0.f, bia1 = 0.f, sc0 = 1.f, sc1 = 1.f, sh0 = 0.f, sh1 = 0.f;
            bool n1ok = (n + 1 < N);
            if (bias)  { bia0 = bias[n]; if (n1ok) bia1 = bias[n + 1]; }
            if (scale) { sc0 = scale[n]; sh0 = shift[n];
                         if (n1ok) { sc1 = scale[n + 1]; sh1 = shift[n + 1]; } }
#pragma unroll
            for (int half = 0; half < 2; half++) {
                int m = m0 + wm * 64 + mi * 16 + half * 8 + r;
                if (m >= M) continue;
                float v0 = acc[mi][ni][half * 2 + 0] + bia0;
                float v1 = acc[mi][ni][half * 2 + 1] + bia1;
                if (scale) { v0 = v0 * sc0 + sh0; v1 = v1 * sc1 + sh1; }
                if (relu)  { v0 = fmaxf(v0, 0.f); v1 = fmaxf(v1, 0.f); }
                float* p = C + (size_t)m * N + n;
                p[0] = v0;
                if (n1ok) p[1] = v1;
            }
        }
    }
}

// ---------------- small SIMT GEMM (fc1/fc2) ----------------
#define BM 64
#define BN 64
#define BK 16
__global__ void k_gemm(const float* __restrict__ A, const float* __restrict__ B,
                       float* __restrict__ C, int M, int N, int K, int transB,
                       const float* __restrict__ bias,
                       const float* __restrict__ scale,
                       const float* __restrict__ shift, int relu) {
    __shared__ float As[BK][BM];
    __shared__ float Bs[BK][BN + 4];
    const int m0 = blockIdx.y * BM;
    const int n0 = blockIdx.x * BN;
    const int tid = threadIdx.x;
    const int tm = tid >> 4;
    const int tn = tid & 15;
    float acc[4][4];
#pragma unroll
    for (int i = 0; i < 4; i++)
#pragma unroll
        for (int j = 0; j < 4; j++) acc[i][j] = 0.f;

    for (int k0 = 0; k0 < K; k0 += BK) {
        {
            int ar = tid >> 2;
            int ac = (tid & 3) * 4;
            int m = m0 + ar;
#pragma unroll
            for (int i = 0; i < 4; i++) {
                int k = k0 + ac + i;
                As[ac + i][ar] = (m < M && k < K) ? A[(size_t)m * K + k] : 0.f;
            }
        }
        if (!transB) {
            int br = tid >> 4;
            int bc = (tid & 15) * 4;
            int k = k0 + br;
#pragma unroll
            for (int i = 0; i < 4; i++) {
                int n = n0 + bc + i;
                Bs[br][bc + i] = (k < K && n < N) ? B[(size_t)k * N + n] : 0.f;
            }
        } else {
            int br = tid >> 2;
            int bc = (tid & 3) * 4;
            int n = n0 + br;
#pragma unroll
            for (int i = 0; i < 4; i++) {
                int k = k0 + bc + i;
                Bs[bc + i][br] = (n < N && k < K) ? B[(size_t)n * K + k] : 0.f;
            }
        }
        __syncthreads();
#pragma unroll
        for (int k = 0; k < BK; k++) {
            float a[4], b[4];
#pragma unroll
            for (int i = 0; i < 4; i++) a[i] = As[k][tm * 4 + i];
#pragma unroll
            for (int j = 0; j < 4; j++) b[j] = Bs[k][tn * 4 + j];
#pragma unroll
            for (int i = 0; i < 4; i++)
#pragma unroll
                for (int j = 0; j < 4; j++) acc[i][j] += a[i] * b[j];
        }
        __syncthreads();
    }
#pragma unroll
    for (int i = 0; i < 4; i++) {
        int m = m0 + tm * 4 + i;
        if (m >= M) continue;
#pragma unroll
        for (int j = 0; j < 4; j++) {
            int n = n0 + tn * 4 + j;
            if (n >= N) continue;
            float v = acc[i][j];
            if (bias)  v += bias[n];
            if (scale) v = v * scale[n] + shift[n];
            if (relu)  v = fmaxf(v, 0.f);
            C[(size_t)m * N + n] = v;
        }
    }
}

// ---------------- zero helper ----------------
__global__ void k_zero(float* __restrict__ p, int n) {
    int i = blockIdx.x * blockDim.x + threadIdx.x;
    if (i < n) p[i] = 0.f;
}

// ---------------- edge scatter-add ----------------
__global__ void k_scatter() {
    int t = blockIdx.x * blockDim.x + threadIdx.x;
    if (t >= NE * 50) return;
    int e = t / 50;
    int c = t - e * 50;
    int s = g_src[e];
    int d = g_dst[e];
    const float4 v = *reinterpret_cast<const float4*>(&g_m[(size_t)s * HID + c * 4]);
    float* p = &g_agg[(size_t)d * HID + c * 4];
    asm volatile("red.global.add.v4.f32 [%0], {%1,%2,%3,%4};"
                 :: "l"(p), "f"(v.x), "f"(v.y), "f"(v.z), "f"(v.w) : "memory");
}

// ---------------- GRU cell (vec4) + fused k-blocked bf16 split write --------
__device__ __forceinline__ float sigm(float x) { return 1.f / (1.f + expf(-x)); }

__global__ void k_gru(int write_split) {
    int t = blockIdx.x * blockDim.x + threadIdx.x;
    if (t >= NN * 50) return;
    int n = t / 50, q = t - n * 50;
    int j = q * 4;
    const float* gi = g_gi + (size_t)n * H3;
    const float* gh = g_gh + (size_t)n * H3;
    float4 ir4 = *(const float4*)(gi + j);
    float4 iz4 = *(const float4*)(gi + j + 200);
    float4 in4 = *(const float4*)(gi + j + 400);
    float4 hr4 = *(const float4*)(gh + j);
    float4 hz4 = *(const float4*)(gh + j + 200);
    float4 hn4 = *(const float4*)(gh + j + 400);
    float* hp = g_h + (size_t)n * HID + j;
    float4 h4 = *(float4*)hp;

    float hv[4];
    {
        const float ir[4] = {ir4.x, ir4.y, ir4.z, ir4.w};
        const float iz[4] = {iz4.x, iz4.y, iz4.z, iz4.w};
        const float in_[4] = {in4.x, in4.y, in4.z, in4.w};
        const float hr[4] = {hr4.x, hr4.y, hr4.z, hr4.w};
        const float hz[4] = {hz4.x, hz4.y, hz4.z, hz4.w};
        const float hn[4] = {hn4.x, hn4.y, hn4.z, hn4.w};
        const float ho[4] = {h4.x, h4.y, h4.z, h4.w};
#pragma unroll
        for (int i = 0; i < 4; i++) {
            float r = sigm(ir[i] + hr[i]);
            float z = sigm(iz[i] + hz[i]);
            float nn = tanhf(in_[i] + r * hn[i]);
            hv[i] = (1.f - z) * nn + z * ho[i];
        }
    }
    *(float4*)hp = make_float4(hv[0], hv[1], hv[2], hv[3]);

    if (write_split) {
        __nv_bfloat16 hi[4], lo[4];
#pragma unroll
        for (int i = 0; i < 4; i++) {
            hi[i] = __float2bfloat16(hv[i]);
            lo[i] = __float2bfloat16(hv[i] - __bfloat162float(hi[i]));
        }
        int ksj = j >> 4, kk = j & 15;
        // sections: 0=hi, 1=lo, 2=hi; step = s*13 + ksj
        __nv_bfloat16* o0 = g_hs + ((size_t)(ksj) * MPAD + n) * RSTR + kk;
        __nv_bfloat16* o1 = g_hs + ((size_t)(13 + ksj) * MPAD + n) * RSTR + kk;
        __nv_bfloat16* o2 = g_hs + ((size_t)(26 + ksj) * MPAD + n) * RSTR + kk;
        ((uint32_t*)o0)[0] = *(const uint32_t*)&hi[0];
        ((uint32_t*)o0)[1] = *(const uint32_t*)&hi[2];
        ((uint32_t*)o1)[0] = *(const uint32_t*)&lo[0];
        ((uint32_t*)o1)[1] = *(const uint32_t*)&lo[2];
        ((uint32_t*)o2)[0] = *(const uint32_t*)&hi[0];
        ((uint32_t*)o2)[1] = *(const uint32_t*)&hi[2];
    }
}

__global__ void k_bn2relu() {
    int idx = blockIdx.x * blockDim.x + threadIdx.x;
    if (idx >= NN * HID) return;
    int j = idx % HID;
    g_h[idx] = fmaxf(g_h[idx] * g_scale[HID + j] + g_shift[HID + j], 0.f);
}

// ---------------- pooling ----------------
__global__ void k_pool() {
    int t = blockIdx.x * blockDim.x + threadIdx.x;
    if (t >= NN * 50) return;
    int node = t / 50;
    int c = t - node * 50;
    int b = g_batch[node];
    const float4 v = *reinterpret_cast<const float4*>(&g_h[(size_t)node * HID + c * 4]);
    float* mp = &g_pool[b * 400 + c * 4];
    atomicAdd(mp + 0, v.x); atomicAdd(mp + 1, v.y);
    atomicAdd(mp + 2, v.z); atomicAdd(mp + 3, v.w);
    int* xp = (int*)&g_pool[b * 400 + 200 + c * 4];
    atomicMax(xp + 0, __float_as_int(v.x));
    atomicMax(xp + 1, __float_as_int(v.y));
    atomicMax(xp + 2, __float_as_int(v.z));
    atomicMax(xp + 3, __float_as_int(v.w));
    if (c == 0) atomicAdd(&g_cnt[b], 1.0f);
}

__global__ void k_pool_fin() {
    int idx = blockIdx.x * blockDim.x + threadIdx.x;
    if (idx >= NG * HID) return;
    int g = idx / HID;
    int j = idx - g * HID;
    g_pool[g * 400 + j] *= 1.f / fmaxf(g_cnt[g], 1.f);
}

// ---------------- host launch ----------------
static inline int cdiv(int a, int b) { return (a + b - 1) / b; }

extern "C" void kernel_launch(void* const* d_in, const int* in_sizes, int n_in,
                              void* d_out, int out_size) {
    static bool init = false;
    static float *p_h, *p_m, *p_agg, *p_gi, *p_gh, *p_pool, *p_cnt, *p_fc1, *p_scale, *p_shift;
    static __nv_bfloat16 *p_xs, *p_hs, *p_as, *p_Bproj, *p_Bggc, *p_Bwih, *p_Bwhh;
    if (!init) {
        cudaGetSymbolAddress((void**)&p_h, g_h);
        cudaGetSymbolAddress((void**)&p_m, g_m);
        cudaGetSymbolAddress((void**)&p_agg, g_agg);
        cudaGetSymbolAddress((void**)&p_gi, g_gi);
        cudaGetSymbolAddress((void**)&p_gh, g_gh);
        cudaGetSymbolAddress((void**)&p_pool, g_pool);
        cudaGetSymbolAddress((void**)&p_cnt, g_cnt);
        cudaGetSymbolAddress((void**)&p_fc1, g_fc1);
        cudaGetSymbolAddress((void**)&p_scale, g_scale);
        cudaGetSymbolAddress((void**)&p_shift, g_shift);
        cudaGetSymbolAddress((void**)&p_xs, g_xs);
        cudaGetSymbolAddress((void**)&p_hs, g_hs);
        cudaGetSymbolAddress((void**)&p_as, g_as);
        cudaGetSymbolAddress((void**)&p_Bproj, g_Bproj);
        cudaGetSymbolAddress((void**)&p_Bggc, g_Bggc);
        cudaGetSymbolAddress((void**)&p_Bwih, g_Bwih);
        cudaGetSymbolAddress((void**)&p_Bwhh, g_Bwhh);
        cudaFuncSetAttribute(k_tgemm, cudaFuncAttributeMaxDynamicSharedMemorySize,
                             SMEM_DYN);
        init = true;
    }

    const float *x, *projW, *projb;
    const void  *edge, *batch;
    const float *bn1g, *bn1b, *bn1m, *bn1v;
    const float *bn2g, *bn2b, *bn2m, *bn2v;
    const float *bnfg, *bnfb, *bnfm, *bnfv;
    const float *ggcW, *wih, *whh, *bih, *bhh, *fc1W, *fc1b, *fc2W, *fc2b;

    x     = (const float*)d_in[0];
    edge  = d_in[1];
    batch = d_in[2];
    projW = (const float*)d_in[3];
    projb = (const float*)d_in[4];
    bn1g = (const float*)d_in[5]; bn1b = (const float*)d_in[6];
    bn1m = (const float*)d_in[7]; bn1v = (const float*)d_in[8];

    if (in_sizes[9] == 120000) {
        ggcW = (const float*)d_in[9];
        wih  = (const float*)d_in[10]; whh = (const float*)d_in[11];
        bih  = (const float*)d_in[12]; bhh = (const float*)d_in[13];
        bn2g = (const float*)d_in[14]; bn2b = (const float*)d_in[15];
        bn2m = (const float*)d_in[16]; bn2v = (const float*)d_in[17];
        fc1W = (const float*)d_in[18]; fc1b = (const float*)d_in[19];
        bnfg = (const float*)d_in[20]; bnfb = (const float*)d_in[21];
        bnfm = (const float*)d_in[22]; bnfv = (const float*)d_in[23];
        fc2W = (const float*)d_in[24]; fc2b = (const float*)d_in[25];
    } else {
        bn2g = (const float*)d_in[9];  bn2b = (const float*)d_in[10];
        bn2m = (const float*)d_in[11]; bn2v = (const float*)d_in[12];
        bnfg = (const float*)d_in[13]; bnfb = (const float*)d_in[14];
        bnfm = (const float*)d_in[15]; bnfv = (const float*)d_in[16];
        ggcW = (const float*)d_in[17];
        wih  = (const float*)d_in[18]; whh = (const float*)d_in[19];
        bih  = (const float*)d_in[20]; bhh = (const float*)d_in[21];
        fc1W = (const float*)d_in[22]; fc1b = (const float*)d_in[23];
        fc2W = (const float*)d_in[24]; fc2b = (const float*)d_in[25];
    }

    const int T = 256;
    const int MT = cdiv(NN, 128);  // 782

    // idx 0-3 arranged so an early ncu sample hits k_tgemm
    k_splitB<<<cdiv(256 * NCH, T), T>>>(projW, p_Bproj, HID, 256, INDIM, 1);   // 0
    k_bnprep_all<<<1, 640>>>(bn1g, bn1b, bn1m, bn1v,
                             bn2g, bn2b, bn2m, bn2v,
                             bnfg, bnfb, bnfm, bnfv);                           // 1
    k_splitA<<<cdiv(NN * NCH, T), T>>>(x, p_xs, INDIM);                         // 2
    // h = relu(bn1(x @ projW^T + projb))
    k_tgemm<<<dim3(1, MT), 256, SMEM_DYN>>>(p_xs, p_Bproj, p_h, NN, HID, 256,
                                            projb, p_scale, p_shift, 1);        // 3
    k_splitA<<<cdiv(NN * NCH, T), T>>>(p_h, p_hs, HID);                         // 4
    k_splitB<<<cdiv(256 * NCH, T), T>>>(ggcW, p_Bggc, HID, 256, HID, 0);        // 5
    // m = h @ ggc_W[0]
    k_tgemm<<<dim3(1, MT), 256, SMEM_DYN>>>(p_hs, p_Bggc, p_m, NN, HID, 256,
                                            nullptr, nullptr, nullptr, 0);      // 6

    k_detect<<<1, 32>>>((const int*)edge, (const int*)batch);
    k_conv_edges<<<cdiv(2 * NE, T), T>>>(edge);
    k_conv_batch<<<cdiv(NN, T), T>>>(batch);
    for (int i = 1; i < 3; i++)
        k_splitB<<<cdiv(256 * NCH, T), T>>>(ggcW + (size_t)i * HID * HID,
                                            p_Bggc + (size_t)i * NSTEP * 256 * RSTR,
                                            HID, 256, HID, 0);
    k_splitB<<<cdiv(768 * NCH, T), T>>>(wih, p_Bwih, H3, 768, HID, 1);
    k_splitB<<<cdiv(768 * NCH, T), T>>>(whh, p_Bwhh, H3, 768, HID, 1);

    for (int it = 0; it < 3; it++) {
        if (it > 0) {
            k_tgemm<<<dim3(1, MT), 256, SMEM_DYN>>>(
                p_hs, p_Bggc + (size_t)it * NSTEP * 256 * RSTR,
                p_m, NN, HID, 256, nullptr, nullptr, nullptr, 0);
        }
        // agg = scatter_add(m[src] -> dst)
        k_zero<<<cdiv(NN * HID, T), T>>>(p_agg, NN * HID);
        k_scatter<<<cdiv(NE * 50, T), T>>>();
        k_splitA<<<cdiv(NN * NCH, T), T>>>(p_agg, p_as, HID);
        // gi = agg @ wih^T + bih ; gh = h @ whh^T + bhh
        k_tgemm<<<dim3(3, MT), 256, SMEM_DYN>>>(p_as, p_Bwih, p_gi, NN, H3, 768,
                                                bih, nullptr, nullptr, 0);
        k_tgemm<<<dim3(3, MT), 256, SMEM_DYN>>>(p_hs, p_Bwhh, p_gh, NN, H3, 768,
                                                bhh, nullptr, nullptr, 0);
        // h = GRU(...); write bf16 split for next iteration
        k_gru<<<cdiv(NN * 50, T), T>>>(it < 2 ? 1 : 0);
    }

    k_bn2relu<<<cdiv(NN * HID, T), T>>>();

    k_zero<<<cdiv(NG * 400, T), T>>>(p_pool, NG * 400);
    k_zero<<<cdiv(NG, T), T>>>(p_cnt, NG);
    k_pool<<<cdiv(NN * 50, T), T>>>();
    k_pool_fin<<<cdiv(NG * HID, T), T>>>();

    {
        dim3 grid(cdiv(HID, BN), cdiv(NG, BM));
        k_gemm<<<grid, T>>>(p_pool, fc1W, p_fc1, NG, HID, 2 * HID, 1,
                            fc1b, p_scale + 2 * HID, p_shift + 2 * HID, 1);
    }
    {
        dim3 grid(cdiv(2, BN), cdiv(NG, BM));
        k_gemm<<<grid, T>>>(p_fc1, fc2W, (float*)d_out, NG, 2, HID, 1,
                            fc2b, nullptr, nullptr, 0);
    }
}

// round 9
// speedup vs baseline: 1.2562x; 1.0257x over previous
#include <cuda_runtime.h>
#include <cuda_bf16.h>
#include <stdint.h>
#include <math.h>

#define NN    100000
#define NE    1600000
#define NG    512
#define HID   200
#define H3    600
#define INDIM 205

#define KP    208
#define K3    624
#define NSTEP 39        // K3/16
#define MPAD  100096    // 782*128
#define HW16  16        // halfwords per row per k-step (packed)

// ---------------- scratch (device globals; no runtime alloc) ----------------
__device__ float g_h  [(size_t)NN * HID];
__device__ float g_m  [(size_t)NN * HID];
__device__ float g_agg[(size_t)NN * HID];
__device__ float g_gi [(size_t)NN * H3];
__device__ float g_gh [(size_t)NN * H3];
__device__ float g_pool[NG * 2 * HID];
__device__ float g_cnt [NG];
__device__ float g_fc1 [NG * HID];
__device__ float g_scale[3 * HID];
__device__ float g_shift[3 * HID];
__device__ int   g_src[NE];
__device__ int   g_dst[NE];
__device__ int   g_batch[NN];
__device__ int   g_flag_e;
__device__ int   g_flag_b;

// packed k-blocked bf16 buffers with baked-in swizzle:
// element (ks, row, kk) at ((ks*ROWS + row)*16) + ((kk>>3) ^ ((row>>2)&1))*8 + (kk&7)
__device__ __nv_bfloat16 g_xs[(size_t)NSTEP * MPAD * HW16];
__device__ __nv_bfloat16 g_hs[(size_t)NSTEP * MPAD * HW16];
__device__ __nv_bfloat16 g_as[(size_t)NSTEP * MPAD * HW16];
__device__ __nv_bfloat16 g_Bproj[(size_t)NSTEP * 256 * HW16];
__device__ __nv_bfloat16 g_Bggc [3][(size_t)NSTEP * 256 * HW16];
__device__ __nv_bfloat16 g_Bwih [(size_t)NSTEP * 768 * HW16];
__device__ __nv_bfloat16 g_Bwhh [(size_t)NSTEP * 768 * HW16];

// ---------------- dtype detection ----------------
__global__ void k_detect(const int* __restrict__ ew, const int* __restrict__ bw) {
    int lane = threadIdx.x;
    int bad_e = 0, bad_b = 0;
    for (int w = 2 * NE - 255 + 2 * lane; w < 2 * NE; w += 64)
        if (ew[w] != 0) bad_e = 1;
    for (int w = NN - 255 + 2 * lane; w < NN; w += 64)
        if (bw[w] != 0) bad_b = 1;
    unsigned me = __ballot_sync(0xFFFFFFFFu, bad_e);
    unsigned mb = __ballot_sync(0xFFFFFFFFu, bad_b);
    if (lane == 0) { g_flag_e = (me == 0); g_flag_b = (mb == 0); }
}

__global__ void k_conv_edges(const void* __restrict__ e) {
    int i = blockIdx.x * blockDim.x + threadIdx.x;
    if (i >= 2 * NE) return;
    int v = g_flag_e ? (int)((const long long*)e)[i] : ((const int*)e)[i];
    if (i < NE) g_src[i] = v; else g_dst[i - NE] = v;
}

__global__ void k_conv_batch(const void* __restrict__ b) {
    int i = blockIdx.x * blockDim.x + threadIdx.x;
    if (i >= NN) return;
    g_batch[i] = g_flag_b ? (int)((const long long*)b)[i] : ((const int*)b)[i];
}

// ---------------- merged BN param prep ----------------
__global__ void k_bnprep_all(
    const float* g1, const float* b1, const float* m1, const float* v1,
    const float* g2, const float* b2, const float* m2, const float* v2,
    const float* gf, const float* bf, const float* mf, const float* vf) {
    int j = threadIdx.x;
    if (j >= 3 * HID) return;
    int which = j / HID, jj = j - which * HID;
    const float *g, *b, *m, *v;
    if (which == 0)      { g = g1; b = b1; m = m1; v = v1; }
    else if (which == 1) { g = g2; b = b2; m = m2; v = v2; }
    else                 { g = gf; b = bf; m = mf; v = vf; }
    float s = g[jj] * rsqrtf(v[jj] + 1e-5f);
    g_scale[j] = s;
    g_shift[j] = b[jj] - m[jj] * s;
}

// ---------------- bf16 split of activations (coalesced, swizzled) -----------
// thread idx = ks*(NN*2) + m*2 + half ; writes one 16B chunk
__global__ void k_splitA(const float* __restrict__ in, __nv_bfloat16* __restrict__ out,
                         int K) {
    int idx = blockIdx.x * blockDim.x + threadIdx.x;
    if (idx >= NSTEP * NN * 2) return;
    int ks   = idx / (NN * 2);
    int rem  = idx - ks * (NN * 2);
    int m    = rem >> 1;
    int half = rem & 1;
    int s  = ks / 13;
    int c  = (ks - s * 13) * 2 + half;   // 0..25
    int k0 = c * 8;
    const float* src = in + (size_t)m * K + k0;
    __nv_bfloat16 o[8];
#pragma unroll
    for (int i = 0; i < 8; i++) {
        float v = (k0 + i < K) ? src[i] : 0.f;
        __nv_bfloat16 hi = __float2bfloat16(v);
        o[i] = (s == 1) ? __float2bfloat16(v - __bfloat162float(hi)) : hi;
    }
    int swz = half ^ ((m >> 2) & 1);
    *(uint4*)(out + ((size_t)ks * MPAD + m) * HW16 + swz * 8) = *(const uint4*)o;
}

// ---------------- bf16 split of weights (swizzled) ----------------
__global__ void k_splitB(const float* __restrict__ W, __nv_bfloat16* __restrict__ out,
                         int N, int Npad, int K, int trans) {
    int idx = blockIdx.x * blockDim.x + threadIdx.x;
    if (idx >= NSTEP * Npad * 2) return;
    int ks   = idx / (Npad * 2);
    int rem  = idx - ks * (Npad * 2);
    int n    = rem >> 1;
    int half = rem & 1;
    int s  = ks / 13;
    int c  = (ks - s * 13) * 2 + half;
    int k0 = c * 8;
    __nv_bfloat16 o[8];
#pragma unroll
    for (int i = 0; i < 8; i++) {
        int k = k0 + i;
        float v = 0.f;
        if (n < N && k < K) v = trans ? W[(size_t)n * K + k] : W[(size_t)k * N + n];
        __nv_bfloat16 hi = __float2bfloat16(v);
        o[i] = (s == 2) ? __float2bfloat16(v - __bfloat162float(hi)) : hi;
    }
    int swz = half ^ ((n >> 2) & 1);
    *(uint4*)(out + ((size_t)ks * Npad + n) * HW16 + swz * 8) = *(const uint4*)o;
}

// ---------------- tensor-core GEMM: 128x256 tile, 512 thr, TMA pipeline -----
// 16 warps (4m x 4n), warp tile 32x64 (2 mi x 8 ni), packed swizzled smem.
#define STAGES       6
#define STAGE_A_HW   (128 * HW16)            // 2048 halfwords (4096 B)
#define STAGE_B_HW   (256 * HW16)            // 4096 halfwords (8192 B)
#define STAGE_HW     (STAGE_A_HW + STAGE_B_HW)
#define STAGE_BYTES  (STAGE_HW * 2)          // 12288
#define A_BYTES      (STAGE_A_HW * 2)
#define B_BYTES      (STAGE_B_HW * 2)
#define SMEM_DYN     (STAGES * STAGE_BYTES + 64)

__global__ void __launch_bounds__(512, 1)
k_tgemm(const __nv_bfloat16* __restrict__ A, const __nv_bfloat16* __restrict__ B,
        float* __restrict__ C, int M, int N, int NPADB,
        const float* __restrict__ bias,
        const float* __restrict__ scale, const float* __restrict__ shift,
        int relu) {
    extern __shared__ __align__(128) __nv_bfloat16 dsm[];

    const int tid  = threadIdx.x;
    const int warp = tid >> 5, lane = tid & 31;
    const int wm = warp & 3, wn = warp >> 2;       // 4 x 4 warps
    const int m0 = blockIdx.y * 128;
    const int n0 = blockIdx.x * 256;

    const uint32_t smem_base = (uint32_t)__cvta_generic_to_shared(dsm);
    const uint32_t mbar_base = smem_base + STAGES * STAGE_BYTES;

    if (tid == 0) {
        for (int s = 0; s < STAGES; s++)
            asm volatile("mbarrier.init.shared.b64 [%0], 1;"
                         :: "r"(mbar_base + s * 8) : "memory");
        asm volatile("fence.proxy.async.shared::cta;" ::: "memory");
    }
    __syncthreads();

    float acc[2][8][4];
#pragma unroll
    for (int mi = 0; mi < 2; mi++)
#pragma unroll
        for (int ni = 0; ni < 8; ni++)
#pragma unroll
            for (int j = 0; j < 4; j++) acc[mi][ni][j] = 0.f;

#define ISSUE(kf)                                                                \
    do {                                                                         \
        int slot_ = (kf) % STAGES;                                               \
        uint32_t mb_ = mbar_base + slot_ * 8;                                    \
        asm volatile("mbarrier.arrive.expect_tx.shared.b64 _, [%0], %1;"         \
                     :: "r"(mb_), "r"((uint32_t)STAGE_BYTES) : "memory");        \
        uint32_t da_ = smem_base + slot_ * STAGE_BYTES;                          \
        const __nv_bfloat16* sa_ = A + ((size_t)(kf) * MPAD + m0) * HW16;        \
        asm volatile("cp.async.bulk.shared::cta.global.mbarrier::complete_tx::bytes " \
                     "[%0], [%1], %2, [%3];"                                     \
                     :: "r"(da_), "l"(sa_), "r"((uint32_t)A_BYTES), "r"(mb_)     \
                     : "memory");                                                \
        uint32_t db_ = da_ + A_BYTES;                                            \
        const __nv_bfloat16* sb_ = B + ((size_t)(kf) * NPADB + n0) * HW16;       \
        asm volatile("cp.async.bulk.shared::cta.global.mbarrier::complete_tx::bytes " \
                     "[%0], [%1], %2, [%3];"                                     \
                     :: "r"(db_), "l"(sb_), "r"((uint32_t)B_BYTES), "r"(mb_)     \
                     : "memory");                                                \
    } while (0)

    if (tid == 0) {
        for (int kf = 0; kf < STAGES - 1 && kf < NSTEP; kf++) ISSUE(kf);
    }

    // per-lane constants
    const int lr   = lane & 15;               // A row within 16
    const int ch   = lane >> 4;               // A chunk select
    const int xa   = (lane >> 2) & 1;         // (row>>2)&1 for A rows (= bit2 of lr)
    const int bn   = lane >> 2;               // B row within 8
    const int xb   = (lane >> 4) & 1;         // (bn>>2)&1
    const int bk   = (lane & 3) * 2;          // halfword offset in chunk

    for (int ks = 0; ks < NSTEP; ks++) {
        __syncthreads();
        if (tid == 0) {
            int kf = ks + STAGES - 1;
            if (kf < NSTEP) ISSUE(kf);
        }
        const int slot = ks % STAGES;
        const uint32_t mb = mbar_base + slot * 8;
        const uint32_t parity = (uint32_t)((ks / STAGES) & 1);
        {
            uint32_t done = 0;
            while (!done) {
                asm volatile(
                    "{\n\t.reg .pred p;\n\t"
                    "mbarrier.try_wait.parity.acquire.cta.shared::cta.b64 p, [%1], %2;\n\t"
                    "selp.b32 %0, 1, 0, p;\n\t}"
                    : "=r"(done) : "r"(mb), "r"(parity) : "memory");
            }
        }

        const uint32_t aBase = smem_base + slot * STAGE_BYTES;
        const __nv_bfloat16* sBp = dsm + slot * STAGE_HW + STAGE_A_HW;

        uint32_t a[2][4];
        uint32_t b[8][2];
#pragma unroll
        for (int mi = 0; mi < 2; mi++) {
            int row = wm * 32 + mi * 16 + lr;
            uint32_t addr = aBase + (row * HW16 + ((ch ^ xa) << 3)) * 2;
            asm volatile("ldmatrix.sync.aligned.m8n8.x4.shared.b16 {%0,%1,%2,%3}, [%4];"
                         : "=r"(a[mi][0]), "=r"(a[mi][1]), "=r"(a[mi][2]), "=r"(a[mi][3])
                         : "r"(addr));
        }
#pragma unroll
        for (int ni = 0; ni < 8; ni++) {
            int row = wn * 64 + ni * 8 + bn;
            const __nv_bfloat16* p0 = sBp + row * HW16 + (xb << 3) + bk;
            const __nv_bfloat16* p1 = sBp + row * HW16 + ((1 ^ xb) << 3) + bk;
            b[ni][0] = *(const uint32_t*)p0;
            b[ni][1] = *(const uint32_t*)p1;
        }
#pragma unroll
        for (int mi = 0; mi < 2; mi++)
#pragma unroll
            for (int ni = 0; ni < 8; ni++) {
                asm volatile(
                    "mma.sync.aligned.m16n8k16.row.col.f32.bf16.bf16.f32 "
                    "{%0,%1,%2,%3}, {%4,%5,%6,%7}, {%8,%9}, {%0,%1,%2,%3};"
                    : "+f"(acc[mi][ni][0]), "+f"(acc[mi][ni][1]),
                      "+f"(acc[mi][ni][2]), "+f"(acc[mi][ni][3])
                    : "r"(a[mi][0]), "r"(a[mi][1]), "r"(a[mi][2]), "r"(a[mi][3]),
                      "r"(b[ni][0]), "r"(b[ni][1]));
            }
    }
#undef ISSUE

    // epilogue
    const int r = lane >> 2;
    const int c = (lane & 3) * 2;
#pragma unroll
    for (int mi = 0; mi < 2; mi++) {
#pragma unroll
        for (int ni = 0; ni < 8; ni++) {
            int n = n0 + wn * 64 + ni * 8 + c;
            if (n >= N) continue;
            float bia0 = 0.f, bia1 = 0.f, sc0 = 1.f, sc1 = 1.f, sh0 = 0.f, sh1 = 0.f;
            bool n1ok = (n + 1 < N);
            if (bias)  { bia0 = bias[n]; if (n1ok) bia1 = bias[n + 1]; }
            if (scale) { sc0 = scale[n]; sh0 = shift[n];
                         if (n1ok) { sc1 = scale[n + 1]; sh1 = shift[n + 1]; } }
#pragma unroll
            for (int half = 0; half < 2; half++) {
                int m = m0 + wm * 32 + mi * 16 + half * 8 + r;
                if (m >= M) continue;
                float v0 = acc[mi][ni][half * 2 + 0] + bia0;
                float v1 = acc[mi][ni][half * 2 + 1] + bia1;
                if (scale) { v0 = v0 * sc0 + sh0; v1 = v1 * sc1 + sh1; }
                if (relu)  { v0 = fmaxf(v0, 0.f); v1 = fmaxf(v1, 0.f); }
                float* p = C + (size_t)m * N + n;
                p[0] = v0;
                if (n1ok) p[1] = v1;
            }
        }
    }
}

// ---------------- small SIMT GEMM (fc1/fc2) ----------------
#define BM 64
#define BN 64
#define BK 16
__global__ void k_gemm(const float* __restrict__ A, const float* __restrict__ B,
                       float* __restrict__ C, int M, int N, int K, int transB,
                       const float* __restrict__ bias,
                       const float* __restrict__ scale,
                       const float* __restrict__ shift, int relu) {
    __shared__ float As[BK][BM];
    __shared__ float Bs[BK][BN + 4];
    const int m0 = blockIdx.y * BM;
    const int n0 = blockIdx.x * BN;
    const int tid = threadIdx.x;
    const int tm = tid >> 4;
    const int tn = tid & 15;
    float acc[4][4];
#pragma unroll
    for (int i = 0; i < 4; i++)
#pragma unroll
        for (int j = 0; j < 4; j++) acc[i][j] = 0.f;

    for (int k0 = 0; k0 < K; k0 += BK) {
        {
            int ar = tid >> 2;
            int ac = (tid & 3) * 4;
            int m = m0 + ar;
#pragma unroll
            for (int i = 0; i < 4; i++) {
                int k = k0 + ac + i;
                As[ac + i][ar] = (m < M && k < K) ? A[(size_t)m * K + k] : 0.f;
            }
        }
        if (!transB) {
            int br = tid >> 4;
            int bc = (tid & 15) * 4;
            int k = k0 + br;
#pragma unroll
            for (int i = 0; i < 4; i++) {
                int n = n0 + bc + i;
                Bs[br][bc + i] = (k < K && n < N) ? B[(size_t)k * N + n] : 0.f;
            }
        } else {
            int br = tid >> 2;
            int bc = (tid & 3) * 4;
            int n = n0 + br;
#pragma unroll
            for (int i = 0; i < 4; i++) {
                int k = k0 + bc + i;
                Bs[bc + i][br] = (n < N && k < K) ? B[(size_t)n * K + k] : 0.f;
            }
        }
        __syncthreads();
#pragma unroll
        for (int k = 0; k < BK; k++) {
            float a[4], b[4];
#pragma unroll
            for (int i = 0; i < 4; i++) a[i] = As[k][tm * 4 + i];
#pragma unroll
            for (int j = 0; j < 4; j++) b[j] = Bs[k][tn * 4 + j];
#pragma unroll
            for (int i = 0; i < 4; i++)
#pragma unroll
                for (int j = 0; j < 4; j++) acc[i][j] += a[i] * b[j];
        }
        __syncthreads();
    }
#pragma unroll
    for (int i = 0; i < 4; i++) {
        int m = m0 + tm * 4 + i;
        if (m >= M) continue;
#pragma unroll
        for (int j = 0; j < 4; j++) {
            int n = n0 + tn * 4 + j;
            if (n >= N) continue;
            float v = acc[i][j];
            if (bias)  v += bias[n];
            if (scale) v = v * scale[n] + shift[n];
            if (relu)  v = fmaxf(v, 0.f);
            C[(size_t)m * N + n] = v;
        }
    }
}

// ---------------- zero helper ----------------
__global__ void k_zero(float* __restrict__ p, int n) {
    int i = blockIdx.x * blockDim.x + threadIdx.x;
    if (i < n) p[i] = 0.f;
}

// ---------------- edge scatter-add ----------------
__global__ void k_scatter() {
    int t = blockIdx.x * blockDim.x + threadIdx.x;
    if (t >= NE * 50) return;
    int e = t / 50;
    int c = t - e * 50;
    int s = g_src[e];
    int d = g_dst[e];
    const float4 v = *reinterpret_cast<const float4*>(&g_m[(size_t)s * HID + c * 4]);
    float* p = &g_agg[(size_t)d * HID + c * 4];
    asm volatile("red.global.add.v4.f32 [%0], {%1,%2,%3,%4};"
                 :: "l"(p), "f"(v.x), "f"(v.y), "f"(v.z), "f"(v.w) : "memory");
}

// ---------------- GRU cell (vec4) + fused swizzled split write --------------
__device__ __forceinline__ float sigm(float x) { return 1.f / (1.f + expf(-x)); }

__global__ void k_gru(int write_split) {
    int t = blockIdx.x * blockDim.x + threadIdx.x;
    if (t >= NN * 50) return;
    int n = t / 50, q = t - n * 50;
    int j = q * 4;
    const float* gi = g_gi + (size_t)n * H3;
    const float* gh = g_gh + (size_t)n * H3;
    float4 ir4 = *(const float4*)(gi + j);
    float4 iz4 = *(const float4*)(gi + j + 200);
    float4 in4 = *(const float4*)(gi + j + 400);
    float4 hr4 = *(const float4*)(gh + j);
    float4 hz4 = *(const float4*)(gh + j + 200);
    float4 hn4 = *(const float4*)(gh + j + 400);
    float* hp = g_h + (size_t)n * HID + j;
    float4 h4 = *(float4*)hp;

    float hv[4];
    {
        const float ir[4] = {ir4.x, ir4.y, ir4.z, ir4.w};
        const float iz[4] = {iz4.x, iz4.y, iz4.z, iz4.w};
        const float in_[4] = {in4.x, in4.y, in4.z, in4.w};
        const float hr[4] = {hr4.x, hr4.y, hr4.z, hr4.w};
        const float hz[4] = {hz4.x, hz4.y, hz4.z, hz4.w};
        const float hn[4] = {hn4.x, hn4.y, hn4.z, hn4.w};
        const float ho[4] = {h4.x, h4.y, h4.z, h4.w};
#pragma unroll
        for (int i = 0; i < 4; i++) {
            float r = sigm(ir[i] + hr[i]);
            float z = sigm(iz[i] + hz[i]);
            float nn = tanhf(in_[i] + r * hn[i]);
            hv[i] = (1.f - z) * nn + z * ho[i];
        }
    }
    *(float4*)hp = make_float4(hv[0], hv[1], hv[2], hv[3]);

    if (write_split) {
        __nv_bfloat16 hi[4], lo[4];
#pragma unroll
        for (int i = 0; i < 4; i++) {
            hi[i] = __float2bfloat16(hv[i]);
            lo[i] = __float2bfloat16(hv[i] - __bfloat162float(hi[i]));
        }
        int c    = j >> 3;            // chunk 0..24
        int ksl  = c >> 1;            // k-step within section
        int half = c & 1;
        int off  = j & 7;             // 0 or 4
        int swz  = (half ^ ((n >> 2) & 1)) << 3;
        // sections: 0=hi, 1=lo, 2=hi
        __nv_bfloat16* o0 = g_hs + ((size_t)(ksl)      * MPAD + n) * HW16 + swz + off;
        __nv_bfloat16* o1 = g_hs + ((size_t)(13 + ksl) * MPAD + n) * HW16 + swz + off;
        __nv_bfloat16* o2 = g_hs + ((size_t)(26 + ksl) * MPAD + n) * HW16 + swz + off;
        ((uint32_t*)o0)[0] = *(const uint32_t*)&hi[0];
        ((uint32_t*)o0)[1] = *(const uint32_t*)&hi[2];
        ((uint32_t*)o1)[0] = *(const uint32_t*)&lo[0];
        ((uint32_t*)o1)[1] = *(const uint32_t*)&lo[2];
        ((uint32_t*)o2)[0] = *(const uint32_t*)&hi[0];
        ((uint32_t*)o2)[1] = *(const uint32_t*)&hi[2];
    }
}

__global__ void k_bn2relu() {
    int idx = blockIdx.x * blockDim.x + threadIdx.x;
    if (idx >= NN * HID) return;
    int j = idx % HID;
    g_h[idx] = fmaxf(g_h[idx] * g_scale[HID + j] + g_shift[HID + j], 0.f);
}

// ---------------- pooling ----------------
__global__ void k_pool() {
    int t = blockIdx.x * blockDim.x + threadIdx.x;
    if (t >= NN * 50) return;
    int node = t / 50;
    int c = t - node * 50;
    int b = g_batch[node];
    const float4 v = *reinterpret_cast<const float4*>(&g_h[(size_t)node * HID + c * 4]);
    float* mp = &g_pool[b * 400 + c * 4];
    atomicAdd(mp + 0, v.x); atomicAdd(mp + 1, v.y);
    atomicAdd(mp + 2, v.z); atomicAdd(mp + 3, v.w);
    int* xp = (int*)&g_pool[b * 400 + 200 + c * 4];
    atomicMax(xp + 0, __float_as_int(v.x));
    atomicMax(xp + 1, __float_as_int(v.y));
    atomicMax(xp + 2, __float_as_int(v.z));
    atomicMax(xp + 3, __float_as_int(v.w));
    if (c == 0) atomicAdd(&g_cnt[b], 1.0f);
}

__global__ void k_pool_fin() {
    int idx = blockIdx.x * blockDim.x + threadIdx.x;
    if (idx >= NG * HID) return;
    int g = idx / HID;
    int j = idx - g * HID;
    g_pool[g * 400 + j] *= 1.f / fmaxf(g_cnt[g], 1.f);
}

// ---------------- host launch ----------------
static inline int cdiv(int a, int b) { return (a + b - 1) / b; }

extern "C" void kernel_launch(void* const* d_in, const int* in_sizes, int n_in,
                              void* d_out, int out_size) {
    static bool init = false;
    static float *p_h, *p_m, *p_agg, *p_gi, *p_gh, *p_pool, *p_cnt, *p_fc1, *p_scale, *p_shift;
    static __nv_bfloat16 *p_xs, *p_hs, *p_as, *p_Bproj, *p_Bggc, *p_Bwih, *p_Bwhh;
    if (!init) {
        cudaGetSymbolAddress((void**)&p_h, g_h);
        cudaGetSymbolAddress((void**)&p_m, g_m);
        cudaGetSymbolAddress((void**)&p_agg, g_agg);
        cudaGetSymbolAddress((void**)&p_gi, g_gi);
        cudaGetSymbolAddress((void**)&p_gh, g_gh);
        cudaGetSymbolAddress((void**)&p_pool, g_pool);
        cudaGetSymbolAddress((void**)&p_cnt, g_cnt);
        cudaGetSymbolAddress((void**)&p_fc1, g_fc1);
        cudaGetSymbolAddress((void**)&p_scale, g_scale);
        cudaGetSymbolAddress((void**)&p_shift, g_shift);
        cudaGetSymbolAddress((void**)&p_xs, g_xs);
        cudaGetSymbolAddress((void**)&p_hs, g_hs);
        cudaGetSymbolAddress((void**)&p_as, g_as);
        cudaGetSymbolAddress((void**)&p_Bproj, g_Bproj);
        cudaGetSymbolAddress((void**)&p_Bggc, g_Bggc);
        cudaGetSymbolAddress((void**)&p_Bwih, g_Bwih);
        cudaGetSymbolAddress((void**)&p_Bwhh, g_Bwhh);
        cudaFuncSetAttribute(k_tgemm, cudaFuncAttributeMaxDynamicSharedMemorySize,
                             SMEM_DYN);
        init = true;
    }

    const float *x, *projW, *projb;
    const void  *edge, *batch;
    const float *bn1g, *bn1b, *bn1m, *bn1v;
    const float *bn2g, *bn2b, *bn2m, *bn2v;
    const float *bnfg, *bnfb, *bnfm, *bnfv;
    const float *ggcW, *wih, *whh, *bih, *bhh, *fc1W, *fc1b, *fc2W, *fc2b;

    x     = (const float*)d_in[0];
    edge  = d_in[1];
    batch = d_in[2];
    projW = (const float*)d_in[3];
    projb = (const float*)d_in[4];
    bn1g = (const float*)d_in[5]; bn1b = (const float*)d_in[6];
    bn1m = (const float*)d_in[7]; bn1v = (const float*)d_in[8];

    if (in_sizes[9] == 120000) {
        ggcW = (const float*)d_in[9];
        wih  = (const float*)d_in[10]; whh = (const float*)d_in[11];
        bih  = (const float*)d_in[12]; bhh = (const float*)d_in[13];
        bn2g = (const float*)d_in[14]; bn2b = (const float*)d_in[15];
        bn2m = (const float*)d_in[16]; bn2v = (const float*)d_in[17];
        fc1W = (const float*)d_in[18]; fc1b = (const float*)d_in[19];
        bnfg = (const float*)d_in[20]; bnfb = (const float*)d_in[21];
        bnfm = (const float*)d_in[22]; bnfv = (const float*)d_in[23];
        fc2W = (const float*)d_in[24]; fc2b = (const float*)d_in[25];
    } else {
        bn2g = (const float*)d_in[9];  bn2b = (const float*)d_in[10];
        bn2m = (const float*)d_in[11]; bn2v = (const float*)d_in[12];
        bnfg = (const float*)d_in[13]; bnfb = (const float*)d_in[14];
        bnfm = (const float*)d_in[15]; bnfv = (const float*)d_in[16];
        ggcW = (const float*)d_in[17];
        wih  = (const float*)d_in[18]; whh = (const float*)d_in[19];
        bih  = (const float*)d_in[20]; bhh = (const float*)d_in[21];
        fc1W = (const float*)d_in[22]; fc1b = (const float*)d_in[23];
        fc2W = (const float*)d_in[24]; fc2b = (const float*)d_in[25];
    }

    const int T = 256;
    const int MT = cdiv(NN, 128);  // 782

    // idx 0-3 arranged so an early ncu sample hits k_tgemm
    k_splitB<<<cdiv(NSTEP * 256 * 2, T), T>>>(projW, p_Bproj, HID, 256, INDIM, 1); // 0
    k_bnprep_all<<<1, 640>>>(bn1g, bn1b, bn1m, bn1v,
                             bn2g, bn2b, bn2m, bn2v,
                             bnfg, bnfb, bnfm, bnfv);                              // 1
    k_splitA<<<cdiv(NSTEP * NN * 2, T), T>>>(x, p_xs, INDIM);                      // 2
    // h = relu(bn1(x @ projW^T + projb))
    k_tgemm<<<dim3(1, MT), 512, SMEM_DYN>>>(p_xs, p_Bproj, p_h, NN, HID, 256,
                                            projb, p_scale, p_shift, 1);           // 3
    k_splitA<<<cdiv(NSTEP * NN * 2, T), T>>>(p_h, p_hs, HID);                      // 4
    k_splitB<<<cdiv(NSTEP * 256 * 2, T), T>>>(ggcW, p_Bggc, HID, 256, HID, 0);     // 5
    // m = h @ ggc_W[0]
    k_tgemm<<<dim3(1, MT), 512, SMEM_DYN>>>(p_hs, p_Bggc, p_m, NN, HID, 256,
                                            nullptr, nullptr, nullptr, 0);         // 6

    k_detect<<<1, 32>>>((const int*)edge, (const int*)batch);
    k_conv_edges<<<cdiv(2 * NE, T), T>>>(edge);
    k_conv_batch<<<cdiv(NN, T), T>>>(batch);
    for (int i = 1; i < 3; i++)
        k_splitB<<<cdiv(NSTEP * 256 * 2, T), T>>>(ggcW + (size_t)i * HID * HID,
                                                  p_Bggc + (size_t)i * NSTEP * 256 * HW16,
                                                  HID, 256, HID, 0);
    k_splitB<<<cdiv(NSTEP * 768 * 2, T), T>>>(wih, p_Bwih, H3, 768, HID, 1);
    k_splitB<<<cdiv(NSTEP * 768 * 2, T), T>>>(whh, p_Bwhh, H3, 768, HID, 1);

    for (int it = 0; it < 3; it++) {
        if (it > 0) {
            k_tgemm<<<dim3(1, MT), 512, SMEM_DYN>>>(
                p_hs, p_Bggc + (size_t)it * NSTEP * 256 * HW16,
                p_m, NN, HID, 256, nullptr, nullptr, nullptr, 0);
        }
        // agg = scatter_add(m[src] -> dst)
        k_zero<<<cdiv(NN * HID, T), T>>>(p_agg, NN * HID);
        k_scatter<<<cdiv(NE * 50, T), T>>>();
        k_splitA<<<cdiv(NSTEP * NN * 2, T), T>>>(p_agg, p_as, HID);
        // gi = agg @ wih^T + bih ; gh = h @ whh^T + bhh
        k_tgemm<<<dim3(3, MT), 512, SMEM_DYN>>>(p_as, p_Bwih, p_gi, NN, H3, 768,
                                                bih, nullptr, nullptr, 0);
        k_tgemm<<<dim3(3, MT), 512, SMEM_DYN>>>(p_hs, p_Bwhh, p_gh, NN, H3, 768,
                                                bhh, nullptr, nullptr, 0);
        // h = GRU(...); write swizzled split for next iteration
        k_gru<<<cdiv(NN * 50, T), T>>>(it < 2 ? 1 : 0);
    }

    k_bn2relu<<<cdiv(NN * HID, T), T>>>();

    k_zero<<<cdiv(NG * 400, T), T>>>(p_pool, NG * 400);
    k_zero<<<cdiv(NG, T), T>>>(p_cnt, NG);
    k_pool<<<cdiv(NN * 50, T), T>>>();
    k_pool_fin<<<cdiv(NG * HID, T), T>>>();

    {
        dim3 grid(cdiv(HID, BN), cdiv(NG, BM));
        k_gemm<<<grid, T>>>(p_pool, fc1W, p_fc1, NG, HID, 2 * HID, 1,
                            fc1b, p_scale + 2 * HID, p_shift + 2 * HID, 1);
    }
    {
        dim3 grid(cdiv(2, BN), cdiv(NG, BM));
        k_gemm<<<grid, T>>>(p_fc1, fc2W, (float*)d_out, NG, 2, HID, 1,
                            fc2b, nullptr, nullptr, 0);
    }
}

// round 11
// speedup vs baseline: 1.4171x; 1.1281x over previous
#include <cuda_runtime.h>
#include <cuda_bf16.h>
#include <stdint.h>
#include <math.h>

#define NN    100000
#define NE    1600000
#define NG    512
#define HID   200
#define H3    600
#define INDIM 205

#define KP    208
#define K3    624
#define NSTEP 39        // K3/16
#define MPAD  100096    // >= 1563*64
#define HW16  16        // halfwords per row per k-step (packed, swizzled)

// ---------------- scratch ----------------
__device__ float g_h  [(size_t)NN * HID];
__device__ float g_m  [(size_t)NN * HID];
__device__ float g_agg[(size_t)NN * HID];
__device__ float g_gi [(size_t)NN * H3];
__device__ float g_pool[NG * 2 * HID];
__device__ float g_cnt [NG];
__device__ float g_fc1 [NG * HID];
__device__ float g_scale[3 * HID];
__device__ float g_shift[3 * HID];
__device__ int   g_src[NE];
__device__ int   g_dst[NE];
__device__ int   g_batch[NN];
__device__ int   g_flag_e;
__device__ int   g_flag_b;

// packed k-blocked bf16 buffers, swizzle baked into gmem layout:
// element (ks,row,kk) at ((ks*ROWS+row)*16) + ((kk>>3) ^ ((row>>2)&1))*8 + (kk&7)
__device__ __nv_bfloat16 g_xs[(size_t)NSTEP * MPAD * HW16];
__device__ __nv_bfloat16 g_hs[(size_t)NSTEP * MPAD * HW16];
__device__ __nv_bfloat16 g_as[(size_t)NSTEP * MPAD * HW16];
__device__ __nv_bfloat16 g_Bproj[(size_t)NSTEP * 256 * HW16];
__device__ __nv_bfloat16 g_Bggc [3][(size_t)NSTEP * 256 * HW16];
__device__ __nv_bfloat16 g_Bwih [(size_t)NSTEP * 768 * HW16];
__device__ __nv_bfloat16 g_Bwhh [(size_t)NSTEP * 768 * HW16];

// ---------------- dtype detection ----------------
__global__ void k_detect(const int* __restrict__ ew, const int* __restrict__ bw) {
    int lane = threadIdx.x;
    int bad_e = 0, bad_b = 0;
    for (int w = 2 * NE - 255 + 2 * lane; w < 2 * NE; w += 64)
        if (ew[w] != 0) bad_e = 1;
    for (int w = NN - 255 + 2 * lane; w < NN; w += 64)
        if (bw[w] != 0) bad_b = 1;
    unsigned me = __ballot_sync(0xFFFFFFFFu, bad_e);
    unsigned mb = __ballot_sync(0xFFFFFFFFu, bad_b);
    if (lane == 0) { g_flag_e = (me == 0); g_flag_b = (mb == 0); }
}

__global__ void k_conv_edges(const void* __restrict__ e) {
    int i = blockIdx.x * blockDim.x + threadIdx.x;
    if (i >= 2 * NE) return;
    int v = g_flag_e ? (int)((const long long*)e)[i] : ((const int*)e)[i];
    if (i < NE) g_src[i] = v; else g_dst[i - NE] = v;
}

__global__ void k_conv_batch(const void* __restrict__ b) {
    int i = blockIdx.x * blockDim.x + threadIdx.x;
    if (i >= NN) return;
    g_batch[i] = g_flag_b ? (int)((const long long*)b)[i] : ((const int*)b)[i];
}

// ---------------- merged BN param prep ----------------
__global__ void k_bnprep_all(
    const float* g1, const float* b1, const float* m1, const float* v1,
    const float* g2, const float* b2, const float* m2, const float* v2,
    const float* gf, const float* bf, const float* mf, const float* vf) {
    int j = threadIdx.x;
    if (j >= 3 * HID) return;
    int which = j / HID, jj = j - which * HID;
    const float *g, *b, *m, *v;
    if (which == 0)      { g = g1; b = b1; m = m1; v = v1; }
    else if (which == 1) { g = g2; b = b2; m = m2; v = v2; }
    else                 { g = gf; b = bf; m = mf; v = vf; }
    float s = g[jj] * rsqrtf(v[jj] + 1e-5f);
    g_scale[j] = s;
    g_shift[j] = b[jj] - m[jj] * s;
}

// ---------------- bf16 split of activations (coalesced, swizzled) -----------
__global__ void k_splitA(const float* __restrict__ in, __nv_bfloat16* __restrict__ out,
                         int K) {
    int idx = blockIdx.x * blockDim.x + threadIdx.x;
    if (idx >= NSTEP * NN * 2) return;
    int ks   = idx / (NN * 2);
    int rem  = idx - ks * (NN * 2);
    int m    = rem >> 1;
    int half = rem & 1;
    int s  = ks / 13;
    int c  = (ks - s * 13) * 2 + half;
    int k0 = c * 8;
    const float* src = in + (size_t)m * K + k0;
    __nv_bfloat16 o[8];
#pragma unroll
    for (int i = 0; i < 8; i++) {
        float v = (k0 + i < K) ? src[i] : 0.f;
        __nv_bfloat16 hi = __float2bfloat16(v);
        o[i] = (s == 1) ? __float2bfloat16(v - __bfloat162float(hi)) : hi;
    }
    int swz = half ^ ((m >> 2) & 1);
    *(uint4*)(out + ((size_t)ks * MPAD + m) * HW16 + swz * 8) = *(const uint4*)o;
}

// ---------------- bf16 split of weights (swizzled) ----------------
__global__ void k_splitB(const float* __restrict__ W, __nv_bfloat16* __restrict__ out,
                         int N, int Npad, int K, int trans) {
    int idx = blockIdx.x * blockDim.x + threadIdx.x;
    if (idx >= NSTEP * Npad * 2) return;
    int ks   = idx / (Npad * 2);
    int rem  = idx - ks * (Npad * 2);
    int n    = rem >> 1;
    int half = rem & 1;
    int s  = ks / 13;
    int c  = (ks - s * 13) * 2 + half;
    int k0 = c * 8;
    __nv_bfloat16 o[8];
#pragma unroll
    for (int i = 0; i < 8; i++) {
        int k = k0 + i;
        float v = 0.f;
        if (n < N && k < K) v = trans ? W[(size_t)n * K + k] : W[(size_t)k * N + n];
        __nv_bfloat16 hi = __float2bfloat16(v);
        o[i] = (s == 2) ? __float2bfloat16(v - __bfloat162float(hi)) : hi;
    }
    int swz = half ^ ((n >> 2) & 1);
    *(uint4*)(out + ((size_t)ks * Npad + n) * HW16 + swz * 8) = *(const uint4*)o;
}

// ---------------- split-pair writer (device helper) ----------------
__device__ __forceinline__ void write_split_pair(
    __nv_bfloat16* __restrict__ hs, int m, int j /*even*/, float v0, float v1) {
    __nv_bfloat16 h0 = __float2bfloat16(v0), h1 = __float2bfloat16(v1);
    __nv_bfloat16 l0 = __float2bfloat16(v0 - __bfloat162float(h0));
    __nv_bfloat16 l1 = __float2bfloat16(v1 - __bfloat162float(h1));
    uint32_t hi2 = ((uint32_t)*(uint16_t*)&h1 << 16) | *(uint16_t*)&h0;
    uint32_t lo2 = ((uint32_t)*(uint16_t*)&l1 << 16) | *(uint16_t*)&l0;
    int c = j >> 3, ksl = c >> 1, half = c & 1, off = j & 7;
    int swz = (half ^ ((m >> 2) & 1)) << 3;
    *(uint32_t*)(hs + ((size_t)(ksl)      * MPAD + m) * HW16 + swz + off) = hi2;
    *(uint32_t*)(hs + ((size_t)(13 + ksl) * MPAD + m) * HW16 + swz + off) = lo2;
    *(uint32_t*)(hs + ((size_t)(26 + ksl) * MPAD + m) * HW16 + swz + off) = hi2;
}

// ---------------- tensor GEMM A: 128x256 tile, 512 thr (R9-proven) ----------
#define STAGES       6
#define STAGE_A_HW   (128 * HW16)
#define STAGE_B_HW   (256 * HW16)
#define STAGE_HW     (STAGE_A_HW + STAGE_B_HW)
#define STAGE_BYTES  (STAGE_HW * 2)          // 12288
#define A_BYTES      (STAGE_A_HW * 2)
#define B_BYTES      (STAGE_B_HW * 2)
#define SMEM_DYN     (STAGES * STAGE_BYTES + 64)

__global__ void __launch_bounds__(512, 1)
k_tgemm(const __nv_bfloat16* __restrict__ A, const __nv_bfloat16* __restrict__ B,
        float* __restrict__ C, int M, int N, int NPADB,
        const float* __restrict__ bias,
        const float* __restrict__ scale, const float* __restrict__ shift,
        int relu, __nv_bfloat16* __restrict__ hs_out) {
    extern __shared__ __align__(128) __nv_bfloat16 dsm[];

    const int tid  = threadIdx.x;
    const int warp = tid >> 5, lane = tid & 31;
    const int wm = warp & 3, wn = warp >> 2;       // 4 x 4
    const int m0 = blockIdx.y * 128;
    const int n0 = blockIdx.x * 256;

    const uint32_t smem_base = (uint32_t)__cvta_generic_to_shared(dsm);
    const uint32_t mbar_base = smem_base + STAGES * STAGE_BYTES;

    if (tid == 0) {
        for (int s = 0; s < STAGES; s++)
            asm volatile("mbarrier.init.shared.b64 [%0], 1;" :: "r"(mbar_base + s * 8) : "memory");
        asm volatile("fence.proxy.async.shared::cta;" ::: "memory");
    }
    __syncthreads();

    float acc[2][8][4];
#pragma unroll
    for (int mi = 0; mi < 2; mi++)
#pragma unroll
        for (int ni = 0; ni < 8; ni++)
#pragma unroll
            for (int j = 0; j < 4; j++) acc[mi][ni][j] = 0.f;

#define ISSUE(kf)                                                                \
    do {                                                                         \
        int slot_ = (kf) % STAGES;                                               \
        uint32_t mb_ = mbar_base + slot_ * 8;                                    \
        asm volatile("mbarrier.arrive.expect_tx.shared.b64 _, [%0], %1;"         \
                     :: "r"(mb_), "r"((uint32_t)STAGE_BYTES) : "memory");        \
        uint32_t da_ = smem_base + slot_ * STAGE_BYTES;                          \
        const __nv_bfloat16* sa_ = A + ((size_t)(kf) * MPAD + m0) * HW16;        \
        asm volatile("cp.async.bulk.shared::cta.global.mbarrier::complete_tx::bytes " \
                     "[%0], [%1], %2, [%3];"                                     \
                     :: "r"(da_), "l"(sa_), "r"((uint32_t)A_BYTES), "r"(mb_)     \
                     : "memory");                                                \
        uint32_t db_ = da_ + A_BYTES;                                            \
        const __nv_bfloat16* sb_ = B + ((size_t)(kf) * NPADB + n0) * HW16;       \
        asm volatile("cp.async.bulk.shared::cta.global.mbarrier::complete_tx::bytes " \
                     "[%0], [%1], %2, [%3];"                                     \
                     :: "r"(db_), "l"(sb_), "r"((uint32_t)B_BYTES), "r"(mb_)     \
                     : "memory");                                                \
    } while (0)

    if (tid == 0)
        for (int kf = 0; kf < STAGES - 1 && kf < NSTEP; kf++) ISSUE(kf);

    const int lr = lane & 15;
    const int ch = lane >> 4;
    const int xa = (lane >> 2) & 1;
    const int bn = lane >> 2;
    const int xb = (lane >> 4) & 1;
    const int bk = (lane & 3) * 2;

    for (int ks = 0; ks < NSTEP; ks++) {
        __syncthreads();
        if (tid == 0) {
            int kf = ks + STAGES - 1;
            if (kf < NSTEP) ISSUE(kf);
        }
        const int slot = ks % STAGES;
        const uint32_t mb = mbar_base + slot * 8;
        const uint32_t parity = (uint32_t)((ks / STAGES) & 1);
        {
            uint32_t done = 0;
            while (!done) {
                asm volatile(
                    "{\n\t.reg .pred p;\n\t"
                    "mbarrier.try_wait.parity.acquire.cta.shared::cta.b64 p, [%1], %2;\n\t"
                    "selp.b32 %0, 1, 0, p;\n\t}"
                    : "=r"(done) : "r"(mb), "r"(parity) : "memory");
            }
        }

        const uint32_t aBase = smem_base + slot * STAGE_BYTES;
        const __nv_bfloat16* sBp = dsm + slot * STAGE_HW + STAGE_A_HW;

        uint32_t a[2][4];
        uint32_t b[8][2];
#pragma unroll
        for (int mi = 0; mi < 2; mi++) {
            int row = wm * 32 + mi * 16 + lr;
            uint32_t addr = aBase + (row * HW16 + ((ch ^ xa) << 3)) * 2;
            asm volatile("ldmatrix.sync.aligned.m8n8.x4.shared.b16 {%0,%1,%2,%3}, [%4];"
                         : "=r"(a[mi][0]), "=r"(a[mi][1]), "=r"(a[mi][2]), "=r"(a[mi][3])
                         : "r"(addr));
        }
#pragma unroll
        for (int ni = 0; ni < 8; ni++) {
            int row = wn * 64 + ni * 8 + bn;
            b[ni][0] = *(const uint32_t*)(sBp + row * HW16 + (xb << 3) + bk);
            b[ni][1] = *(const uint32_t*)(sBp + row * HW16 + ((1 ^ xb) << 3) + bk);
        }
#pragma unroll
        for (int mi = 0; mi < 2; mi++)
#pragma unroll
            for (int ni = 0; ni < 8; ni++) {
                asm volatile(
                    "mma.sync.aligned.m16n8k16.row.col.f32.bf16.bf16.f32 "
                    "{%0,%1,%2,%3}, {%4,%5,%6,%7}, {%8,%9}, {%0,%1,%2,%3};"
                    : "+f"(acc[mi][ni][0]), "+f"(acc[mi][ni][1]),
                      "+f"(acc[mi][ni][2]), "+f"(acc[mi][ni][3])
                    : "r"(a[mi][0]), "r"(a[mi][1]), "r"(a[mi][2]), "r"(a[mi][3]),
                      "r"(b[ni][0]), "r"(b[ni][1]));
            }
    }
#undef ISSUE

    const int r = lane >> 2;
    const int c = (lane & 3) * 2;
#pragma unroll
    for (int mi = 0; mi < 2; mi++) {
#pragma unroll
        for (int ni = 0; ni < 8; ni++) {
            int n = n0 + wn * 64 + ni * 8 + c;
            if (n >= N) continue;
            float bia0 = 0.f, bia1 = 0.f, sc0 = 1.f, sc1 = 1.f, sh0 = 0.f, sh1 = 0.f;
            bool n1ok = (n + 1 < N);
            if (bias)  { bia0 = bias[n]; if (n1ok) bia1 = bias[n + 1]; }
            if (scale) { sc0 = scale[n]; sh0 = shift[n];
                         if (n1ok) { sc1 = scale[n + 1]; sh1 = shift[n + 1]; } }
#pragma unroll
            for (int half = 0; half < 2; half++) {
                int m = m0 + wm * 32 + mi * 16 + half * 8 + r;
                if (m >= M) continue;
                float v0 = acc[mi][ni][half * 2 + 0] + bia0;
                float v1 = acc[mi][ni][half * 2 + 1] + bia1;
                if (scale) { v0 = v0 * sc0 + sh0; v1 = v1 * sc1 + sh1; }
                if (relu)  { v0 = fmaxf(v0, 0.f); v1 = fmaxf(v1, 0.f); }
                float* p = C + (size_t)m * N + n;
                p[0] = v0;
                if (n1ok) p[1] = v1;
                if (hs_out && n1ok) write_split_pair(hs_out, m, n, v0, v1);
            }
        }
    }
}

// ---------------- tensor GEMM B: 64 x 640 tile, optional fused GRU ----------
// 16 warps (2m x 8n), warp tile 32x80 (2 mi x 10 ni).
// mode 1: C[m,600] = A@B^T + bias.   mode 2: gh=A@B^T+bias, fuse GRU with gi.
#define T64S        4
#define T64_A_B     (64 * 32)                 // 2048
#define T64_B_B     (640 * 32)                // 20480
#define T64_ST_B    (T64_A_B + T64_B_B)       // 22528
#define T64_EPI_STR 608
#define T64_EPI_B   (64 * T64_EPI_STR * 4)    // 155648
#define T64_SMEM    (T64_EPI_B + 64)

__global__ void __launch_bounds__(512, 1)
k_tg64(const __nv_bfloat16* __restrict__ A, const __nv_bfloat16* __restrict__ B,
       int NPADB, const float* __restrict__ bias,
       float* __restrict__ C,
       const float* __restrict__ gi_in, float* __restrict__ h_io,
       __nv_bfloat16* __restrict__ hs_out, int mode, int do_split) {
    extern __shared__ __align__(128) __nv_bfloat16 dsm[];

    const int tid  = threadIdx.x;
    const int warp = tid >> 5, lane = tid & 31;
    const int wm = warp & 1, wn = warp >> 1;       // 2 x 8
    const int m0 = blockIdx.y * 64;

    const uint32_t smem_base = (uint32_t)__cvta_generic_to_shared(dsm);
    const uint32_t mbar_base = smem_base + T64_EPI_B;   // barriers beyond epi region

    if (tid == 0) {
        for (int s = 0; s < T64S; s++)
            asm volatile("mbarrier.init.shared.b64 [%0], 1;" :: "r"(mbar_base + s * 8) : "memory");
        asm volatile("fence.proxy.async.shared::cta;" ::: "memory");
    }
    __syncthreads();

    float acc[2][10][4];
#pragma unroll
    for (int mi = 0; mi < 2; mi++)
#pragma unroll
        for (int ni = 0; ni < 10; ni++)
#pragma unroll
            for (int j = 0; j < 4; j++) acc[mi][ni][j] = 0.f;

#define ISSUE64(kf)                                                              \
    do {                                                                         \
        int slot_ = (kf) % T64S;                                                 \
        uint32_t mb_ = mbar_base + slot_ * 8;                                    \
        asm volatile("mbarrier.arrive.expect_tx.shared.b64 _, [%0], %1;"         \
                     :: "r"(mb_), "r"((uint32_t)T64_ST_B) : "memory");           \
        uint32_t da_ = smem_base + slot_ * T64_ST_B;                             \
        const __nv_bfloat16* sa_ = A + ((size_t)(kf) * MPAD + m0) * HW16;        \
        asm volatile("cp.async.bulk.shared::cta.global.mbarrier::complete_tx::bytes " \
                     "[%0], [%1], %2, [%3];"                                     \
                     :: "r"(da_), "l"(sa_), "r"((uint32_t)T64_A_B), "r"(mb_)     \
                     : "memory");                                                \
        uint32_t db_ = da_ + T64_A_B;                                            \
        const __nv_bfloat16* sb_ = B + (size_t)(kf) * NPADB * HW16;              \
        asm volatile("cp.async.bulk.shared::cta.global.mbarrier::complete_tx::bytes " \
                     "[%0], [%1], %2, [%3];"                                     \
                     :: "r"(db_), "l"(sb_), "r"((uint32_t)T64_B_B), "r"(mb_)     \
                     : "memory");                                                \
    } while (0)

    if (tid == 0)
        for (int kf = 0; kf < T64S - 1 && kf < NSTEP; kf++) ISSUE64(kf);

    const int lr = lane & 15;
    const int ch = lane >> 4;
    const int xa = (lane >> 2) & 1;
    const int bn = lane >> 2;
    const int xb = (lane >> 4) & 1;
    const int bk = (lane & 3) * 2;

    for (int ks = 0; ks < NSTEP; ks++) {
        __syncthreads();
        if (tid == 0) {
            int kf = ks + T64S - 1;
            if (kf < NSTEP) ISSUE64(kf);
        }
        const int slot = ks % T64S;
        const uint32_t mb = mbar_base + slot * 8;
        const uint32_t parity = (uint32_t)((ks / T64S) & 1);
        {
            uint32_t done = 0;
            while (!done) {
                asm volatile(
                    "{\n\t.reg .pred p;\n\t"
                    "mbarrier.try_wait.parity.acquire.cta.shared::cta.b64 p, [%1], %2;\n\t"
                    "selp.b32 %0, 1, 0, p;\n\t}"
                    : "=r"(done) : "r"(mb), "r"(parity) : "memory");
            }
        }

        const uint32_t aBase = smem_base + slot * T64_ST_B;
        const __nv_bfloat16* sBp = dsm + slot * (T64_ST_B / 2) + (T64_A_B / 2);

        uint32_t a[2][4];
        uint32_t b[10][2];
#pragma unroll
        for (int mi = 0; mi < 2; mi++) {
            int row = wm * 32 + mi * 16 + lr;
            uint32_t addr = aBase + (row * HW16 + ((ch ^ xa) << 3)) * 2;
            asm volatile("ldmatrix.sync.aligned.m8n8.x4.shared.b16 {%0,%1,%2,%3}, [%4];"
                         : "=r"(a[mi][0]), "=r"(a[mi][1]), "=r"(a[mi][2]), "=r"(a[mi][3])
                         : "r"(addr));
        }
#pragma unroll
        for (int ni = 0; ni < 10; ni++) {
            int row = wn * 80 + ni * 8 + bn;
            b[ni][0] = *(const uint32_t*)(sBp + row * HW16 + (xb << 3) + bk);
            b[ni][1] = *(const uint32_t*)(sBp + row * HW16 + ((1 ^ xb) << 3) + bk);
        }
#pragma unroll
        for (int mi = 0; mi < 2; mi++)
#pragma unroll
            for (int ni = 0; ni < 10; ni++) {
                asm volatile(
                    "mma.sync.aligned.m16n8k16.row.col.f32.bf16.bf16.f32 "
                    "{%0,%1,%2,%3}, {%4,%5,%6,%7}, {%8,%9}, {%0,%1,%2,%3};"
                    : "+f"(acc[mi][ni][0]), "+f"(acc[mi][ni][1]),
                      "+f"(acc[mi][ni][2]), "+f"(acc[mi][ni][3])
                    : "r"(a[mi][0]), "r"(a[mi][1]), "r"(a[mi][2]), "r"(a[mi][3]),
                      "r"(b[ni][0]), "r"(b[ni][1]));
            }
    }
#undef ISSUE64

    const int r = lane >> 2;
    const int c = (lane & 3) * 2;

    if (mode == 1) {
        // write C = acc + bias, [M, 600]
#pragma unroll
        for (int mi = 0; mi < 2; mi++)
#pragma unroll
            for (int ni = 0; ni < 10; ni++) {
                int n = wn * 80 + ni * 8 + c;
                if (n >= H3) continue;
                float bia0 = bias ? bias[n] : 0.f;
                float bia1 = bias ? bias[n + 1] : 0.f;
#pragma unroll
                for (int half = 0; half < 2; half++) {
                    int m = m0 + wm * 32 + mi * 16 + half * 8 + r;
                    if (m >= NN) continue;
                    float* p = C + (size_t)m * H3 + n;
                    p[0] = acc[mi][ni][half * 2 + 0] + bia0;
                    p[1] = acc[mi][ni][half * 2 + 1] + bia1;
                }
            }
        return;
    }

    // mode 2: stage gh = acc + bhh to smem, then fused GRU
    __syncthreads();   // all warps done with pipeline smem
    float* sg = (float*)dsm;
#pragma unroll
    for (int mi = 0; mi < 2; mi++)
#pragma unroll
        for (int ni = 0; ni < 10; ni++) {
            int n = wn * 80 + ni * 8 + c;
            if (n >= H3) continue;
            float bia0 = bias[n], bia1 = bias[n + 1];
#pragma unroll
            for (int half = 0; half < 2; half++) {
                int row = wm * 32 + mi * 16 + half * 8 + r;
                sg[row * T64_EPI_STR + n]     = acc[mi][ni][half * 2 + 0] + bia0;
                sg[row * T64_EPI_STR + n + 1] = acc[mi][ni][half * 2 + 1] + bia1;
            }
        }
    __syncthreads();

    for (int task = tid; task < 64 * 50; task += 512) {
        int row = task / 50;
        int m = m0 + row;
        if (m >= NN) continue;
        int j = (task - row * 50) * 4;
        const float* gi = gi_in + (size_t)m * H3;
        float4 ir4 = *(const float4*)(gi + j);
        float4 iz4 = *(const float4*)(gi + j + 200);
        float4 in4 = *(const float4*)(gi + j + 400);
        const float* sgr = sg + row * T64_EPI_STR;
        float4 hr4 = *(const float4*)(sgr + j);
        float4 hz4 = *(const float4*)(sgr + j + 200);
        float4 hn4 = *(const float4*)(sgr + j + 400);
        float* hp = h_io + (size_t)m * HID + j;
        float4 h4 = *(float4*)hp;

        float hv[4];
        const float ir[4] = {ir4.x, ir4.y, ir4.z, ir4.w};
        const float iz[4] = {iz4.x, iz4.y, iz4.z, iz4.w};
        const float in_[4] = {in4.x, in4.y, in4.z, in4.w};
        const float hr[4] = {hr4.x, hr4.y, hr4.z, hr4.w};
        const float hz[4] = {hz4.x, hz4.y, hz4.z, hz4.w};
        const float hn[4] = {hn4.x, hn4.y, hn4.z, hn4.w};
        const float ho[4] = {h4.x, h4.y, h4.z, h4.w};
#pragma unroll
        for (int i = 0; i < 4; i++) {
            float rr = 1.f / (1.f + expf(-(ir[i] + hr[i])));
            float zz = 1.f / (1.f + expf(-(iz[i] + hz[i])));
            float nn = tanhf(in_[i] + rr * hn[i]);
            hv[i] = (1.f - zz) * nn + zz * ho[i];
        }
        *(float4*)hp = make_float4(hv[0], hv[1], hv[2], hv[3]);
        if (do_split) {
            write_split_pair(hs_out, m, j,     hv[0], hv[1]);
            write_split_pair(hs_out, m, j + 2, hv[2], hv[3]);
        }
    }
}

// ---------------- small SIMT GEMM (fc1/fc2) ----------------
#define BM 64
#define BN 64
#define BK 16
__global__ void k_gemm(const float* __restrict__ A, const float* __restrict__ B,
                       float* __restrict__ C, int M, int N, int K, int transB,
                       const float* __restrict__ bias,
                       const float* __restrict__ scale,
                       const float* __restrict__ shift, int relu) {
    __shared__ float As[BK][BM];
    __shared__ float Bs[BK][BN + 4];
    const int m0 = blockIdx.y * BM;
    const int n0 = blockIdx.x * BN;
    const int tid = threadIdx.x;
    const int tm = tid >> 4;
    const int tn = tid & 15;
    float acc[4][4];
#pragma unroll
    for (int i = 0; i < 4; i++)
#pragma unroll
        for (int j = 0; j < 4; j++) acc[i][j] = 0.f;

    for (int k0 = 0; k0 < K; k0 += BK) {
        {
            int ar = tid >> 2;
            int ac = (tid & 3) * 4;
            int m = m0 + ar;
#pragma unroll
            for (int i = 0; i < 4; i++) {
                int k = k0 + ac + i;
                As[ac + i][ar] = (m < M && k < K) ? A[(size_t)m * K + k] : 0.f;
            }
        }
        if (!transB) {
            int br = tid >> 4;
            int bc = (tid & 15) * 4;
            int k = k0 + br;
#pragma unroll
            for (int i = 0; i < 4; i++) {
                int n = n0 + bc + i;
                Bs[br][bc + i] = (k < K && n < N) ? B[(size_t)k * N + n] : 0.f;
            }
        } else {
            int br = tid >> 2;
            int bc = (tid & 3) * 4;
            int n = n0 + br;
#pragma unroll
            for (int i = 0; i < 4; i++) {
                int k = k0 + bc + i;
                Bs[bc + i][br] = (n < N && k < K) ? B[(size_t)n * K + k] : 0.f;
            }
        }
        __syncthreads();
#pragma unroll
        for (int k = 0; k < BK; k++) {
            float a[4], b[4];
#pragma unroll
            for (int i = 0; i < 4; i++) a[i] = As[k][tm * 4 + i];
#pragma unroll
            for (int j = 0; j < 4; j++) b[j] = Bs[k][tn * 4 + j];
#pragma unroll
            for (int i = 0; i < 4; i++)
#pragma unroll
                for (int j = 0; j < 4; j++) acc[i][j] += a[i] * b[j];
        }
        __syncthreads();
    }
#pragma unroll
    for (int i = 0; i < 4; i++) {
        int m = m0 + tm * 4 + i;
        if (m >= M) continue;
#pragma unroll
        for (int j = 0; j < 4; j++) {
            int n = n0 + tn * 4 + j;
            if (n >= N) continue;
            float v = acc[i][j];
            if (bias)  v += bias[n];
            if (scale) v = v * scale[n] + shift[n];
            if (relu)  v = fmaxf(v, 0.f);
            C[(size_t)m * N + n] = v;
        }
    }
}

// ---------------- zero helper ----------------
__global__ void k_zero(float* __restrict__ p, int n) {
    int i = blockIdx.x * blockDim.x + threadIdx.x;
    if (i < n) p[i] = 0.f;
}

// ---------------- edge scatter-add ----------------
__global__ void k_scatter() {
    int t = blockIdx.x * blockDim.x + threadIdx.x;
    if (t >= NE * 50) return;
    int e = t / 50;
    int c = t - e * 50;
    int s = g_src[e];
    int d = g_dst[e];
    const float4 v = *reinterpret_cast<const float4*>(&g_m[(size_t)s * HID + c * 4]);
    float* p = &g_agg[(size_t)d * HID + c * 4];
    asm volatile("red.global.add.v4.f32 [%0], {%1,%2,%3,%4};"
                 :: "l"(p), "f"(v.x), "f"(v.y), "f"(v.z), "f"(v.w) : "memory");
}

__global__ void k_bn2relu() {
    int idx = blockIdx.x * blockDim.x + threadIdx.x;
    if (idx >= NN * HID) return;
    int j = idx % HID;
    g_h[idx] = fmaxf(g_h[idx] * g_scale[HID + j] + g_shift[HID + j], 0.f);
}

// ---------------- pooling ----------------
__global__ void k_pool() {
    int t = blockIdx.x * blockDim.x + threadIdx.x;
    if (t >= NN * 50) return;
    int node = t / 50;
    int c = t - node * 50;
    int b = g_batch[node];
    const float4 v = *reinterpret_cast<const float4*>(&g_h[(size_t)node * HID + c * 4]);
    float* mp = &g_pool[b * 400 + c * 4];
    atomicAdd(mp + 0, v.x); atomicAdd(mp + 1, v.y);
    atomicAdd(mp + 2, v.z); atomicAdd(mp + 3, v.w);
    int* xp = (int*)&g_pool[b * 400 + 200 + c * 4];
    atomicMax(xp + 0, __float_as_int(v.x));
    atomicMax(xp + 1, __float_as_int(v.y));
    atomicMax(xp + 2, __float_as_int(v.z));
    atomicMax(xp + 3, __float_as_int(v.w));
    if (c == 0) atomicAdd(&g_cnt[b], 1.0f);
}

__global__ void k_pool_fin() {
    int idx = blockIdx.x * blockDim.x + threadIdx.x;
    if (idx >= NG * HID) return;
    int g = idx / HID;
    int j = idx - g * HID;
    g_pool[g * 400 + j] *= 1.f / fmaxf(g_cnt[g], 1.f);
}

// ---------------- host launch ----------------
static inline int cdiv(int a, int b) { return (a + b - 1) / b; }

extern "C" void kernel_launch(void* const* d_in, const int* in_sizes, int n_in,
                              void* d_out, int out_size) {
    static bool init = false;
    static float *p_h, *p_m, *p_agg, *p_gi, *p_pool, *p_cnt, *p_fc1, *p_scale, *p_shift;
    static __nv_bfloat16 *p_xs, *p_hs, *p_as, *p_Bproj, *p_Bggc, *p_Bwih, *p_Bwhh;
    if (!init) {
        cudaGetSymbolAddress((void**)&p_h, g_h);
        cudaGetSymbolAddress((void**)&p_m, g_m);
        cudaGetSymbolAddress((void**)&p_agg, g_agg);
        cudaGetSymbolAddress((void**)&p_gi, g_gi);
        cudaGetSymbolAddress((void**)&p_pool, g_pool);
        cudaGetSymbolAddress((void**)&p_cnt, g_cnt);
        cudaGetSymbolAddress((void**)&p_fc1, g_fc1);
        cudaGetSymbolAddress((void**)&p_scale, g_scale);
        cudaGetSymbolAddress((void**)&p_shift, g_shift);
        cudaGetSymbolAddress((void**)&p_xs, g_xs);
        cudaGetSymbolAddress((void**)&p_hs, g_hs);
        cudaGetSymbolAddress((void**)&p_as, g_as);
        cudaGetSymbolAddress((void**)&p_Bproj, g_Bproj);
        cudaGetSymbolAddress((void**)&p_Bggc, g_Bggc);
        cudaGetSymbolAddress((void**)&p_Bwih, g_Bwih);
        cudaGetSymbolAddress((void**)&p_Bwhh, g_Bwhh);
        cudaFuncSetAttribute(k_tgemm, cudaFuncAttributeMaxDynamicSharedMemorySize, SMEM_DYN);
        cudaFuncSetAttribute(k_tg64, cudaFuncAttributeMaxDynamicSharedMemorySize, T64_SMEM);
        init = true;
    }

    const float *x, *projW, *projb;
    const void  *edge, *batch;
    const float *bn1g, *bn1b, *bn1m, *bn1v;
    const float *bn2g, *bn2b, *bn2m, *bn2v;
    const float *bnfg, *bnfb, *bnfm, *bnfv;
    const float *ggcW, *wih, *whh, *bih, *bhh, *fc1W, *fc1b, *fc2W, *fc2b;

    x     = (const float*)d_in[0];
    edge  = d_in[1];
    batch = d_in[2];
    projW = (const float*)d_in[3];
    projb = (const float*)d_in[4];
    bn1g = (const float*)d_in[5]; bn1b = (const float*)d_in[6];
    bn1m = (const float*)d_in[7]; bn1v = (const float*)d_in[8];

    if (in_sizes[9] == 120000) {
        ggcW = (const float*)d_in[9];
        wih  = (const float*)d_in[10]; whh = (const float*)d_in[11];
        bih  = (const float*)d_in[12]; bhh = (const float*)d_in[13];
        bn2g = (const float*)d_in[14]; bn2b = (const float*)d_in[15];
        bn2m = (const float*)d_in[16]; bn2v = (const float*)d_in[17];
        fc1W = (const float*)d_in[18]; fc1b = (const float*)d_in[19];
        bnfg = (const float*)d_in[20]; bnfb = (const float*)d_in[21];
        bnfm = (const float*)d_in[22]; bnfv = (const float*)d_in[23];
        fc2W = (const float*)d_in[24]; fc2b = (const float*)d_in[25];
    } else {
        bn2g = (const float*)d_in[9];  bn2b = (const float*)d_in[10];
        bn2m = (const float*)d_in[11]; bn2v = (const float*)d_in[12];
        bnfg = (const float*)d_in[13]; bnfb = (const float*)d_in[14];
        bnfm = (const float*)d_in[15]; bnfv = (const float*)d_in[16];
        ggcW = (const float*)d_in[17];
        wih  = (const float*)d_in[18]; whh = (const float*)d_in[19];
        bih  = (const float*)d_in[20]; bhh = (const float*)d_in[21];
        fc1W = (const float*)d_in[22]; fc1b = (const float*)d_in[23];
        fc2W = (const float*)d_in[24]; fc2b = (const float*)d_in[25];
    }

    const int T = 256;
    const int MT  = cdiv(NN, 128);   // 782
    const int MT64 = cdiv(NN, 64);   // 1563

    k_splitB<<<cdiv(NSTEP * 256 * 2, T), T>>>(projW, p_Bproj, HID, 256, INDIM, 1);
    k_bnprep_all<<<1, 640>>>(bn1g, bn1b, bn1m, bn1v,
                             bn2g, bn2b, bn2m, bn2v,
                             bnfg, bnfb, bnfm, bnfv);
    k_splitA<<<cdiv(NSTEP * NN * 2, T), T>>>(x, p_xs, INDIM);
    // h = relu(bn1(x @ projW^T + projb)); epilogue also writes hs split
    k_tgemm<<<dim3(1, MT), 512, SMEM_DYN>>>(p_xs, p_Bproj, p_h, NN, HID, 256,
                                            projb, p_scale, p_shift, 1, p_hs);
    k_splitB<<<cdiv(NSTEP * 256 * 2, T), T>>>(ggcW, p_Bggc, HID, 256, HID, 0);
    // m = h @ ggc_W[0]
    k_tgemm<<<dim3(1, MT), 512, SMEM_DYN>>>(p_hs, p_Bggc, p_m, NN, HID, 256,
                                            nullptr, nullptr, nullptr, 0, nullptr);

    k_detect<<<1, 32>>>((const int*)edge, (const int*)batch);
    k_conv_edges<<<cdiv(2 * NE, T), T>>>(edge);
    k_conv_batch<<<cdiv(NN, T), T>>>(batch);
    for (int i = 1; i < 3; i++)
        k_splitB<<<cdiv(NSTEP * 256 * 2, T), T>>>(ggcW + (size_t)i * HID * HID,
                                                  p_Bggc + (size_t)i * NSTEP * 256 * HW16,
                                                  HID, 256, HID, 0);
    k_splitB<<<cdiv(NSTEP * 768 * 2, T), T>>>(wih, p_Bwih, H3, 768, HID, 1);
    k_splitB<<<cdiv(NSTEP * 768 * 2, T), T>>>(whh, p_Bwhh, H3, 768, HID, 1);

    for (int it = 0; it < 3; it++) {
        if (it > 0) {
            k_tgemm<<<dim3(1, MT), 512, SMEM_DYN>>>(
                p_hs, p_Bggc + (size_t)it * NSTEP * 256 * HW16,
                p_m, NN, HID, 256, nullptr, nullptr, nullptr, 0, nullptr);
        }
        // agg = scatter_add(m[src] -> dst)
        k_zero<<<cdiv(NN * HID, T), T>>>(p_agg, NN * HID);
        k_scatter<<<cdiv(NE * 50, T), T>>>();
        k_splitA<<<cdiv(NSTEP * NN * 2, T), T>>>(p_agg, p_as, HID);
        // gi = agg @ wih^T + bih
        k_tg64<<<dim3(1, MT64), 512, T64_SMEM>>>(p_as, p_Bwih, 768, bih,
                                                 p_gi, nullptr, nullptr, nullptr, 1, 0);
        // gh = h @ whh^T + bhh, fused GRU -> h (+ split for next iter)
        k_tg64<<<dim3(1, MT64), 512, T64_SMEM>>>(p_hs, p_Bwhh, 768, bhh,
                                                 nullptr, p_gi, p_h, p_hs, 2, it < 2 ? 1 : 0);
    }

    k_bn2relu<<<cdiv(NN * HID, T), T>>>();

    k_zero<<<cdiv(NG * 400, T), T>>>(p_pool, NG * 400);
    k_zero<<<cdiv(NG, T), T>>>(p_cnt, NG);
    k_pool<<<cdiv(NN * 50, T), T>>>();
    k_pool_fin<<<cdiv(NG * HID, T), T>>>();

    {
        dim3 grid(cdiv(HID, BN), cdiv(NG, BM));
        k_gemm<<<grid, T>>>(p_pool, fc1W, p_fc1, NG, HID, 2 * HID, 1,
                            fc1b, p_scale + 2 * HID, p_shift + 2 * HID, 1);
    }
    {
        dim3 grid(cdiv(2, BN), cdiv(NG, BM));
        k_gemm<<<grid, T>>>(p_fc1, fc2W, (float*)d_out, NG, 2, HID, 1,
                            fc2b, nullptr, nullptr, 0);
    }
}

// round 12
// speedup vs baseline: 1.6469x; 1.1622x over previous
#include <cuda_runtime.h>
#include <cuda_bf16.h>
#include <stdint.h>
#include <math.h>

#define NN    100000
#define NE    1600000
#define NG    512
#define HID   200
#define H3    600
#define INDIM 205

#define KP    208
#define K3    624
#define NSTEP 39        // K3/16
#define MPAD  100096    // >= 1563*64
#define HW16  16        // halfwords per row per k-step (packed, swizzled)

// ---------------- scratch ----------------
__device__ float g_h  [(size_t)NN * HID];
__device__ float g_m  [(size_t)NN * HID];
__device__ float g_agg[(size_t)NN * HID];
__device__ float g_gi [(size_t)NN * H3];
__device__ float g_pool[NG * 2 * HID];
__device__ float g_cnt [NG];
__device__ float g_fc1 [NG * HID];
__device__ float g_scale[3 * HID];
__device__ float g_shift[3 * HID];
__device__ int   g_src[NE];
__device__ int   g_dst[NE];
__device__ int   g_batch[NN];
__device__ int   g_flag_e;
__device__ int   g_flag_b;
// CSR (built once; graph identical across iterations)
__device__ int   g_deg [NN];
__device__ int   g_tmp [NN];
__device__ int   g_rptr[NN + 1];
__device__ int   g_csr [NE];

// packed k-blocked bf16 buffers, swizzle baked into gmem layout:
// element (ks,row,kk) at ((ks*ROWS+row)*16) + ((kk>>3) ^ ((row>>2)&1))*8 + (kk&7)
__device__ __nv_bfloat16 g_xs[(size_t)NSTEP * MPAD * HW16];
__device__ __nv_bfloat16 g_hs[(size_t)NSTEP * MPAD * HW16];
__device__ __nv_bfloat16 g_as[(size_t)NSTEP * MPAD * HW16];
__device__ __nv_bfloat16 g_Bproj[(size_t)NSTEP * 256 * HW16];
__device__ __nv_bfloat16 g_Bggc [3][(size_t)NSTEP * 256 * HW16];
__device__ __nv_bfloat16 g_Bwih [(size_t)NSTEP * 768 * HW16];
__device__ __nv_bfloat16 g_Bwhh [(size_t)NSTEP * 768 * HW16];

// ---------------- dtype detection ----------------
__global__ void k_detect(const int* __restrict__ ew, const int* __restrict__ bw) {
    int lane = threadIdx.x;
    int bad_e = 0, bad_b = 0;
    for (int w = 2 * NE - 255 + 2 * lane; w < 2 * NE; w += 64)
        if (ew[w] != 0) bad_e = 1;
    for (int w = NN - 255 + 2 * lane; w < NN; w += 64)
        if (bw[w] != 0) bad_b = 1;
    unsigned me = __ballot_sync(0xFFFFFFFFu, bad_e);
    unsigned mb = __ballot_sync(0xFFFFFFFFu, bad_b);
    if (lane == 0) { g_flag_e = (me == 0); g_flag_b = (mb == 0); }
}

__global__ void k_conv_edges(const void* __restrict__ e) {
    int i = blockIdx.x * blockDim.x + threadIdx.x;
    if (i >= 2 * NE) return;
    int v = g_flag_e ? (int)((const long long*)e)[i] : ((const int*)e)[i];
    if (i < NE) g_src[i] = v; else g_dst[i - NE] = v;
}

__global__ void k_conv_batch(const void* __restrict__ b) {
    int i = blockIdx.x * blockDim.x + threadIdx.x;
    if (i >= NN) return;
    g_batch[i] = g_flag_b ? (int)((const long long*)b)[i] : ((const int*)b)[i];
}

// ---------------- CSR build (once) ----------------
__global__ void k_hist() {
    int i = blockIdx.x * blockDim.x + threadIdx.x;
    if (i < NE) atomicAdd(&g_deg[g_dst[i]], 1);
}

__global__ void k_scan() {   // single block, 1024 threads
    __shared__ int buf[1024];
    __shared__ int carry;
    int tid = threadIdx.x;
    if (tid == 0) carry = 0;
    __syncthreads();
    for (int base = 0; base < NN; base += 1024) {
        int v = (base + tid < NN) ? g_deg[base + tid] : 0;
        buf[tid] = v;
        __syncthreads();
        for (int off = 1; off < 1024; off <<= 1) {
            int t = (tid >= off) ? buf[tid - off] : 0;
            __syncthreads();
            buf[tid] += t;
            __syncthreads();
        }
        if (base + tid < NN) g_rptr[base + tid] = buf[tid] - v + carry;
        __syncthreads();
        if (tid == 0) carry += buf[1023];
        __syncthreads();
    }
    if (tid == 0) g_rptr[NN] = carry;
}

__global__ void k_fill() {
    int i = blockIdx.x * blockDim.x + threadIdx.x;
    if (i >= NE) return;
    int d = g_dst[i];
    int pos = g_rptr[d] + atomicAdd(&g_tmp[d], 1);
    g_csr[pos] = g_src[i];
}

// ---------------- CSR gather-sum: agg[n] = sum_{e in in(n)} m[src(e)] --------
__global__ void k_agg() {
    int idx = blockIdx.x * blockDim.x + threadIdx.x;
    if (idx >= NN * 50) return;
    int n = idx / 50, c = idx - n * 50;
    int e0 = g_rptr[n], e1 = g_rptr[n + 1];
    float ax = 0.f, ay = 0.f, az = 0.f, aw = 0.f;
    for (int e = e0; e < e1; e++) {
        int s = g_csr[e];
        const float4 v = *(const float4*)&g_m[(size_t)s * HID + c * 4];
        ax += v.x; ay += v.y; az += v.z; aw += v.w;
    }
    *(float4*)&g_agg[(size_t)n * HID + c * 4] = make_float4(ax, ay, az, aw);
}

// ---------------- merged BN param prep ----------------
__global__ void k_bnprep_all(
    const float* g1, const float* b1, const float* m1, const float* v1,
    const float* g2, const float* b2, const float* m2, const float* v2,
    const float* gf, const float* bf, const float* mf, const float* vf) {
    int j = threadIdx.x;
    if (j >= 3 * HID) return;
    int which = j / HID, jj = j - which * HID;
    const float *g, *b, *m, *v;
    if (which == 0)      { g = g1; b = b1; m = m1; v = v1; }
    else if (which == 1) { g = g2; b = b2; m = m2; v = v2; }
    else                 { g = gf; b = bf; m = mf; v = vf; }
    float s = g[jj] * rsqrtf(v[jj] + 1e-5f);
    g_scale[j] = s;
    g_shift[j] = b[jj] - m[jj] * s;
}

// ---------------- bf16 split of activations (coalesced, swizzled) -----------
__global__ void k_splitA(const float* __restrict__ in, __nv_bfloat16* __restrict__ out,
                         int K) {
    int idx = blockIdx.x * blockDim.x + threadIdx.x;
    if (idx >= NSTEP * NN * 2) return;
    int ks   = idx / (NN * 2);
    int rem  = idx - ks * (NN * 2);
    int m    = rem >> 1;
    int half = rem & 1;
    int s  = ks / 13;
    int c  = (ks - s * 13) * 2 + half;
    int k0 = c * 8;
    const float* src = in + (size_t)m * K + k0;
    __nv_bfloat16 o[8];
#pragma unroll
    for (int i = 0; i < 8; i++) {
        float v = (k0 + i < K) ? src[i] : 0.f;
        __nv_bfloat16 hi = __float2bfloat16(v);
        o[i] = (s == 1) ? __float2bfloat16(v - __bfloat162float(hi)) : hi;
    }
    int swz = half ^ ((m >> 2) & 1);
    *(uint4*)(out + ((size_t)ks * MPAD + m) * HW16 + swz * 8) = *(const uint4*)o;
}

// ---------------- bf16 split of weights (swizzled) ----------------
__global__ void k_splitB(const float* __restrict__ W, __nv_bfloat16* __restrict__ out,
                         int N, int Npad, int K, int trans) {
    int idx = blockIdx.x * blockDim.x + threadIdx.x;
    if (idx >= NSTEP * Npad * 2) return;
    int ks   = idx / (Npad * 2);
    int rem  = idx - ks * (Npad * 2);
    int n    = rem >> 1;
    int half = rem & 1;
    int s  = ks / 13;
    int c  = (ks - s * 13) * 2 + half;
    int k0 = c * 8;
    __nv_bfloat16 o[8];
#pragma unroll
    for (int i = 0; i < 8; i++) {
        int k = k0 + i;
        float v = 0.f;
        if (n < N && k < K) v = trans ? W[(size_t)n * K + k] : W[(size_t)k * N + n];
        __nv_bfloat16 hi = __float2bfloat16(v);
        o[i] = (s == 2) ? __float2bfloat16(v - __bfloat162float(hi)) : hi;
    }
    int swz = half ^ ((n >> 2) & 1);
    *(uint4*)(out + ((size_t)ks * Npad + n) * HW16 + swz * 8) = *(const uint4*)o;
}

// ---------------- split-pair writer (device helper) ----------------
__device__ __forceinline__ void write_split_pair(
    __nv_bfloat16* __restrict__ hs, int m, int j /*even*/, float v0, float v1) {
    __nv_bfloat16 h0 = __float2bfloat16(v0), h1 = __float2bfloat16(v1);
    __nv_bfloat16 l0 = __float2bfloat16(v0 - __bfloat162float(h0));
    __nv_bfloat16 l1 = __float2bfloat16(v1 - __bfloat162float(h1));
    uint32_t hi2 = ((uint32_t)*(uint16_t*)&h1 << 16) | *(uint16_t*)&h0;
    uint32_t lo2 = ((uint32_t)*(uint16_t*)&l1 << 16) | *(uint16_t*)&l0;
    int c = j >> 3, ksl = c >> 1, half = c & 1, off = j & 7;
    int swz = (half ^ ((m >> 2) & 1)) << 3;
    *(uint32_t*)(hs + ((size_t)(ksl)      * MPAD + m) * HW16 + swz + off) = hi2;
    *(uint32_t*)(hs + ((size_t)(13 + ksl) * MPAD + m) * HW16 + swz + off) = lo2;
    *(uint32_t*)(hs + ((size_t)(26 + ksl) * MPAD + m) * HW16 + swz + off) = hi2;
}

// ---------------- tensor GEMM A: 128x256 tile, 512 thr ----------------------
#define STAGES       6
#define STAGE_A_HW   (128 * HW16)
#define STAGE_B_HW   (256 * HW16)
#define STAGE_HW     (STAGE_A_HW + STAGE_B_HW)
#define STAGE_BYTES  (STAGE_HW * 2)          // 12288
#define A_BYTES      (STAGE_A_HW * 2)
#define B_BYTES      (STAGE_B_HW * 2)
#define SMEM_DYN     (STAGES * STAGE_BYTES + 64)

__global__ void __launch_bounds__(512, 1)
k_tgemm(const __nv_bfloat16* __restrict__ A, const __nv_bfloat16* __restrict__ B,
        float* __restrict__ C, int M, int N, int NPADB,
        const float* __restrict__ bias,
        const float* __restrict__ scale, const float* __restrict__ shift,
        int relu, __nv_bfloat16* __restrict__ hs_out) {
    extern __shared__ __align__(128) __nv_bfloat16 dsm[];

    const int tid  = threadIdx.x;
    const int warp = tid >> 5, lane = tid & 31;
    const int wm = warp & 3, wn = warp >> 2;       // 4 x 4
    const int m0 = blockIdx.y * 128;
    const int n0 = blockIdx.x * 256;

    const uint32_t smem_base = (uint32_t)__cvta_generic_to_shared(dsm);
    const uint32_t mbar_base = smem_base + STAGES * STAGE_BYTES;

    if (tid == 0) {
        for (int s = 0; s < STAGES; s++)
            asm volatile("mbarrier.init.shared.b64 [%0], 1;" :: "r"(mbar_base + s * 8) : "memory");
        asm volatile("fence.proxy.async.shared::cta;" ::: "memory");
    }
    __syncthreads();

    float acc[2][8][4];
#pragma unroll
    for (int mi = 0; mi < 2; mi++)
#pragma unroll
        for (int ni = 0; ni < 8; ni++)
#pragma unroll
            for (int j = 0; j < 4; j++) acc[mi][ni][j] = 0.f;

#define ISSUE(kf)                                                                \
    do {                                                                         \
        int slot_ = (kf) % STAGES;                                               \
        uint32_t mb_ = mbar_base + slot_ * 8;                                    \
        asm volatile("mbarrier.arrive.expect_tx.shared.b64 _, [%0], %1;"         \
                     :: "r"(mb_), "r"((uint32_t)STAGE_BYTES) : "memory");        \
        uint32_t da_ = smem_base + slot_ * STAGE_BYTES;                          \
        const __nv_bfloat16* sa_ = A + ((size_t)(kf) * MPAD + m0) * HW16;        \
        asm volatile("cp.async.bulk.shared::cta.global.mbarrier::complete_tx::bytes " \
                     "[%0], [%1], %2, [%3];"                                     \
                     :: "r"(da_), "l"(sa_), "r"((uint32_t)A_BYTES), "r"(mb_)     \
                     : "memory");                                                \
        uint32_t db_ = da_ + A_BYTES;                                            \
        const __nv_bfloat16* sb_ = B + ((size_t)(kf) * NPADB + n0) * HW16;       \
        asm volatile("cp.async.bulk.shared::cta.global.mbarrier::complete_tx::bytes " \
                     "[%0], [%1], %2, [%3];"                                     \
                     :: "r"(db_), "l"(sb_), "r"((uint32_t)B_BYTES), "r"(mb_)     \
                     : "memory");                                                \
    } while (0)

    if (tid == 0)
        for (int kf = 0; kf < STAGES - 1 && kf < NSTEP; kf++) ISSUE(kf);

    const int lr = lane & 15;
    const int ch = lane >> 4;
    const int xa = (lane >> 2) & 1;
    const int bn = lane >> 2;
    const int xb = (lane >> 4) & 1;
    const int bk = (lane & 3) * 2;

    for (int ks = 0; ks < NSTEP; ks++) {
        __syncthreads();
        if (tid == 0) {
            int kf = ks + STAGES - 1;
            if (kf < NSTEP) ISSUE(kf);
        }
        const int slot = ks % STAGES;
        const uint32_t mb = mbar_base + slot * 8;
        const uint32_t parity = (uint32_t)((ks / STAGES) & 1);
        {
            uint32_t done = 0;
            while (!done) {
                asm volatile(
                    "{\n\t.reg .pred p;\n\t"
                    "mbarrier.try_wait.parity.acquire.cta.shared::cta.b64 p, [%1], %2;\n\t"
                    "selp.b32 %0, 1, 0, p;\n\t}"
                    : "=r"(done) : "r"(mb), "r"(parity) : "memory");
            }
        }

        const uint32_t aBase = smem_base + slot * STAGE_BYTES;
        const __nv_bfloat16* sBp = dsm + slot * STAGE_HW + STAGE_A_HW;

        uint32_t a[2][4];
        uint32_t b[8][2];
#pragma unroll
        for (int mi = 0; mi < 2; mi++) {
            int row = wm * 32 + mi * 16 + lr;
            uint32_t addr = aBase + (row * HW16 + ((ch ^ xa) << 3)) * 2;
            asm volatile("ldmatrix.sync.aligned.m8n8.x4.shared.b16 {%0,%1,%2,%3}, [%4];"
                         : "=r"(a[mi][0]), "=r"(a[mi][1]), "=r"(a[mi][2]), "=r"(a[mi][3])
                         : "r"(addr));
        }
#pragma unroll
        for (int ni = 0; ni < 8; ni++) {
            int row = wn * 64 + ni * 8 + bn;
            b[ni][0] = *(const uint32_t*)(sBp + row * HW16 + (xb << 3) + bk);
            b[ni][1] = *(const uint32_t*)(sBp + row * HW16 + ((1 ^ xb) << 3) + bk);
        }
#pragma unroll
        for (int mi = 0; mi < 2; mi++)
#pragma unroll
            for (int ni = 0; ni < 8; ni++) {
                asm volatile(
                    "mma.sync.aligned.m16n8k16.row.col.f32.bf16.bf16.f32 "
                    "{%0,%1,%2,%3}, {%4,%5,%6,%7}, {%8,%9}, {%0,%1,%2,%3};"
                    : "+f"(acc[mi][ni][0]), "+f"(acc[mi][ni][1]),
                      "+f"(acc[mi][ni][2]), "+f"(acc[mi][ni][3])
                    : "r"(a[mi][0]), "r"(a[mi][1]), "r"(a[mi][2]), "r"(a[mi][3]),
                      "r"(b[ni][0]), "r"(b[ni][1]));
            }
    }
#undef ISSUE

    const int r = lane >> 2;
    const int c = (lane & 3) * 2;
#pragma unroll
    for (int mi = 0; mi < 2; mi++) {
#pragma unroll
        for (int ni = 0; ni < 8; ni++) {
            int n = n0 + wn * 64 + ni * 8 + c;
            if (n >= N) continue;
            float bia0 = 0.f, bia1 = 0.f, sc0 = 1.f, sc1 = 1.f, sh0 = 0.f, sh1 = 0.f;
            bool n1ok = (n + 1 < N);
            if (bias)  { bia0 = bias[n]; if (n1ok) bia1 = bias[n + 1]; }
            if (scale) { sc0 = scale[n]; sh0 = shift[n];
                         if (n1ok) { sc1 = scale[n + 1]; sh1 = shift[n + 1]; } }
#pragma unroll
            for (int half = 0; half < 2; half++) {
                int m = m0 + wm * 32 + mi * 16 + half * 8 + r;
                if (m >= M) continue;
                float v0 = acc[mi][ni][half * 2 + 0] + bia0;
                float v1 = acc[mi][ni][half * 2 + 1] + bia1;
                if (scale) { v0 = v0 * sc0 + sh0; v1 = v1 * sc1 + sh1; }
                if (relu)  { v0 = fmaxf(v0, 0.f); v1 = fmaxf(v1, 0.f); }
                float* p = C + (size_t)m * N + n;
                p[0] = v0;
                if (n1ok) p[1] = v1;
                if (hs_out && n1ok) write_split_pair(hs_out, m, n, v0, v1);
            }
        }
    }
}

// ---------------- tensor GEMM B: 64 x 640 tile, optional fused GRU ----------
#define T64S        4
#define T64_A_B     (64 * 32)                 // 2048
#define T64_B_B     (640 * 32)                // 20480
#define T64_ST_B    (T64_A_B + T64_B_B)       // 22528
#define T64_EPI_STR 608
#define T64_EPI_B   (64 * T64_EPI_STR * 4)    // 155648
#define T64_SMEM    (T64_EPI_B + 64)

__global__ void __launch_bounds__(512, 1)
k_tg64(const __nv_bfloat16* __restrict__ A, const __nv_bfloat16* __restrict__ B,
       int NPADB, const float* __restrict__ bias,
       float* __restrict__ C,
       const float* __restrict__ gi_in, float* __restrict__ h_io,
       __nv_bfloat16* __restrict__ hs_out, int mode, int do_split) {
    extern __shared__ __align__(128) __nv_bfloat16 dsm[];

    const int tid  = threadIdx.x;
    const int warp = tid >> 5, lane = tid & 31;
    const int wm = warp & 1, wn = warp >> 1;       // 2 x 8
    const int m0 = blockIdx.y * 64;

    const uint32_t smem_base = (uint32_t)__cvta_generic_to_shared(dsm);
    const uint32_t mbar_base = smem_base + T64_EPI_B;

    if (tid == 0) {
        for (int s = 0; s < T64S; s++)
            asm volatile("mbarrier.init.shared.b64 [%0], 1;" :: "r"(mbar_base + s * 8) : "memory");
        asm volatile("fence.proxy.async.shared::cta;" ::: "memory");
    }
    __syncthreads();

    float acc[2][10][4];
#pragma unroll
    for (int mi = 0; mi < 2; mi++)
#pragma unroll
        for (int ni = 0; ni < 10; ni++)
#pragma unroll
            for (int j = 0; j < 4; j++) acc[mi][ni][j] = 0.f;

#define ISSUE64(kf)                                                              \
    do {                                                                         \
        int slot_ = (kf) % T64S;                                                 \
        uint32_t mb_ = mbar_base + slot_ * 8;                                    \
        asm volatile("mbarrier.arrive.expect_tx.shared.b64 _, [%0], %1;"         \
                     :: "r"(mb_), "r"((uint32_t)T64_ST_B) : "memory");           \
        uint32_t da_ = smem_base + slot_ * T64_ST_B;                             \
        const __nv_bfloat16* sa_ = A + ((size_t)(kf) * MPAD + m0) * HW16;        \
        asm volatile("cp.async.bulk.shared::cta.global.mbarrier::complete_tx::bytes " \
                     "[%0], [%1], %2, [%3];"                                     \
                     :: "r"(da_), "l"(sa_), "r"((uint32_t)T64_A_B), "r"(mb_)     \
                     : "memory");                                                \
        uint32_t db_ = da_ + T64_A_B;                                            \
        const __nv_bfloat16* sb_ = B + (size_t)(kf) * NPADB * HW16;              \
        asm volatile("cp.async.bulk.shared::cta.global.mbarrier::complete_tx::bytes " \
                     "[%0], [%1], %2, [%3];"                                     \
                     :: "r"(db_), "l"(sb_), "r"((uint32_t)T64_B_B), "r"(mb_)     \
                     : "memory");                                                \
    } while (0)

    if (tid == 0)
        for (int kf = 0; kf < T64S - 1 && kf < NSTEP; kf++) ISSUE64(kf);

    const int lr = lane & 15;
    const int ch = lane >> 4;
    const int xa = (lane >> 2) & 1;
    const int bn = lane >> 2;
    const int xb = (lane >> 4) & 1;
    const int bk = (lane & 3) * 2;

    for (int ks = 0; ks < NSTEP; ks++) {
        __syncthreads();
        if (tid == 0) {
            int kf = ks + T64S - 1;
            if (kf < NSTEP) ISSUE64(kf);
        }
        const int slot = ks % T64S;
        const uint32_t mb = mbar_base + slot * 8;
        const uint32_t parity = (uint32_t)((ks / T64S) & 1);
        {
            uint32_t done = 0;
            while (!done) {
                asm volatile(
                    "{\n\t.reg .pred p;\n\t"
                    "mbarrier.try_wait.parity.acquire.cta.shared::cta.b64 p, [%1], %2;\n\t"
                    "selp.b32 %0, 1, 0, p;\n\t}"
                    : "=r"(done) : "r"(mb), "r"(parity) : "memory");
            }
        }

        const uint32_t aBase = smem_base + slot * T64_ST_B;
        const __nv_bfloat16* sBp = dsm + slot * (T64_ST_B / 2) + (T64_A_B / 2);

        uint32_t a[2][4];
        uint32_t b[10][2];
#pragma unroll
        for (int mi = 0; mi < 2; mi++) {
            int row = wm * 32 + mi * 16 + lr;
            uint32_t addr = aBase + (row * HW16 + ((ch ^ xa) << 3)) * 2;
            asm volatile("ldmatrix.sync.aligned.m8n8.x4.shared.b16 {%0,%1,%2,%3}, [%4];"
                         : "=r"(a[mi][0]), "=r"(a[mi][1]), "=r"(a[mi][2]), "=r"(a[mi][3])
                         : "r"(addr));
        }
#pragma unroll
        for (int ni = 0; ni < 10; ni++) {
            int row = wn * 80 + ni * 8 + bn;
            b[ni][0] = *(const uint32_t*)(sBp + row * HW16 + (xb << 3) + bk);
            b[ni][1] = *(const uint32_t*)(sBp + row * HW16 + ((1 ^ xb) << 3) + bk);
        }
#pragma unroll
        for (int mi = 0; mi < 2; mi++)
#pragma unroll
            for (int ni = 0; ni < 10; ni++) {
                asm volatile(
                    "mma.sync.aligned.m16n8k16.row.col.f32.bf16.bf16.f32 "
                    "{%0,%1,%2,%3}, {%4,%5,%6,%7}, {%8,%9}, {%0,%1,%2,%3};"
                    : "+f"(acc[mi][ni][0]), "+f"(acc[mi][ni][1]),
                      "+f"(acc[mi][ni][2]), "+f"(acc[mi][ni][3])
                    : "r"(a[mi][0]), "r"(a[mi][1]), "r"(a[mi][2]), "r"(a[mi][3]),
                      "r"(b[ni][0]), "r"(b[ni][1]));
            }
    }
#undef ISSUE64

    const int r = lane >> 2;
    const int c = (lane & 3) * 2;

    if (mode == 1) {
#pragma unroll
        for (int mi = 0; mi < 2; mi++)
#pragma unroll
            for (int ni = 0; ni < 10; ni++) {
                int n = wn * 80 + ni * 8 + c;
                if (n >= H3) continue;
                float bia0 = bias ? bias[n] : 0.f;
                float bia1 = bias ? bias[n + 1] : 0.f;
#pragma unroll
                for (int half = 0; half < 2; half++) {
                    int m = m0 + wm * 32 + mi * 16 + half * 8 + r;
                    if (m >= NN) continue;
                    float* p = C + (size_t)m * H3 + n;
                    p[0] = acc[mi][ni][half * 2 + 0] + bia0;
                    p[1] = acc[mi][ni][half * 2 + 1] + bia1;
                }
            }
        return;
    }

    // mode 2: stage gh = acc + bhh to smem, then fused GRU
    __syncthreads();
    float* sg = (float*)dsm;
#pragma unroll
    for (int mi = 0; mi < 2; mi++)
#pragma unroll
        for (int ni = 0; ni < 10; ni++) {
            int n = wn * 80 + ni * 8 + c;
            if (n >= H3) continue;
            float bia0 = bias[n], bia1 = bias[n + 1];
#pragma unroll
            for (int half = 0; half < 2; half++) {
                int row = wm * 32 + mi * 16 + half * 8 + r;
                sg[row * T64_EPI_STR + n]     = acc[mi][ni][half * 2 + 0] + bia0;
                sg[row * T64_EPI_STR + n + 1] = acc[mi][ni][half * 2 + 1] + bia1;
            }
        }
    __syncthreads();

    for (int task = tid; task < 64 * 50; task += 512) {
        int row = task / 50;
        int m = m0 + row;
        if (m >= NN) continue;
        int j = (task - row * 50) * 4;
        const float* gi = gi_in + (size_t)m * H3;
        float4 ir4 = *(const float4*)(gi + j);
        float4 iz4 = *(const float4*)(gi + j + 200);
        float4 in4 = *(const float4*)(gi + j + 400);
        const float* sgr = sg + row * T64_EPI_STR;
        float4 hr4 = *(const float4*)(sgr + j);
        float4 hz4 = *(const float4*)(sgr + j + 200);
        float4 hn4 = *(const float4*)(sgr + j + 400);
        float* hp = h_io + (size_t)m * HID + j;
        float4 h4 = *(float4*)hp;

        float hv[4];
        const float ir[4] = {ir4.x, ir4.y, ir4.z, ir4.w};
        const float iz[4] = {iz4.x, iz4.y, iz4.z, iz4.w};
        const float in_[4] = {in4.x, in4.y, in4.z, in4.w};
        const float hr[4] = {hr4.x, hr4.y, hr4.z, hr4.w};
        const float hz[4] = {hz4.x, hz4.y, hz4.z, hz4.w};
        const float hn[4] = {hn4.x, hn4.y, hn4.z, hn4.w};
        const float ho[4] = {h4.x, h4.y, h4.z, h4.w};
#pragma unroll
        for (int i = 0; i < 4; i++) {
            float rr = 1.f / (1.f + expf(-(ir[i] + hr[i])));
            float zz = 1.f / (1.f + expf(-(iz[i] + hz[i])));
            float nn = tanhf(in_[i] + rr * hn[i]);
            hv[i] = (1.f - zz) * nn + zz * ho[i];
        }
        *(float4*)hp = make_float4(hv[0], hv[1], hv[2], hv[3]);
        if (do_split) {
            write_split_pair(hs_out, m, j,     hv[0], hv[1]);
            write_split_pair(hs_out, m, j + 2, hv[2], hv[3]);
        }
    }
}

// ---------------- small SIMT GEMM (fc1/fc2) ----------------
#define BM 64
#define BN 64
#define BK 16
__global__ void k_gemm(const float* __restrict__ A, const float* __restrict__ B,
                       float* __restrict__ C, int M, int N, int K, int transB,
                       const float* __restrict__ bias,
                       const float* __restrict__ scale,
                       const float* __restrict__ shift, int relu) {
    __shared__ float As[BK][BM];
    __shared__ float Bs[BK][BN + 4];
    const int m0 = blockIdx.y * BM;
    const int n0 = blockIdx.x * BN;
    const int tid = threadIdx.x;
    const int tm = tid >> 4;
    const int tn = tid & 15;
    float acc[4][4];
#pragma unroll
    for (int i = 0; i < 4; i++)
#pragma unroll
        for (int j = 0; j < 4; j++) acc[i][j] = 0.f;

    for (int k0 = 0; k0 < K; k0 += BK) {
        {
            int ar = tid >> 2;
            int ac = (tid & 3) * 4;
            int m = m0 + ar;
#pragma unroll
            for (int i = 0; i < 4; i++) {
                int k = k0 + ac + i;
                As[ac + i][ar] = (m < M && k < K) ? A[(size_t)m * K + k] : 0.f;
            }
        }
        if (!transB) {
            int br = tid >> 4;
            int bc = (tid & 15) * 4;
            int k = k0 + br;
#pragma unroll
            for (int i = 0; i < 4; i++) {
                int n = n0 + bc + i;
                Bs[br][bc + i] = (k < K && n < N) ? B[(size_t)k * N + n] : 0.f;
            }
        } else {
            int br = tid >> 2;
            int bc = (tid & 3) * 4;
            int n = n0 + br;
#pragma unroll
            for (int i = 0; i < 4; i++) {
                int k = k0 + bc + i;
                Bs[bc + i][br] = (n < N && k < K) ? B[(size_t)n * K + k] : 0.f;
            }
        }
        __syncthreads();
#pragma unroll
        for (int k = 0; k < BK; k++) {
            float a[4], b[4];
#pragma unroll
            for (int i = 0; i < 4; i++) a[i] = As[k][tm * 4 + i];
#pragma unroll
            for (int j = 0; j < 4; j++) b[j] = Bs[k][tn * 4 + j];
#pragma unroll
            for (int i = 0; i < 4; i++)
#pragma unroll
                for (int j = 0; j < 4; j++) acc[i][j] += a[i] * b[j];
        }
        __syncthreads();
    }
#pragma unroll
    for (int i = 0; i < 4; i++) {
        int m = m0 + tm * 4 + i;
        if (m >= M) continue;
#pragma unroll
        for (int j = 0; j < 4; j++) {
            int n = n0 + tn * 4 + j;
            if (n >= N) continue;
            float v = acc[i][j];
            if (bias)  v += bias[n];
            if (scale) v = v * scale[n] + shift[n];
            if (relu)  v = fmaxf(v, 0.f);
            C[(size_t)m * N + n] = v;
        }
    }
}

// ---------------- zero helper ----------------
__global__ void k_zero(float* __restrict__ p, int n) {
    int i = blockIdx.x * blockDim.x + threadIdx.x;
    if (i < n) p[i] = 0.f;
}

__global__ void k_bn2relu() {
    int idx = blockIdx.x * blockDim.x + threadIdx.x;
    if (idx >= NN * HID) return;
    int j = idx % HID;
    g_h[idx] = fmaxf(g_h[idx] * g_scale[HID + j] + g_shift[HID + j], 0.f);
}

// ---------------- pooling ----------------
__global__ void k_pool() {
    int t = blockIdx.x * blockDim.x + threadIdx.x;
    if (t >= NN * 50) return;
    int node = t / 50;
    int c = t - node * 50;
    int b = g_batch[node];
    const float4 v = *reinterpret_cast<const float4*>(&g_h[(size_t)node * HID + c * 4]);
    float* mp = &g_pool[b * 400 + c * 4];
    atomicAdd(mp + 0, v.x); atomicAdd(mp + 1, v.y);
    atomicAdd(mp + 2, v.z); atomicAdd(mp + 3, v.w);
    int* xp = (int*)&g_pool[b * 400 + 200 + c * 4];
    atomicMax(xp + 0, __float_as_int(v.x));
    atomicMax(xp + 1, __float_as_int(v.y));
    atomicMax(xp + 2, __float_as_int(v.z));
    atomicMax(xp + 3, __float_as_int(v.w));
    if (c == 0) atomicAdd(&g_cnt[b], 1.0f);
}

__global__ void k_pool_fin() {
    int idx = blockIdx.x * blockDim.x + threadIdx.x;
    if (idx >= NG * HID) return;
    int g = idx / HID;
    int j = idx - g * HID;
    g_pool[g * 400 + j] *= 1.f / fmaxf(g_cnt[g], 1.f);
}

// ---------------- host launch ----------------
static inline int cdiv(int a, int b) { return (a + b - 1) / b; }

extern "C" void kernel_launch(void* const* d_in, const int* in_sizes, int n_in,
                              void* d_out, int out_size) {
    static bool init = false;
    static float *p_h, *p_m, *p_agg, *p_gi, *p_pool, *p_cnt, *p_fc1, *p_scale, *p_shift;
    static int *p_deg, *p_tmp;
    static __nv_bfloat16 *p_xs, *p_hs, *p_as, *p_Bproj, *p_Bggc, *p_Bwih, *p_Bwhh;
    if (!init) {
        cudaGetSymbolAddress((void**)&p_h, g_h);
        cudaGetSymbolAddress((void**)&p_m, g_m);
        cudaGetSymbolAddress((void**)&p_agg, g_agg);
        cudaGetSymbolAddress((void**)&p_gi, g_gi);
        cudaGetSymbolAddress((void**)&p_pool, g_pool);
        cudaGetSymbolAddress((void**)&p_cnt, g_cnt);
        cudaGetSymbolAddress((void**)&p_fc1, g_fc1);
        cudaGetSymbolAddress((void**)&p_scale, g_scale);
        cudaGetSymbolAddress((void**)&p_shift, g_shift);
        cudaGetSymbolAddress((void**)&p_deg, g_deg);
        cudaGetSymbolAddress((void**)&p_tmp, g_tmp);
        cudaGetSymbolAddress((void**)&p_xs, g_xs);
        cudaGetSymbolAddress((void**)&p_hs, g_hs);
        cudaGetSymbolAddress((void**)&p_as, g_as);
        cudaGetSymbolAddress((void**)&p_Bproj, g_Bproj);
        cudaGetSymbolAddress((void**)&p_Bggc, g_Bggc);
        cudaGetSymbolAddress((void**)&p_Bwih, g_Bwih);
        cudaGetSymbolAddress((void**)&p_Bwhh, g_Bwhh);
        cudaFuncSetAttribute(k_tgemm, cudaFuncAttributeMaxDynamicSharedMemorySize, SMEM_DYN);
        cudaFuncSetAttribute(k_tg64, cudaFuncAttributeMaxDynamicSharedMemorySize, T64_SMEM);
        init = true;
    }

    const float *x, *projW, *projb;
    const void  *edge, *batch;
    const float *bn1g, *bn1b, *bn1m, *bn1v;
    const float *bn2g, *bn2b, *bn2m, *bn2v;
    const float *bnfg, *bnfb, *bnfm, *bnfv;
    const float *ggcW, *wih, *whh, *bih, *bhh, *fc1W, *fc1b, *fc2W, *fc2b;

    x     = (const float*)d_in[0];
    edge  = d_in[1];
    batch = d_in[2];
    projW = (const float*)d_in[3];
    projb = (const float*)d_in[4];
    bn1g = (const float*)d_in[5]; bn1b = (const float*)d_in[6];
    bn1m = (const float*)d_in[7]; bn1v = (const float*)d_in[8];

    if (in_sizes[9] == 120000) {
        ggcW = (const float*)d_in[9];
        wih  = (const float*)d_in[10]; whh = (const float*)d_in[11];
        bih  = (const float*)d_in[12]; bhh = (const float*)d_in[13];
        bn2g = (const float*)d_in[14]; bn2b = (const float*)d_in[15];
        bn2m = (const float*)d_in[16]; bn2v = (const float*)d_in[17];
        fc1W = (const float*)d_in[18]; fc1b = (const float*)d_in[19];
        bnfg = (const float*)d_in[20]; bnfb = (const float*)d_in[21];
        bnfm = (const float*)d_in[22]; bnfv = (const float*)d_in[23];
        fc2W = (const float*)d_in[24]; fc2b = (const float*)d_in[25];
    } else {
        bn2g = (const float*)d_in[9];  bn2b = (const float*)d_in[10];
        bn2m = (const float*)d_in[11]; bn2v = (const float*)d_in[12];
        bnfg = (const float*)d_in[13]; bnfb = (const float*)d_in[14];
        bnfm = (const float*)d_in[15]; bnfv = (const float*)d_in[16];
        ggcW = (const float*)d_in[17];
        wih  = (const float*)d_in[18]; whh = (const float*)d_in[19];
        bih  = (const float*)d_in[20]; bhh = (const float*)d_in[21];
        fc1W = (const float*)d_in[22]; fc1b = (const float*)d_in[23];
        fc2W = (const float*)d_in[24]; fc2b = (const float*)d_in[25];
    }

    const int T = 256;
    const int MT  = cdiv(NN, 128);   // 782
    const int MT64 = cdiv(NN, 64);   // 1563

    k_splitB<<<cdiv(NSTEP * 256 * 2, T), T>>>(projW, p_Bproj, HID, 256, INDIM, 1);
    k_bnprep_all<<<1, 640>>>(bn1g, bn1b, bn1m, bn1v,
                             bn2g, bn2b, bn2m, bn2v,
                             bnfg, bnfb, bnfm, bnfv);
    k_splitA<<<cdiv(NSTEP * NN * 2, T), T>>>(x, p_xs, INDIM);
    // h = relu(bn1(x @ projW^T + projb)); epilogue also writes hs split
    k_tgemm<<<dim3(1, MT), 512, SMEM_DYN>>>(p_xs, p_Bproj, p_h, NN, HID, 256,
                                            projb, p_scale, p_shift, 1, p_hs);
    k_splitB<<<cdiv(NSTEP * 256 * 2, T), T>>>(ggcW, p_Bggc, HID, 256, HID, 0);
    // m = h @ ggc_W[0]
    k_tgemm<<<dim3(1, MT), 512, SMEM_DYN>>>(p_hs, p_Bggc, p_m, NN, HID, 256,
                                            nullptr, nullptr, nullptr, 0, nullptr);

    // edge preprocessing + CSR build (once; reused all 3 iterations)
    k_detect<<<1, 32>>>((const int*)edge, (const int*)batch);
    k_conv_edges<<<cdiv(2 * NE, T), T>>>(edge);
    k_conv_batch<<<cdiv(NN, T), T>>>(batch);
    k_zero<<<cdiv(NN, T), T>>>((float*)p_deg, NN);
    k_hist<<<cdiv(NE, T), T>>>();
    k_scan<<<1, 1024>>>();
    k_zero<<<cdiv(NN, T), T>>>((float*)p_tmp, NN);
    k_fill<<<cdiv(NE, T), T>>>();

    for (int i = 1; i < 3; i++)
        k_splitB<<<cdiv(NSTEP * 256 * 2, T), T>>>(ggcW + (size_t)i * HID * HID,
                                                  p_Bggc + (size_t)i * NSTEP * 256 * HW16,
                                                  HID, 256, HID, 0);
    k_splitB<<<cdiv(NSTEP * 768 * 2, T), T>>>(wih, p_Bwih, H3, 768, HID, 1);
    k_splitB<<<cdiv(NSTEP * 768 * 2, T), T>>>(whh, p_Bwhh, H3, 768, HID, 1);

    for (int it = 0; it < 3; it++) {
        if (it > 0) {
            k_tgemm<<<dim3(1, MT), 512, SMEM_DYN>>>(
                p_hs, p_Bggc + (size_t)it * NSTEP * 256 * HW16,
                p_m, NN, HID, 256, nullptr, nullptr, nullptr, 0, nullptr);
        }
        // agg = CSR gather-sum (no atomics, no zero pass)
        k_agg<<<cdiv(NN * 50, T), T>>>();
        k_splitA<<<cdiv(NSTEP * NN * 2, T), T>>>(p_agg, p_as, HID);
        // gi = agg @ wih^T + bih
        k_tg64<<<dim3(1, MT64), 512, T64_SMEM>>>(p_as, p_Bwih, 768, bih,
                                                 p_gi, nullptr, nullptr, nullptr, 1, 0);
        // gh = h @ whh^T + bhh, fused GRU -> h (+ split for next iter)
        k_tg64<<<dim3(1, MT64), 512, T64_SMEM>>>(p_hs, p_Bwhh, 768, bhh,
                                                 nullptr, p_gi, p_h, p_hs, 2, it < 2 ? 1 : 0);
    }

    k_bn2relu<<<cdiv(NN * HID, T), T>>>();

    k_zero<<<cdiv(NG * 400, T), T>>>(p_pool, NG * 400);
    k_zero<<<cdiv(NG, T), T>>>(p_cnt, NG);
    k_pool<<<cdiv(NN * 50, T), T>>>();
    k_pool_fin<<<cdiv(NG * HID, T), T>>>();

    {
        dim3 grid(cdiv(HID, BN), cdiv(NG, BM));
        k_gemm<<<grid, T>>>(p_pool, fc1W, p_fc1, NG, HID, 2 * HID, 1,
                            fc1b, p_scale + 2 * HID, p_shift + 2 * HID, 1);
    }
    {
        dim3 grid(cdiv(2, BN), cdiv(NG, BM));
        k_gemm<<<grid, T>>>(p_fc1, fc2W, (float*)d_out, NG, 2, HID, 1,
                            fc2b, nullptr, nullptr, 0);
    }
}

// round 13
// speedup vs baseline: 1.8907x; 1.1480x over previous
#include <cuda_runtime.h>
#include <cuda_bf16.h>
#include <stdint.h>
#include <math.h>

#define NN    100000
#define NE    1600000
#define NG    512
#define HID   200
#define H3    600
#define INDIM 205

#define KP    208
#define K3    624
#define NSTEP 39        // K3/16
#define MPAD  100096    // >= 1563*64
#define HW16  16        // halfwords per row per k-step (packed, swizzled)

// ---------------- scratch ----------------
__device__ float g_h  [(size_t)NN * HID];
__device__ float g_m  [(size_t)NN * HID];
__device__ float g_gi [(size_t)NN * H3];
__device__ float g_pool[NG * 2 * HID];
__device__ float g_cnt [NG];
__device__ float g_fc1 [NG * HID];
__device__ float g_scale[3 * HID];
__device__ float g_shift[3 * HID];
__device__ int   g_src[NE];
__device__ int   g_dst[NE];
__device__ int   g_batch[NN];
__device__ int   g_flag_e;
__device__ int   g_flag_b;
// CSR (built once; graph identical across iterations)
__device__ int   g_deg [NN];
__device__ int   g_tmp [NN];
__device__ int   g_rptr[NN + 1];
__device__ int   g_csr [NE];

// packed k-blocked bf16 buffers, swizzle baked into gmem layout:
// element (ks,row,kk) at ((ks*ROWS+row)*16) + ((kk>>3) ^ ((row>>2)&1))*8 + (kk&7)
__device__ __nv_bfloat16 g_xs[(size_t)NSTEP * MPAD * HW16];
__device__ __nv_bfloat16 g_hs[(size_t)NSTEP * MPAD * HW16];
__device__ __nv_bfloat16 g_as[(size_t)NSTEP * MPAD * HW16];
__device__ __nv_bfloat16 g_Bproj[(size_t)NSTEP * 256 * HW16];
__device__ __nv_bfloat16 g_Bggc [3][(size_t)NSTEP * 256 * HW16];
__device__ __nv_bfloat16 g_Bwih [(size_t)NSTEP * 768 * HW16];
__device__ __nv_bfloat16 g_Bwhh [(size_t)NSTEP * 768 * HW16];

// ---------------- dtype detection ----------------
__global__ void k_detect(const int* __restrict__ ew, const int* __restrict__ bw) {
    int lane = threadIdx.x;
    int bad_e = 0, bad_b = 0;
    for (int w = 2 * NE - 255 + 2 * lane; w < 2 * NE; w += 64)
        if (ew[w] != 0) bad_e = 1;
    for (int w = NN - 255 + 2 * lane; w < NN; w += 64)
        if (bw[w] != 0) bad_b = 1;
    unsigned me = __ballot_sync(0xFFFFFFFFu, bad_e);
    unsigned mb = __ballot_sync(0xFFFFFFFFu, bad_b);
    if (lane == 0) { g_flag_e = (me == 0); g_flag_b = (mb == 0); }
}

__global__ void k_conv_edges(const void* __restrict__ e) {
    int i = blockIdx.x * blockDim.x + threadIdx.x;
    if (i >= 2 * NE) return;
    int v = g_flag_e ? (int)((const long long*)e)[i] : ((const int*)e)[i];
    if (i < NE) g_src[i] = v; else g_dst[i - NE] = v;
}

__global__ void k_conv_batch(const void* __restrict__ b) {
    int i = blockIdx.x * blockDim.x + threadIdx.x;
    if (i >= NN) return;
    g_batch[i] = g_flag_b ? (int)((const long long*)b)[i] : ((const int*)b)[i];
}

// ---------------- CSR build (once) ----------------
__global__ void k_hist() {
    int i = blockIdx.x * blockDim.x + threadIdx.x;
    if (i < NE) atomicAdd(&g_deg[g_dst[i]], 1);
}

__global__ void k_scan() {   // single block, 1024 threads
    __shared__ int buf[1024];
    __shared__ int carry;
    int tid = threadIdx.x;
    if (tid == 0) carry = 0;
    __syncthreads();
    for (int base = 0; base < NN; base += 1024) {
        int v = (base + tid < NN) ? g_deg[base + tid] : 0;
        buf[tid] = v;
        __syncthreads();
        for (int off = 1; off < 1024; off <<= 1) {
            int t = (tid >= off) ? buf[tid - off] : 0;
            __syncthreads();
            buf[tid] += t;
            __syncthreads();
        }
        if (base + tid < NN) g_rptr[base + tid] = buf[tid] - v + carry;
        __syncthreads();
        if (tid == 0) carry += buf[1023];
        __syncthreads();
    }
    if (tid == 0) g_rptr[NN] = carry;
}

__global__ void k_fill() {
    int i = blockIdx.x * blockDim.x + threadIdx.x;
    if (i >= NE) return;
    int d = g_dst[i];
    int pos = g_rptr[d] + atomicAdd(&g_tmp[d], 1);
    g_csr[pos] = g_src[i];
}

// ---------------- split-pair writer (device helper) ----------------
__device__ __forceinline__ void write_split_pair(
    __nv_bfloat16* __restrict__ hs, int m, int j /*even*/, float v0, float v1) {
    __nv_bfloat16 h0 = __float2bfloat16(v0), h1 = __float2bfloat16(v1);
    __nv_bfloat16 l0 = __float2bfloat16(v0 - __bfloat162float(h0));
    __nv_bfloat16 l1 = __float2bfloat16(v1 - __bfloat162float(h1));
    uint32_t hi2 = ((uint32_t)*(uint16_t*)&h1 << 16) | *(uint16_t*)&h0;
    uint32_t lo2 = ((uint32_t)*(uint16_t*)&l1 << 16) | *(uint16_t*)&l0;
    int c = j >> 3, ksl = c >> 1, half = c & 1, off = j & 7;
    int swz = (half ^ ((m >> 2) & 1)) << 3;
    *(uint32_t*)(hs + ((size_t)(ksl)      * MPAD + m) * HW16 + swz + off) = hi2;
    *(uint32_t*)(hs + ((size_t)(13 + ksl) * MPAD + m) * HW16 + swz + off) = lo2;
    *(uint32_t*)(hs + ((size_t)(26 + ksl) * MPAD + m) * HW16 + swz + off) = hi2;
}

// ---------------- CSR gather-sum, fused bf16 split output -------------------
// agg values go directly to g_as (bf16 split); fp32 agg buffer eliminated.
__global__ void k_agg() {
    int idx = blockIdx.x * blockDim.x + threadIdx.x;
    if (idx >= NN * 50) return;
    int n = idx / 50, c = idx - n * 50;
    int e0 = g_rptr[n], e1 = g_rptr[n + 1];
    float ax = 0.f, ay = 0.f, az = 0.f, aw = 0.f;
    for (int e = e0; e < e1; e++) {
        int s = g_csr[e];
        const float4 v = *(const float4*)&g_m[(size_t)s * HID + c * 4];
        ax += v.x; ay += v.y; az += v.z; aw += v.w;
    }
    int j = c * 4;
    write_split_pair(g_as, n, j,     ax, ay);
    write_split_pair(g_as, n, j + 2, az, aw);
}

// ---------------- merged BN param prep ----------------
__global__ void k_bnprep_all(
    const float* g1, const float* b1, const float* m1, const float* v1,
    const float* g2, const float* b2, const float* m2, const float* v2,
    const float* gf, const float* bf, const float* mf, const float* vf) {
    int j = threadIdx.x;
    if (j >= 3 * HID) return;
    int which = j / HID, jj = j - which * HID;
    const float *g, *b, *m, *v;
    if (which == 0)      { g = g1; b = b1; m = m1; v = v1; }
    else if (which == 1) { g = g2; b = b2; m = m2; v = v2; }
    else                 { g = gf; b = bf; m = mf; v = vf; }
    float s = g[jj] * rsqrtf(v[jj] + 1e-5f);
    g_scale[j] = s;
    g_shift[j] = b[jj] - m[jj] * s;
}

// ---------------- bf16 split of activations (coalesced, swizzled) -----------
__global__ void k_splitA(const float* __restrict__ in, __nv_bfloat16* __restrict__ out,
                         int K) {
    int idx = blockIdx.x * blockDim.x + threadIdx.x;
    if (idx >= NSTEP * NN * 2) return;
    int ks   = idx / (NN * 2);
    int rem  = idx - ks * (NN * 2);
    int m    = rem >> 1;
    int half = rem & 1;
    int s  = ks / 13;
    int c  = (ks - s * 13) * 2 + half;
    int k0 = c * 8;
    const float* src = in + (size_t)m * K + k0;
    __nv_bfloat16 o[8];
#pragma unroll
    for (int i = 0; i < 8; i++) {
        float v = (k0 + i < K) ? src[i] : 0.f;
        __nv_bfloat16 hi = __float2bfloat16(v);
        o[i] = (s == 1) ? __float2bfloat16(v - __bfloat162float(hi)) : hi;
    }
    int swz = half ^ ((m >> 2) & 1);
    *(uint4*)(out + ((size_t)ks * MPAD + m) * HW16 + swz * 8) = *(const uint4*)o;
}

// ---------------- bf16 split of weights (swizzled) ----------------
__global__ void k_splitB(const float* __restrict__ W, __nv_bfloat16* __restrict__ out,
                         int N, int Npad, int K, int trans) {
    int idx = blockIdx.x * blockDim.x + threadIdx.x;
    if (idx >= NSTEP * Npad * 2) return;
    int ks   = idx / (Npad * 2);
    int rem  = idx - ks * (Npad * 2);
    int n    = rem >> 1;
    int half = rem & 1;
    int s  = ks / 13;
    int c  = (ks - s * 13) * 2 + half;
    int k0 = c * 8;
    __nv_bfloat16 o[8];
#pragma unroll
    for (int i = 0; i < 8; i++) {
        int k = k0 + i;
        float v = 0.f;
        if (n < N && k < K) v = trans ? W[(size_t)n * K + k] : W[(size_t)k * N + n];
        __nv_bfloat16 hi = __float2bfloat16(v);
        o[i] = (s == 2) ? __float2bfloat16(v - __bfloat162float(hi)) : hi;
    }
    int swz = half ^ ((n >> 2) & 1);
    *(uint4*)(out + ((size_t)ks * Npad + n) * HW16 + swz * 8) = *(const uint4*)o;
}

// ---------------- tensor GEMM A: 128x256 tile, 512 thr ----------------------
#define STAGES       6
#define STAGE_A_HW   (128 * HW16)
#define STAGE_B_HW   (256 * HW16)
#define STAGE_HW     (STAGE_A_HW + STAGE_B_HW)
#define STAGE_BYTES  (STAGE_HW * 2)          // 12288
#define A_BYTES      (STAGE_A_HW * 2)
#define B_BYTES      (STAGE_B_HW * 2)
#define SMEM_DYN     (STAGES * STAGE_BYTES + 64)

__global__ void __launch_bounds__(512, 1)
k_tgemm(const __nv_bfloat16* __restrict__ A, const __nv_bfloat16* __restrict__ B,
        float* __restrict__ C, int M, int N, int NPADB,
        const float* __restrict__ bias,
        const float* __restrict__ scale, const float* __restrict__ shift,
        int relu, __nv_bfloat16* __restrict__ hs_out) {
    extern __shared__ __align__(128) __nv_bfloat16 dsm[];

    const int tid  = threadIdx.x;
    const int warp = tid >> 5, lane = tid & 31;
    const int wm = warp & 3, wn = warp >> 2;       // 4 x 4
    const int m0 = blockIdx.y * 128;
    const int n0 = blockIdx.x * 256;

    const uint32_t smem_base = (uint32_t)__cvta_generic_to_shared(dsm);
    const uint32_t mbar_base = smem_base + STAGES * STAGE_BYTES;

    if (tid == 0) {
        for (int s = 0; s < STAGES; s++)
            asm volatile("mbarrier.init.shared.b64 [%0], 1;" :: "r"(mbar_base + s * 8) : "memory");
        asm volatile("fence.proxy.async.shared::cta;" ::: "memory");
    }
    __syncthreads();

    float acc[2][8][4];
#pragma unroll
    for (int mi = 0; mi < 2; mi++)
#pragma unroll
        for (int ni = 0; ni < 8; ni++)
#pragma unroll
            for (int j = 0; j < 4; j++) acc[mi][ni][j] = 0.f;

#define ISSUE(kf)                                                                \
    do {                                                                         \
        int slot_ = (kf) % STAGES;                                               \
        uint32_t mb_ = mbar_base + slot_ * 8;                                    \
        asm volatile("mbarrier.arrive.expect_tx.shared.b64 _, [%0], %1;"         \
                     :: "r"(mb_), "r"((uint32_t)STAGE_BYTES) : "memory");        \
        uint32_t da_ = smem_base + slot_ * STAGE_BYTES;                          \
        const __nv_bfloat16* sa_ = A + ((size_t)(kf) * MPAD + m0) * HW16;        \
        asm volatile("cp.async.bulk.shared::cta.global.mbarrier::complete_tx::bytes " \
                     "[%0], [%1], %2, [%3];"                                     \
                     :: "r"(da_), "l"(sa_), "r"((uint32_t)A_BYTES), "r"(mb_)     \
                     : "memory");                                                \
        uint32_t db_ = da_ + A_BYTES;                                            \
        const __nv_bfloat16* sb_ = B + ((size_t)(kf) * NPADB + n0) * HW16;       \
        asm volatile("cp.async.bulk.shared::cta.global.mbarrier::complete_tx::bytes " \
                     "[%0], [%1], %2, [%3];"                                     \
                     :: "r"(db_), "l"(sb_), "r"((uint32_t)B_BYTES), "r"(mb_)     \
                     : "memory");                                                \
    } while (0)

    if (tid == 0)
        for (int kf = 0; kf < STAGES - 1 && kf < NSTEP; kf++) ISSUE(kf);

    const int lr = lane & 15;
    const int ch = lane >> 4;
    const int xa = (lane >> 2) & 1;
    const int bn = lane >> 2;
    const int xb = (lane >> 4) & 1;
    const int bk = (lane & 3) * 2;

    for (int ks = 0; ks < NSTEP; ks++) {
        __syncthreads();
        if (tid == 0) {
            int kf = ks + STAGES - 1;
            if (kf < NSTEP) ISSUE(kf);
        }
        const int slot = ks % STAGES;
        const uint32_t mb = mbar_base + slot * 8;
        const uint32_t parity = (uint32_t)((ks / STAGES) & 1);
        {
            uint32_t done = 0;
            while (!done) {
                asm volatile(
                    "{\n\t.reg .pred p;\n\t"
                    "mbarrier.try_wait.parity.acquire.cta.shared::cta.b64 p, [%1], %2;\n\t"
                    "selp.b32 %0, 1, 0, p;\n\t}"
                    : "=r"(done) : "r"(mb), "r"(parity) : "memory");
            }
        }

        const uint32_t aBase = smem_base + slot * STAGE_BYTES;
        const __nv_bfloat16* sBp = dsm + slot * STAGE_HW + STAGE_A_HW;

        uint32_t a[2][4];
        uint32_t b[8][2];
#pragma unroll
        for (int mi = 0; mi < 2; mi++) {
            int row = wm * 32 + mi * 16 + lr;
            uint32_t addr = aBase + (row * HW16 + ((ch ^ xa) << 3)) * 2;
            asm volatile("ldmatrix.sync.aligned.m8n8.x4.shared.b16 {%0,%1,%2,%3}, [%4];"
                         : "=r"(a[mi][0]), "=r"(a[mi][1]), "=r"(a[mi][2]), "=r"(a[mi][3])
                         : "r"(addr));
        }
#pragma unroll
        for (int ni = 0; ni < 8; ni++) {
            int row = wn * 64 + ni * 8 + bn;
            b[ni][0] = *(const uint32_t*)(sBp + row * HW16 + (xb << 3) + bk);
            b[ni][1] = *(const uint32_t*)(sBp + row * HW16 + ((1 ^ xb) << 3) + bk);
        }
#pragma unroll
        for (int mi = 0; mi < 2; mi++)
#pragma unroll
            for (int ni = 0; ni < 8; ni++) {
                asm volatile(
                    "mma.sync.aligned.m16n8k16.row.col.f32.bf16.bf16.f32 "
                    "{%0,%1,%2,%3}, {%4,%5,%6,%7}, {%8,%9}, {%0,%1,%2,%3};"
                    : "+f"(acc[mi][ni][0]), "+f"(acc[mi][ni][1]),
                      "+f"(acc[mi][ni][2]), "+f"(acc[mi][ni][3])
                    : "r"(a[mi][0]), "r"(a[mi][1]), "r"(a[mi][2]), "r"(a[mi][3]),
                      "r"(b[ni][0]), "r"(b[ni][1]));
            }
    }
#undef ISSUE

    const int r = lane >> 2;
    const int c = (lane & 3) * 2;
#pragma unroll
    for (int mi = 0; mi < 2; mi++) {
#pragma unroll
        for (int ni = 0; ni < 8; ni++) {
            int n = n0 + wn * 64 + ni * 8 + c;
            if (n >= N) continue;
            float bia0 = 0.f, bia1 = 0.f, sc0 = 1.f, sc1 = 1.f, sh0 = 0.f, sh1 = 0.f;
            bool n1ok = (n + 1 < N);
            if (bias)  { bia0 = bias[n]; if (n1ok) bia1 = bias[n + 1]; }
            if (scale) { sc0 = scale[n]; sh0 = shift[n];
                         if (n1ok) { sc1 = scale[n + 1]; sh1 = shift[n + 1]; } }
#pragma unroll
            for (int half = 0; half < 2; half++) {
                int m = m0 + wm * 32 + mi * 16 + half * 8 + r;
                if (m >= M) continue;
                float v0 = acc[mi][ni][half * 2 + 0] + bia0;
                float v1 = acc[mi][ni][half * 2 + 1] + bia1;
                if (scale) { v0 = v0 * sc0 + sh0; v1 = v1 * sc1 + sh1; }
                if (relu)  { v0 = fmaxf(v0, 0.f); v1 = fmaxf(v1, 0.f); }
                float* p = C + (size_t)m * N + n;
                p[0] = v0;
                if (n1ok) p[1] = v1;
                if (hs_out && n1ok) write_split_pair(hs_out, m, n, v0, v1);
            }
        }
    }
}

// ---------------- tensor GEMM B: 64 x 640 tile, fused GRU / tail ------------
// mode 1: C[m,600] = A@B^T + bias
// mode 2: gh = A@B^T + bias, fused GRU -> h (+ optional hs split)
// mode 3: gh = A@B^T + bias, fused GRU -> bn2+relu -> pool atomics (no h write)
#define T64S        4
#define T64_A_B     (64 * 32)                 // 2048
#define T64_B_B     (640 * 32)                // 20480
#define T64_ST_B    (T64_A_B + T64_B_B)       // 22528
#define T64_EPI_STR 608
#define T64_EPI_B   (64 * T64_EPI_STR * 4)    // 155648
#define T64_SMEM    (T64_EPI_B + 64)

__global__ void __launch_bounds__(512, 1)
k_tg64(const __nv_bfloat16* __restrict__ A, const __nv_bfloat16* __restrict__ B,
       int NPADB, const float* __restrict__ bias,
       float* __restrict__ C,
       const float* __restrict__ gi_in, float* __restrict__ h_io,
       __nv_bfloat16* __restrict__ hs_out, int mode, int do_split) {
    extern __shared__ __align__(128) __nv_bfloat16 dsm[];

    const int tid  = threadIdx.x;
    const int warp = tid >> 5, lane = tid & 31;
    const int wm = warp & 1, wn = warp >> 1;       // 2 x 8
    const int m0 = blockIdx.y * 64;

    const uint32_t smem_base = (uint32_t)__cvta_generic_to_shared(dsm);
    const uint32_t mbar_base = smem_base + T64_EPI_B;

    if (tid == 0) {
        for (int s = 0; s < T64S; s++)
            asm volatile("mbarrier.init.shared.b64 [%0], 1;" :: "r"(mbar_base + s * 8) : "memory");
        asm volatile("fence.proxy.async.shared::cta;" ::: "memory");
    }
    __syncthreads();

    float acc[2][10][4];
#pragma unroll
    for (int mi = 0; mi < 2; mi++)
#pragma unroll
        for (int ni = 0; ni < 10; ni++)
#pragma unroll
            for (int j = 0; j < 4; j++) acc[mi][ni][j] = 0.f;

#define ISSUE64(kf)                                                              \
    do {                                                                         \
        int slot_ = (kf) % T64S;                                                 \
        uint32_t mb_ = mbar_base + slot_ * 8;                                    \
        asm volatile("mbarrier.arrive.expect_tx.shared.b64 _, [%0], %1;"         \
                     :: "r"(mb_), "r"((uint32_t)T64_ST_B) : "memory");           \
        uint32_t da_ = smem_base + slot_ * T64_ST_B;                             \
        const __nv_bfloat16* sa_ = A + ((size_t)(kf) * MPAD + m0) * HW16;        \
        asm volatile("cp.async.bulk.shared::cta.global.mbarrier::complete_tx::bytes " \
                     "[%0], [%1], %2, [%3];"                                     \
                     :: "r"(da_), "l"(sa_), "r"((uint32_t)T64_A_B), "r"(mb_)     \
                     : "memory");                                                \
        uint32_t db_ = da_ + T64_A_B;                                            \
        const __nv_bfloat16* sb_ = B + (size_t)(kf) * NPADB * HW16;              \
        asm volatile("cp.async.bulk.shared::cta.global.mbarrier::complete_tx::bytes " \
                     "[%0], [%1], %2, [%3];"                                     \
                     :: "r"(db_), "l"(sb_), "r"((uint32_t)T64_B_B), "r"(mb_)     \
                     : "memory");                                                \
    } while (0)

    if (tid == 0)
        for (int kf = 0; kf < T64S - 1 && kf < NSTEP; kf++) ISSUE64(kf);

    const int lr = lane & 15;
    const int ch = lane >> 4;
    const int xa = (lane >> 2) & 1;
    const int bn = lane >> 2;
    const int xb = (lane >> 4) & 1;
    const int bk = (lane & 3) * 2;

    for (int ks = 0; ks < NSTEP; ks++) {
        __syncthreads();
        if (tid == 0) {
            int kf = ks + T64S - 1;
            if (kf < NSTEP) ISSUE64(kf);
        }
        const int slot = ks % T64S;
        const uint32_t mb = mbar_base + slot * 8;
        const uint32_t parity = (uint32_t)((ks / T64S) & 1);
        {
            uint32_t done = 0;
            while (!done) {
                asm volatile(
                    "{\n\t.reg .pred p;\n\t"
                    "mbarrier.try_wait.parity.acquire.cta.shared::cta.b64 p, [%1], %2;\n\t"
                    "selp.b32 %0, 1, 0, p;\n\t}"
                    : "=r"(done) : "r"(mb), "r"(parity) : "memory");
            }
        }

        const uint32_t aBase = smem_base + slot * T64_ST_B;
        const __nv_bfloat16* sBp = dsm + slot * (T64_ST_B / 2) + (T64_A_B / 2);

        uint32_t a[2][4];
        uint32_t b[10][2];
#pragma unroll
        for (int mi = 0; mi < 2; mi++) {
            int row = wm * 32 + mi * 16 + lr;
            uint32_t addr = aBase + (row * HW16 + ((ch ^ xa) << 3)) * 2;
            asm volatile("ldmatrix.sync.aligned.m8n8.x4.shared.b16 {%0,%1,%2,%3}, [%4];"
                         : "=r"(a[mi][0]), "=r"(a[mi][1]), "=r"(a[mi][2]), "=r"(a[mi][3])
                         : "r"(addr));
        }
#pragma unroll
        for (int ni = 0; ni < 10; ni++) {
            int row = wn * 80 + ni * 8 + bn;
            b[ni][0] = *(const uint32_t*)(sBp + row * HW16 + (xb << 3) + bk);
            b[ni][1] = *(const uint32_t*)(sBp + row * HW16 + ((1 ^ xb) << 3) + bk);
        }
#pragma unroll
        for (int mi = 0; mi < 2; mi++)
#pragma unroll
            for (int ni = 0; ni < 10; ni++) {
                asm volatile(
                    "mma.sync.aligned.m16n8k16.row.col.f32.bf16.bf16.f32 "
                    "{%0,%1,%2,%3}, {%4,%5,%6,%7}, {%8,%9}, {%0,%1,%2,%3};"
                    : "+f"(acc[mi][ni][0]), "+f"(acc[mi][ni][1]),
                      "+f"(acc[mi][ni][2]), "+f"(acc[mi][ni][3])
                    : "r"(a[mi][0]), "r"(a[mi][1]), "r"(a[mi][2]), "r"(a[mi][3]),
                      "r"(b[ni][0]), "r"(b[ni][1]));
            }
    }
#undef ISSUE64

    const int r = lane >> 2;
    const int c = (lane & 3) * 2;

    if (mode == 1) {
#pragma unroll
        for (int mi = 0; mi < 2; mi++)
#pragma unroll
            for (int ni = 0; ni < 10; ni++) {
                int n = wn * 80 + ni * 8 + c;
                if (n >= H3) continue;
                float bia0 = bias ? bias[n] : 0.f;
                float bia1 = bias ? bias[n + 1] : 0.f;
#pragma unroll
                for (int half = 0; half < 2; half++) {
                    int m = m0 + wm * 32 + mi * 16 + half * 8 + r;
                    if (m >= NN) continue;
                    float* p = C + (size_t)m * H3 + n;
                    p[0] = acc[mi][ni][half * 2 + 0] + bia0;
                    p[1] = acc[mi][ni][half * 2 + 1] + bia1;
                }
            }
        return;
    }

    // modes 2/3: stage gh = acc + bhh to smem, then fused GRU (+tail)
    __syncthreads();
    float* sg = (float*)dsm;
#pragma unroll
    for (int mi = 0; mi < 2; mi++)
#pragma unroll
        for (int ni = 0; ni < 10; ni++) {
            int n = wn * 80 + ni * 8 + c;
            if (n >= H3) continue;
            float bia0 = bias[n], bia1 = bias[n + 1];
#pragma unroll
            for (int half = 0; half < 2; half++) {
                int row = wm * 32 + mi * 16 + half * 8 + r;
                sg[row * T64_EPI_STR + n]     = acc[mi][ni][half * 2 + 0] + bia0;
                sg[row * T64_EPI_STR + n + 1] = acc[mi][ni][half * 2 + 1] + bia1;
            }
        }
    __syncthreads();

    for (int task = tid; task < 64 * 50; task += 512) {
        int row = task / 50;
        int m = m0 + row;
        if (m >= NN) continue;
        int jc = task - row * 50;
        int j = jc * 4;
        const float* gi = gi_in + (size_t)m * H3;
        float4 ir4 = *(const float4*)(gi + j);
        float4 iz4 = *(const float4*)(gi + j + 200);
        float4 in4 = *(const float4*)(gi + j + 400);
        const float* sgr = sg + row * T64_EPI_STR;
        float4 hr4 = *(const float4*)(sgr + j);
        float4 hz4 = *(const float4*)(sgr + j + 200);
        float4 hn4 = *(const float4*)(sgr + j + 400);
        float* hp = h_io + (size_t)m * HID + j;
        float4 h4 = *(float4*)hp;

        float hv[4];
        const float ir[4] = {ir4.x, ir4.y, ir4.z, ir4.w};
        const float iz[4] = {iz4.x, iz4.y, iz4.z, iz4.w};
        const float in_[4] = {in4.x, in4.y, in4.z, in4.w};
        const float hr[4] = {hr4.x, hr4.y, hr4.z, hr4.w};
        const float hz[4] = {hz4.x, hz4.y, hz4.z, hz4.w};
        const float hn[4] = {hn4.x, hn4.y, hn4.z, hn4.w};
        const float ho[4] = {h4.x, h4.y, h4.z, h4.w};
#pragma unroll
        for (int i = 0; i < 4; i++) {
            float rr = 1.f / (1.f + expf(-(ir[i] + hr[i])));
            float zz = 1.f / (1.f + expf(-(iz[i] + hz[i])));
            float nn = tanhf(in_[i] + rr * hn[i]);
            hv[i] = (1.f - zz) * nn + zz * ho[i];
        }

        if (mode == 2) {
            *(float4*)hp = make_float4(hv[0], hv[1], hv[2], hv[3]);
            if (do_split) {
                write_split_pair(hs_out, m, j,     hv[0], hv[1]);
                write_split_pair(hs_out, m, j + 2, hv[2], hv[3]);
            }
        } else {
            // mode 3: bn2 + relu + pool atomics, no h write
            int b = g_batch[m];
            float* mp = &g_pool[b * 400 + j];
            int*   xp = (int*)&g_pool[b * 400 + 200 + j];
#pragma unroll
            for (int i = 0; i < 4; i++) {
                int jj = j + i;
                float v = fmaxf(hv[i] * g_scale[HID + jj] + g_shift[HID + jj], 0.f);
                atomicAdd(mp + i, v);
                atomicMax(xp + i, __float_as_int(v));
            }
            if (jc == 0) atomicAdd(&g_cnt[b], 1.0f);
        }
    }
}

// ---------------- small SIMT GEMM (fc1/fc2) ----------------
#define BM 64
#define BN 64
#define BK 16
__global__ void k_gemm(const float* __restrict__ A, const float* __restrict__ B,
                       float* __restrict__ C, int M, int N, int K, int transB,
                       const float* __restrict__ bias,
                       const float* __restrict__ scale,
                       const float* __restrict__ shift, int relu) {
    __shared__ float As[BK][BM];
    __shared__ float Bs[BK][BN + 4];
    const int m0 = blockIdx.y * BM;
    const int n0 = blockIdx.x * BN;
    const int tid = threadIdx.x;
    const int tm = tid >> 4;
    const int tn = tid & 15;
    float acc[4][4];
#pragma unroll
    for (int i = 0; i < 4; i++)
#pragma unroll
        for (int j = 0; j < 4; j++) acc[i][j] = 0.f;

    for (int k0 = 0; k0 < K; k0 += BK) {
        {
            int ar = tid >> 2;
            int ac = (tid & 3) * 4;
            int m = m0 + ar;
#pragma unroll
            for (int i = 0; i < 4; i++) {
                int k = k0 + ac + i;
                As[ac + i][ar] = (m < M && k < K) ? A[(size_t)m * K + k] : 0.f;
            }
        }
        if (!transB) {
            int br = tid >> 4;
            int bc = (tid & 15) * 4;
            int k = k0 + br;
#pragma unroll
            for (int i = 0; i < 4; i++) {
                int n = n0 + bc + i;
                Bs[br][bc + i] = (k < K && n < N) ? B[(size_t)k * N + n] : 0.f;
            }
        } else {
            int br = tid >> 2;
            int bc = (tid & 3) * 4;
            int n = n0 + br;
#pragma unroll
            for (int i = 0; i < 4; i++) {
                int k = k0 + bc + i;
                Bs[bc + i][br] = (n < N && k < K) ? B[(size_t)n * K + k] : 0.f;
            }
        }
        __syncthreads();
#pragma unroll
        for (int k = 0; k < BK; k++) {
            float a[4], b[4];
#pragma unroll
            for (int i = 0; i < 4; i++) a[i] = As[k][tm * 4 + i];
#pragma unroll
            for (int j = 0; j < 4; j++) b[j] = Bs[k][tn * 4 + j];
#pragma unroll
            for (int i = 0; i < 4; i++)
#pragma unroll
                for (int j = 0; j < 4; j++) acc[i][j] += a[i] * b[j];
        }
        __syncthreads();
    }
#pragma unroll
    for (int i = 0; i < 4; i++) {
        int m = m0 + tm * 4 + i;
        if (m >= M) continue;
#pragma unroll
        for (int j = 0; j < 4; j++) {
            int n = n0 + tn * 4 + j;
            if (n >= N) continue;
            float v = acc[i][j];
            if (bias)  v += bias[n];
            if (scale) v = v * scale[n] + shift[n];
            if (relu)  v = fmaxf(v, 0.f);
            C[(size_t)m * N + n] = v;
        }
    }
}

// ---------------- zero helper ----------------
__global__ void k_zero(float* __restrict__ p, int n) {
    int i = blockIdx.x * blockDim.x + threadIdx.x;
    if (i < n) p[i] = 0.f;
}

__global__ void k_pool_fin() {
    int idx = blockIdx.x * blockDim.x + threadIdx.x;
    if (idx >= NG * HID) return;
    int g = idx / HID;
    int j = idx - g * HID;
    g_pool[g * 400 + j] *= 1.f / fmaxf(g_cnt[g], 1.f);
}

// ---------------- host launch ----------------
static inline int cdiv(int a, int b) { return (a + b - 1) / b; }

extern "C" void kernel_launch(void* const* d_in, const int* in_sizes, int n_in,
                              void* d_out, int out_size) {
    static bool init = false;
    static float *p_h, *p_m, *p_gi, *p_pool, *p_cnt, *p_fc1, *p_scale, *p_shift;
    static int *p_deg, *p_tmp;
    static __nv_bfloat16 *p_xs, *p_hs, *p_as, *p_Bproj, *p_Bggc, *p_Bwih, *p_Bwhh;
    if (!init) {
        cudaGetSymbolAddress((void**)&p_h, g_h);
        cudaGetSymbolAddress((void**)&p_m, g_m);
        cudaGetSymbolAddress((void**)&p_gi, g_gi);
        cudaGetSymbolAddress((void**)&p_pool, g_pool);
        cudaGetSymbolAddress((void**)&p_cnt, g_cnt);
        cudaGetSymbolAddress((void**)&p_fc1, g_fc1);
        cudaGetSymbolAddress((void**)&p_scale, g_scale);
        cudaGetSymbolAddress((void**)&p_shift, g_shift);
        cudaGetSymbolAddress((void**)&p_deg, g_deg);
        cudaGetSymbolAddress((void**)&p_tmp, g_tmp);
        cudaGetSymbolAddress((void**)&p_xs, g_xs);
        cudaGetSymbolAddress((void**)&p_hs, g_hs);
        cudaGetSymbolAddress((void**)&p_as, g_as);
        cudaGetSymbolAddress((void**)&p_Bproj, g_Bproj);
        cudaGetSymbolAddress((void**)&p_Bggc, g_Bggc);
        cudaGetSymbolAddress((void**)&p_Bwih, g_Bwih);
        cudaGetSymbolAddress((void**)&p_Bwhh, g_Bwhh);
        cudaFuncSetAttribute(k_tgemm, cudaFuncAttributeMaxDynamicSharedMemorySize, SMEM_DYN);
        cudaFuncSetAttribute(k_tg64, cudaFuncAttributeMaxDynamicSharedMemorySize, T64_SMEM);
        init = true;
    }

    const float *x, *projW, *projb;
    const void  *edge, *batch;
    const float *bn1g, *bn1b, *bn1m, *bn1v;
    const float *bn2g, *bn2b, *bn2m, *bn2v;
    const float *bnfg, *bnfb, *bnfm, *bnfv;
    const float *ggcW, *wih, *whh, *bih, *bhh, *fc1W, *fc1b, *fc2W, *fc2b;

    x     = (const float*)d_in[0];
    edge  = d_in[1];
    batch = d_in[2];
    projW = (const float*)d_in[3];
    projb = (const float*)d_in[4];
    bn1g = (const float*)d_in[5]; bn1b = (const float*)d_in[6];
    bn1m = (const float*)d_in[7]; bn1v = (const float*)d_in[8];

    if (in_sizes[9] == 120000) {
        ggcW = (const float*)d_in[9];
        wih  = (const float*)d_in[10]; whh = (const float*)d_in[11];
        bih  = (const float*)d_in[12]; bhh = (const float*)d_in[13];
        bn2g = (const float*)d_in[14]; bn2b = (const float*)d_in[15];
        bn2m = (const float*)d_in[16]; bn2v = (const float*)d_in[17];
        fc1W = (const float*)d_in[18]; fc1b = (const float*)d_in[19];
        bnfg = (const float*)d_in[20]; bnfb = (const float*)d_in[21];
        bnfm = (const float*)d_in[22]; bnfv = (const float*)d_in[23];
        fc2W = (const float*)d_in[24]; fc2b = (const float*)d_in[25];
    } else {
        bn2g = (const float*)d_in[9];  bn2b = (const float*)d_in[10];
        bn2m = (const float*)d_in[11]; bn2v = (const float*)d_in[12];
        bnfg = (const float*)d_in[13]; bnfb = (const float*)d_in[14];
        bnfm = (const float*)d_in[15]; bnfv = (const float*)d_in[16];
        ggcW = (const float*)d_in[17];
        wih  = (const float*)d_in[18]; whh = (const float*)d_in[19];
        bih  = (const float*)d_in[20]; bhh = (const float*)d_in[21];
        fc1W = (const float*)d_in[22]; fc1b = (const float*)d_in[23];
        fc2W = (const float*)d_in[24]; fc2b = (const float*)d_in[25];
    }

    const int T = 256;
    const int MT  = cdiv(NN, 128);   // 782
    const int MT64 = cdiv(NN, 64);   // 1563

    k_splitB<<<cdiv(NSTEP * 256 * 2, T), T>>>(projW, p_Bproj, HID, 256, INDIM, 1);
    k_bnprep_all<<<1, 640>>>(bn1g, bn1b, bn1m, bn1v,
                             bn2g, bn2b, bn2m, bn2v,
                             bnfg, bnfb, bnfm, bnfv);
    k_splitA<<<cdiv(NSTEP * NN * 2, T), T>>>(x, p_xs, INDIM);
    // h = relu(bn1(x @ projW^T + projb)); epilogue also writes hs split
    k_tgemm<<<dim3(1, MT), 512, SMEM_DYN>>>(p_xs, p_Bproj, p_h, NN, HID, 256,
                                            projb, p_scale, p_shift, 1, p_hs);
    k_splitB<<<cdiv(NSTEP * 256 * 2, T), T>>>(ggcW, p_Bggc, HID, 256, HID, 0);
    // m = h @ ggc_W[0]
    k_tgemm<<<dim3(1, MT), 512, SMEM_DYN>>>(p_hs, p_Bggc, p_m, NN, HID, 256,
                                            nullptr, nullptr, nullptr, 0, nullptr);

    // edge preprocessing + CSR build (once)
    k_detect<<<1, 32>>>((const int*)edge, (const int*)batch);
    k_conv_edges<<<cdiv(2 * NE, T), T>>>(edge);
    k_conv_batch<<<cdiv(NN, T), T>>>(batch);
    k_zero<<<cdiv(NN, T), T>>>((float*)p_deg, NN);
    k_hist<<<cdiv(NE, T), T>>>();
    k_scan<<<1, 1024>>>();
    k_zero<<<cdiv(NN, T), T>>>((float*)p_tmp, NN);
    k_fill<<<cdiv(NE, T), T>>>();

    for (int i = 1; i < 3; i++)
        k_splitB<<<cdiv(NSTEP * 256 * 2, T), T>>>(ggcW + (size_t)i * HID * HID,
                                                  p_Bggc + (size_t)i * NSTEP * 256 * HW16,
                                                  HID, 256, HID, 0);
    k_splitB<<<cdiv(NSTEP * 768 * 2, T), T>>>(wih, p_Bwih, H3, 768, HID, 1);
    k_splitB<<<cdiv(NSTEP * 768 * 2, T), T>>>(whh, p_Bwhh, H3, 768, HID, 1);

    // pool buffers zeroed before the loop (mode-3 tail writes them)
    k_zero<<<cdiv(NG * 400, T), T>>>(p_pool, NG * 400);
    k_zero<<<cdiv(NG, T), T>>>(p_cnt, NG);

    for (int it = 0; it < 3; it++) {
        if (it > 0) {
            k_tgemm<<<dim3(1, MT), 512, SMEM_DYN>>>(
                p_hs, p_Bggc + (size_t)it * NSTEP * 256 * HW16,
                p_m, NN, HID, 256, nullptr, nullptr, nullptr, 0, nullptr);
        }
        // agg = CSR gather-sum; writes bf16 split (g_as) directly
        k_agg<<<cdiv(NN * 50, T), T>>>();
        // gi = agg @ wih^T + bih
        k_tg64<<<dim3(1, MT64), 512, T64_SMEM>>>(p_as, p_Bwih, 768, bih,
                                                 p_gi, nullptr, nullptr, nullptr, 1, 0);
        // gh = h @ whh^T + bhh, fused GRU; last iter also fuses bn2+relu+pool
        int mode = (it < 2) ? 2 : 3;
        k_tg64<<<dim3(1, MT64), 512, T64_SMEM>>>(p_hs, p_Bwhh, 768, bhh,
                                                 nullptr, p_gi, p_h, p_hs, mode,
                                                 it < 2 ? 1 : 0);
    }

    k_pool_fin<<<cdiv(NG * HID, T), T>>>();

    {
        dim3 grid(cdiv(HID, BN), cdiv(NG, BM));
        k_gemm<<<grid, T>>>(p_pool, fc1W, p_fc1, NG, HID, 2 * HID, 1,
                            fc1b, p_scale + 2 * HID, p_shift + 2 * HID, 1);
    }
    {
        dim3 grid(cdiv(2, BN), cdiv(NG, BM));
        k_gemm<<<grid, T>>>(p_fc1, fc2W, (float*)d_out, NG, 2, HID, 1,
                            fc2b, nullptr, nullptr, 0);
    }
}

// round 14
// speedup vs baseline: 2.1214x; 1.1220x over previous
#include <cuda_runtime.h>
#include <cuda_bf16.h>
#include <stdint.h>
#include <math.h>

#define NN    100000
#define NE    1600000
#define NG    512
#define HID   200
#define H3    600
#define INDIM 205

#define KP    208
#define K3    624
#define NSTEP 39        // K3/16
#define MPAD  100096    // >= 1563*64
#define HW16  16        // halfwords per row per k-step (packed, swizzled)

// ---------------- scratch ----------------
__device__ float g_h  [(size_t)NN * HID];
__device__ float g_gi [(size_t)NN * H3];   // head also used as Wc fp32 scratch pre-loop
__device__ float g_pool[NG * 2 * HID];
__device__ float g_cnt [NG];
__device__ float g_fc1 [NG * HID];
__device__ float g_scale[3 * HID];
__device__ float g_shift[3 * HID];
__device__ int   g_src[NE];
__device__ int   g_dst[NE];
__device__ int   g_batch[NN];
__device__ int   g_flag_e;
__device__ int   g_flag_b;
// CSR (built once; graph identical across iterations)
__device__ int   g_deg [NN];
__device__ int   g_tmp [NN];
__device__ int   g_rptr[NN + 1];
__device__ int   g_csr [NE];

// packed k-blocked bf16 buffers, swizzle baked into gmem layout:
// element (ks,row,kk) at ((ks*ROWS+row)*16) + ((kk>>3) ^ ((row>>2)&1))*8 + (kk&7)
__device__ __nv_bfloat16 g_xs[(size_t)NSTEP * MPAD * HW16];
__device__ __nv_bfloat16 g_hs[(size_t)NSTEP * MPAD * HW16];
__device__ __nv_bfloat16 g_as[(size_t)NSTEP * MPAD * HW16];
__device__ __nv_bfloat16 g_Bproj[(size_t)NSTEP * 256 * HW16];
__device__ __nv_bfloat16 g_BWc [3][(size_t)NSTEP * 640 * HW16];   // (ggcW_i @ wih^T) split
__device__ __nv_bfloat16 g_Bwhh[(size_t)NSTEP * 768 * HW16];

// ---------------- dtype detection ----------------
__global__ void k_detect(const int* __restrict__ ew, const int* __restrict__ bw) {
    int lane = threadIdx.x;
    int bad_e = 0, bad_b = 0;
    for (int w = 2 * NE - 255 + 2 * lane; w < 2 * NE; w += 64)
        if (ew[w] != 0) bad_e = 1;
    for (int w = NN - 255 + 2 * lane; w < NN; w += 64)
        if (bw[w] != 0) bad_b = 1;
    unsigned me = __ballot_sync(0xFFFFFFFFu, bad_e);
    unsigned mb = __ballot_sync(0xFFFFFFFFu, bad_b);
    if (lane == 0) { g_flag_e = (me == 0); g_flag_b = (mb == 0); }
}

__global__ void k_conv_edges(const void* __restrict__ e) {
    int i = blockIdx.x * blockDim.x + threadIdx.x;
    if (i >= 2 * NE) return;
    int v = g_flag_e ? (int)((const long long*)e)[i] : ((const int*)e)[i];
    if (i < NE) g_src[i] = v; else g_dst[i - NE] = v;
}

__global__ void k_conv_batch(const void* __restrict__ b) {
    int i = blockIdx.x * blockDim.x + threadIdx.x;
    if (i >= NN) return;
    g_batch[i] = g_flag_b ? (int)((const long long*)b)[i] : ((const int*)b)[i];
}

// ---------------- CSR build (once) ----------------
__global__ void k_hist() {
    int i = blockIdx.x * blockDim.x + threadIdx.x;
    if (i < NE) atomicAdd(&g_deg[g_dst[i]], 1);
}

__global__ void k_scan() {   // single block, 1024 threads
    __shared__ int buf[1024];
    __shared__ int carry;
    int tid = threadIdx.x;
    if (tid == 0) carry = 0;
    __syncthreads();
    for (int base = 0; base < NN; base += 1024) {
        int v = (base + tid < NN) ? g_deg[base + tid] : 0;
        buf[tid] = v;
        __syncthreads();
        for (int off = 1; off < 1024; off <<= 1) {
            int t = (tid >= off) ? buf[tid - off] : 0;
            __syncthreads();
            buf[tid] += t;
            __syncthreads();
        }
        if (base + tid < NN) g_rptr[base + tid] = buf[tid] - v + carry;
        __syncthreads();
        if (tid == 0) carry += buf[1023];
        __syncthreads();
    }
    if (tid == 0) g_rptr[NN] = carry;
}

__global__ void k_fill() {
    int i = blockIdx.x * blockDim.x + threadIdx.x;
    if (i >= NE) return;
    int d = g_dst[i];
    int pos = g_rptr[d] + atomicAdd(&g_tmp[d], 1);
    g_csr[pos] = g_src[i];
}

// ---------------- split-pair writer (device helper) ----------------
__device__ __forceinline__ void write_split_pair(
    __nv_bfloat16* __restrict__ hs, int m, int j /*even*/, float v0, float v1) {
    __nv_bfloat16 h0 = __float2bfloat16(v0), h1 = __float2bfloat16(v1);
    __nv_bfloat16 l0 = __float2bfloat16(v0 - __bfloat162float(h0));
    __nv_bfloat16 l1 = __float2bfloat16(v1 - __bfloat162float(h1));
    uint32_t hi2 = ((uint32_t)*(uint16_t*)&h1 << 16) | *(uint16_t*)&h0;
    uint32_t lo2 = ((uint32_t)*(uint16_t*)&l1 << 16) | *(uint16_t*)&l0;
    int c = j >> 3, ksl = c >> 1, half = c & 1, off = j & 7;
    int swz = (half ^ ((m >> 2) & 1)) << 3;
    *(uint32_t*)(hs + ((size_t)(ksl)      * MPAD + m) * HW16 + swz + off) = hi2;
    *(uint32_t*)(hs + ((size_t)(13 + ksl) * MPAD + m) * HW16 + swz + off) = lo2;
    *(uint32_t*)(hs + ((size_t)(26 + ksl) * MPAD + m) * HW16 + swz + off) = hi2;
}

// ---------------- CSR gather-sum of h, fused bf16 split output --------------
__global__ void k_agg() {
    int idx = blockIdx.x * blockDim.x + threadIdx.x;
    if (idx >= NN * 50) return;
    int n = idx / 50, c = idx - n * 50;
    int e0 = g_rptr[n], e1 = g_rptr[n + 1];
    float ax = 0.f, ay = 0.f, az = 0.f, aw = 0.f;
    for (int e = e0; e < e1; e++) {
        int s = g_csr[e];
        const float4 v = *(const float4*)&g_h[(size_t)s * HID + c * 4];
        ax += v.x; ay += v.y; az += v.z; aw += v.w;
    }
    int j = c * 4;
    write_split_pair(g_as, n, j,     ax, ay);
    write_split_pair(g_as, n, j + 2, az, aw);
}

// ---------------- merged BN param prep ----------------
__global__ void k_bnprep_all(
    const float* g1, const float* b1, const float* m1, const float* v1,
    const float* g2, const float* b2, const float* m2, const float* v2,
    const float* gf, const float* bf, const float* mf, const float* vf) {
    int j = threadIdx.x;
    if (j >= 3 * HID) return;
    int which = j / HID, jj = j - which * HID;
    const float *g, *b, *m, *v;
    if (which == 0)      { g = g1; b = b1; m = m1; v = v1; }
    else if (which == 1) { g = g2; b = b2; m = m2; v = v2; }
    else                 { g = gf; b = bf; m = mf; v = vf; }
    float s = g[jj] * rsqrtf(v[jj] + 1e-5f);
    g_scale[j] = s;
    g_shift[j] = b[jj] - m[jj] * s;
}

// ---------------- bf16 split of activations (coalesced, swizzled) -----------
__global__ void k_splitA(const float* __restrict__ in, __nv_bfloat16* __restrict__ out,
                         int K) {
    int idx = blockIdx.x * blockDim.x + threadIdx.x;
    if (idx >= NSTEP * NN * 2) return;
    int ks   = idx / (NN * 2);
    int rem  = idx - ks * (NN * 2);
    int m    = rem >> 1;
    int half = rem & 1;
    int s  = ks / 13;
    int c  = (ks - s * 13) * 2 + half;
    int k0 = c * 8;
    const float* src = in + (size_t)m * K + k0;
    __nv_bfloat16 o[8];
#pragma unroll
    for (int i = 0; i < 8; i++) {
        float v = (k0 + i < K) ? src[i] : 0.f;
        __nv_bfloat16 hi = __float2bfloat16(v);
        o[i] = (s == 1) ? __float2bfloat16(v - __bfloat162float(hi)) : hi;
    }
    int swz = half ^ ((m >> 2) & 1);
    *(uint4*)(out + ((size_t)ks * MPAD + m) * HW16 + swz * 8) = *(const uint4*)o;
}

// ---------------- bf16 split of weights (swizzled) ----------------
__global__ void k_splitB(const float* __restrict__ W, __nv_bfloat16* __restrict__ out,
                         int N, int Npad, int K, int trans) {
    int idx = blockIdx.x * blockDim.x + threadIdx.x;
    if (idx >= NSTEP * Npad * 2) return;
    int ks   = idx / (Npad * 2);
    int rem  = idx - ks * (Npad * 2);
    int n    = rem >> 1;
    int half = rem & 1;
    int s  = ks / 13;
    int c  = (ks - s * 13) * 2 + half;
    int k0 = c * 8;
    __nv_bfloat16 o[8];
#pragma unroll
    for (int i = 0; i < 8; i++) {
        int k = k0 + i;
        float v = 0.f;
        if (n < N && k < K) v = trans ? W[(size_t)n * K + k] : W[(size_t)k * N + n];
        __nv_bfloat16 hi = __float2bfloat16(v);
        o[i] = (s == 2) ? __float2bfloat16(v - __bfloat162float(hi)) : hi;
    }
    int swz = half ^ ((n >> 2) & 1);
    *(uint4*)(out + ((size_t)ks * Npad + n) * HW16 + swz * 8) = *(const uint4*)o;
}

// ---------------- tensor GEMM A: 128x256 tile, 512 thr ----------------------
#define STAGES       6
#define STAGE_A_HW   (128 * HW16)
#define STAGE_B_HW   (256 * HW16)
#define STAGE_HW     (STAGE_A_HW + STAGE_B_HW)
#define STAGE_BYTES  (STAGE_HW * 2)          // 12288
#define A_BYTES      (STAGE_A_HW * 2)
#define B_BYTES      (STAGE_B_HW * 2)
#define SMEM_DYN     (STAGES * STAGE_BYTES + 64)

__global__ void __launch_bounds__(512, 1)
k_tgemm(const __nv_bfloat16* __restrict__ A, const __nv_bfloat16* __restrict__ B,
        float* __restrict__ C, int M, int N, int NPADB,
        const float* __restrict__ bias,
        const float* __restrict__ scale, const float* __restrict__ shift,
        int relu, __nv_bfloat16* __restrict__ hs_out) {
    extern __shared__ __align__(128) __nv_bfloat16 dsm[];

    const int tid  = threadIdx.x;
    const int warp = tid >> 5, lane = tid & 31;
    const int wm = warp & 3, wn = warp >> 2;       // 4 x 4
    const int m0 = blockIdx.y * 128;
    const int n0 = blockIdx.x * 256;

    const uint32_t smem_base = (uint32_t)__cvta_generic_to_shared(dsm);
    const uint32_t mbar_base = smem_base + STAGES * STAGE_BYTES;

    if (tid == 0) {
        for (int s = 0; s < STAGES; s++)
            asm volatile("mbarrier.init.shared.b64 [%0], 1;" :: "r"(mbar_base + s * 8) : "memory");
        asm volatile("fence.proxy.async.shared::cta;" ::: "memory");
    }
    __syncthreads();

    float acc[2][8][4];
#pragma unroll
    for (int mi = 0; mi < 2; mi++)
#pragma unroll
        for (int ni = 0; ni < 8; ni++)
#pragma unroll
            for (int j = 0; j < 4; j++) acc[mi][ni][j] = 0.f;

#define ISSUE(kf)                                                                \
    do {                                                                         \
        int slot_ = (kf) % STAGES;                                               \
        uint32_t mb_ = mbar_base + slot_ * 8;                                    \
        asm volatile("mbarrier.arrive.expect_tx.shared.b64 _, [%0], %1;"         \
                     :: "r"(mb_), "r"((uint32_t)STAGE_BYTES) : "memory");        \
        uint32_t da_ = smem_base + slot_ * STAGE_BYTES;                          \
        const __nv_bfloat16* sa_ = A + ((size_t)(kf) * MPAD + m0) * HW16;        \
        asm volatile("cp.async.bulk.shared::cta.global.mbarrier::complete_tx::bytes " \
                     "[%0], [%1], %2, [%3];"                                     \
                     :: "r"(da_), "l"(sa_), "r"((uint32_t)A_BYTES), "r"(mb_)     \
                     : "memory");                                                \
        uint32_t db_ = da_ + A_BYTES;                                            \
        const __nv_bfloat16* sb_ = B + ((size_t)(kf) * NPADB + n0) * HW16;       \
        asm volatile("cp.async.bulk.shared::cta.global.mbarrier::complete_tx::bytes " \
                     "[%0], [%1], %2, [%3];"                                     \
                     :: "r"(db_), "l"(sb_), "r"((uint32_t)B_BYTES), "r"(mb_)     \
                     : "memory");                                                \
    } while (0)

    if (tid == 0)
        for (int kf = 0; kf < STAGES - 1 && kf < NSTEP; kf++) ISSUE(kf);

    const int lr = lane & 15;
    const int ch = lane >> 4;
    const int xa = (lane >> 2) & 1;
    const int bn = lane >> 2;
    const int xb = (lane >> 4) & 1;
    const int bk = (lane & 3) * 2;

    for (int ks = 0; ks < NSTEP; ks++) {
        __syncthreads();
        if (tid == 0) {
            int kf = ks + STAGES - 1;
            if (kf < NSTEP) ISSUE(kf);
        }
        const int slot = ks % STAGES;
        const uint32_t mb = mbar_base + slot * 8;
        const uint32_t parity = (uint32_t)((ks / STAGES) & 1);
        {
            uint32_t done = 0;
            while (!done) {
                asm volatile(
                    "{\n\t.reg .pred p;\n\t"
                    "mbarrier.try_wait.parity.acquire.cta.shared::cta.b64 p, [%1], %2;\n\t"
                    "selp.b32 %0, 1, 0, p;\n\t}"
                    : "=r"(done) : "r"(mb), "r"(parity) : "memory");
            }
        }

        const uint32_t aBase = smem_base + slot * STAGE_BYTES;
        const __nv_bfloat16* sBp = dsm + slot * STAGE_HW + STAGE_A_HW;

        uint32_t a[2][4];
        uint32_t b[8][2];
#pragma unroll
        for (int mi = 0; mi < 2; mi++) {
            int row = wm * 32 + mi * 16 + lr;
            uint32_t addr = aBase + (row * HW16 + ((ch ^ xa) << 3)) * 2;
            asm volatile("ldmatrix.sync.aligned.m8n8.x4.shared.b16 {%0,%1,%2,%3}, [%4];"
                         : "=r"(a[mi][0]), "=r"(a[mi][1]), "=r"(a[mi][2]), "=r"(a[mi][3])
                         : "r"(addr));
        }
#pragma unroll
        for (int ni = 0; ni < 8; ni++) {
            int row = wn * 64 + ni * 8 + bn;
            b[ni][0] = *(const uint32_t*)(sBp + row * HW16 + (xb << 3) + bk);
            b[ni][1] = *(const uint32_t*)(sBp + row * HW16 + ((1 ^ xb) << 3) + bk);
        }
#pragma unroll
        for (int mi = 0; mi < 2; mi++)
#pragma unroll
            for (int ni = 0; ni < 8; ni++) {
                asm volatile(
                    "mma.sync.aligned.m16n8k16.row.col.f32.bf16.bf16.f32 "
                    "{%0,%1,%2,%3}, {%4,%5,%6,%7}, {%8,%9}, {%0,%1,%2,%3};"
                    : "+f"(acc[mi][ni][0]), "+f"(acc[mi][ni][1]),
                      "+f"(acc[mi][ni][2]), "+f"(acc[mi][ni][3])
                    : "r"(a[mi][0]), "r"(a[mi][1]), "r"(a[mi][2]), "r"(a[mi][3]),
                      "r"(b[ni][0]), "r"(b[ni][1]));
            }
    }
#undef ISSUE

    const int r = lane >> 2;
    const int c = (lane & 3) * 2;
#pragma unroll
    for (int mi = 0; mi < 2; mi++) {
#pragma unroll
        for (int ni = 0; ni < 8; ni++) {
            int n = n0 + wn * 64 + ni * 8 + c;
            if (n >= N) continue;
            float bia0 = 0.f, bia1 = 0.f, sc0 = 1.f, sc1 = 1.f, sh0 = 0.f, sh1 = 0.f;
            bool n1ok = (n + 1 < N);
            if (bias)  { bia0 = bias[n]; if (n1ok) bia1 = bias[n + 1]; }
            if (scale) { sc0 = scale[n]; sh0 = shift[n];
                         if (n1ok) { sc1 = scale[n + 1]; sh1 = shift[n + 1]; } }
#pragma unroll
            for (int half = 0; half < 2; half++) {
                int m = m0 + wm * 32 + mi * 16 + half * 8 + r;
                if (m >= M) continue;
                float v0 = acc[mi][ni][half * 2 + 0] + bia0;
                float v1 = acc[mi][ni][half * 2 + 1] + bia1;
                if (scale) { v0 = v0 * sc0 + sh0; v1 = v1 * sc1 + sh1; }
                if (relu)  { v0 = fmaxf(v0, 0.f); v1 = fmaxf(v1, 0.f); }
                float* p = C + (size_t)m * N + n;
                p[0] = v0;
                if (n1ok) p[1] = v1;
                if (hs_out && n1ok) write_split_pair(hs_out, m, n, v0, v1);
            }
        }
    }
}

// ---------------- tensor GEMM B: 64 x 640 tile, fused GRU / tail ------------
// mode 1: C[m,600] = A@B^T + bias
// mode 2: gh = A@B^T + bias, fused GRU -> h (+ optional hs split)
// mode 3: gh = A@B^T + bias, fused GRU -> bn2+relu -> pool atomics (no h write)
#define T64S        4
#define T64_A_B     (64 * 32)                 // 2048
#define T64_B_B     (640 * 32)                // 20480
#define T64_ST_B    (T64_A_B + T64_B_B)       // 22528
#define T64_EPI_STR 608
#define T64_EPI_B   (64 * T64_EPI_STR * 4)    // 155648
#define T64_SMEM    (T64_EPI_B + 64)

__global__ void __launch_bounds__(512, 1)
k_tg64(const __nv_bfloat16* __restrict__ A, const __nv_bfloat16* __restrict__ B,
       int NPADB, const float* __restrict__ bias,
       float* __restrict__ C,
       const float* __restrict__ gi_in, float* __restrict__ h_io,
       __nv_bfloat16* __restrict__ hs_out, int mode, int do_split) {
    extern __shared__ __align__(128) __nv_bfloat16 dsm[];

    const int tid  = threadIdx.x;
    const int warp = tid >> 5, lane = tid & 31;
    const int wm = warp & 1, wn = warp >> 1;       // 2 x 8
    const int m0 = blockIdx.y * 64;

    const uint32_t smem_base = (uint32_t)__cvta_generic_to_shared(dsm);
    const uint32_t mbar_base = smem_base + T64_EPI_B;

    if (tid == 0) {
        for (int s = 0; s < T64S; s++)
            asm volatile("mbarrier.init.shared.b64 [%0], 1;" :: "r"(mbar_base + s * 8) : "memory");
        asm volatile("fence.proxy.async.shared::cta;" ::: "memory");
    }
    __syncthreads();

    float acc[2][10][4];
#pragma unroll
    for (int mi = 0; mi < 2; mi++)
#pragma unroll
        for (int ni = 0; ni < 10; ni++)
#pragma unroll
            for (int j = 0; j < 4; j++) acc[mi][ni][j] = 0.f;

#define ISSUE64(kf)                                                              \
    do {                                                                         \
        int slot_ = (kf) % T64S;                                                 \
        uint32_t mb_ = mbar_base + slot_ * 8;                                    \
        asm volatile("mbarrier.arrive.expect_tx.shared.b64 _, [%0], %1;"         \
                     :: "r"(mb_), "r"((uint32_t)T64_ST_B) : "memory");           \
        uint32_t da_ = smem_base + slot_ * T64_ST_B;                             \
        const __nv_bfloat16* sa_ = A + ((size_t)(kf) * MPAD + m0) * HW16;        \
        asm volatile("cp.async.bulk.shared::cta.global.mbarrier::complete_tx::bytes " \
                     "[%0], [%1], %2, [%3];"                                     \
                     :: "r"(da_), "l"(sa_), "r"((uint32_t)T64_A_B), "r"(mb_)     \
                     : "memory");                                                \
        uint32_t db_ = da_ + T64_A_B;                                            \
        const __nv_bfloat16* sb_ = B + (size_t)(kf) * NPADB * HW16;              \
        asm volatile("cp.async.bulk.shared::cta.global.mbarrier::complete_tx::bytes " \
                     "[%0], [%1], %2, [%3];"                                     \
                     :: "r"(db_), "l"(sb_), "r"((uint32_t)T64_B_B), "r"(mb_)     \
                     : "memory");                                                \
    } while (0)

    if (tid == 0)
        for (int kf = 0; kf < T64S - 1 && kf < NSTEP; kf++) ISSUE64(kf);

    const int lr = lane & 15;
    const int ch = lane >> 4;
    const int xa = (lane >> 2) & 1;
    const int bn = lane >> 2;
    const int xb = (lane >> 4) & 1;
    const int bk = (lane & 3) * 2;

    for (int ks = 0; ks < NSTEP; ks++) {
        __syncthreads();
        if (tid == 0) {
            int kf = ks + T64S - 1;
            if (kf < NSTEP) ISSUE64(kf);
        }
        const int slot = ks % T64S;
        const uint32_t mb = mbar_base + slot * 8;
        const uint32_t parity = (uint32_t)((ks / T64S) & 1);
        {
            uint32_t done = 0;
            while (!done) {
                asm volatile(
                    "{\n\t.reg .pred p;\n\t"
                    "mbarrier.try_wait.parity.acquire.cta.shared::cta.b64 p, [%1], %2;\n\t"
                    "selp.b32 %0, 1, 0, p;\n\t}"
                    : "=r"(done) : "r"(mb), "r"(parity) : "memory");
            }
        }

        const uint32_t aBase = smem_base + slot * T64_ST_B;
        const __nv_bfloat16* sBp = dsm + slot * (T64_ST_B / 2) + (T64_A_B / 2);

        uint32_t a[2][4];
        uint32_t b[10][2];
#pragma unroll
        for (int mi = 0; mi < 2; mi++) {
            int row = wm * 32 + mi * 16 + lr;
            uint32_t addr = aBase + (row * HW16 + ((ch ^ xa) << 3)) * 2;
            asm volatile("ldmatrix.sync.aligned.m8n8.x4.shared.b16 {%0,%1,%2,%3}, [%4];"
                         : "=r"(a[mi][0]), "=r"(a[mi][1]), "=r"(a[mi][2]), "=r"(a[mi][3])
                         : "r"(addr));
        }
#pragma unroll
        for (int ni = 0; ni < 10; ni++) {
            int row = wn * 80 + ni * 8 + bn;
            b[ni][0] = *(const uint32_t*)(sBp + row * HW16 + (xb << 3) + bk);
            b[ni][1] = *(const uint32_t*)(sBp + row * HW16 + ((1 ^ xb) << 3) + bk);
        }
#pragma unroll
        for (int mi = 0; mi < 2; mi++)
#pragma unroll
            for (int ni = 0; ni < 10; ni++) {
                asm volatile(
                    "mma.sync.aligned.m16n8k16.row.col.f32.bf16.bf16.f32 "
                    "{%0,%1,%2,%3}, {%4,%5,%6,%7}, {%8,%9}, {%0,%1,%2,%3};"
                    : "+f"(acc[mi][ni][0]), "+f"(acc[mi][ni][1]),
                      "+f"(acc[mi][ni][2]), "+f"(acc[mi][ni][3])
                    : "r"(a[mi][0]), "r"(a[mi][1]), "r"(a[mi][2]), "r"(a[mi][3]),
                      "r"(b[ni][0]), "r"(b[ni][1]));
            }
    }
#undef ISSUE64

    const int r = lane >> 2;
    const int c = (lane & 3) * 2;

    if (mode == 1) {
#pragma unroll
        for (int mi = 0; mi < 2; mi++)
#pragma unroll
            for (int ni = 0; ni < 10; ni++) {
                int n = wn * 80 + ni * 8 + c;
                if (n >= H3) continue;
                float bia0 = bias ? bias[n] : 0.f;
                float bia1 = bias ? bias[n + 1] : 0.f;
#pragma unroll
                for (int half = 0; half < 2; half++) {
                    int m = m0 + wm * 32 + mi * 16 + half * 8 + r;
                    if (m >= NN) continue;
                    float* p = C + (size_t)m * H3 + n;
                    p[0] = acc[mi][ni][half * 2 + 0] + bia0;
                    p[1] = acc[mi][ni][half * 2 + 1] + bia1;
                }
            }
        return;
    }

    // modes 2/3: stage gh = acc + bhh to smem, then fused GRU (+tail)
    __syncthreads();
    float* sg = (float*)dsm;
#pragma unroll
    for (int mi = 0; mi < 2; mi++)
#pragma unroll
        for (int ni = 0; ni < 10; ni++) {
            int n = wn * 80 + ni * 8 + c;
            if (n >= H3) continue;
            float bia0 = bias[n], bia1 = bias[n + 1];
#pragma unroll
            for (int half = 0; half < 2; half++) {
                int row = wm * 32 + mi * 16 + half * 8 + r;
                sg[row * T64_EPI_STR + n]     = acc[mi][ni][half * 2 + 0] + bia0;
                sg[row * T64_EPI_STR + n + 1] = acc[mi][ni][half * 2 + 1] + bia1;
            }
        }
    __syncthreads();

    for (int task = tid; task < 64 * 50; task += 512) {
        int row = task / 50;
        int m = m0 + row;
        if (m >= NN) continue;
        int jc = task - row * 50;
        int j = jc * 4;
        const float* gi = gi_in + (size_t)m * H3;
        float4 ir4 = *(const float4*)(gi + j);
        float4 iz4 = *(const float4*)(gi + j + 200);
        float4 in4 = *(const float4*)(gi + j + 400);
        const float* sgr = sg + row * T64_EPI_STR;
        float4 hr4 = *(const float4*)(sgr + j);
        float4 hz4 = *(const float4*)(sgr + j + 200);
        float4 hn4 = *(const float4*)(sgr + j + 400);
        float* hp = h_io + (size_t)m * HID + j;
        float4 h4 = *(float4*)hp;

        float hv[4];
        const float ir[4] = {ir4.x, ir4.y, ir4.z, ir4.w};
        const float iz[4] = {iz4.x, iz4.y, iz4.z, iz4.w};
        const float in_[4] = {in4.x, in4.y, in4.z, in4.w};
        const float hr[4] = {hr4.x, hr4.y, hr4.z, hr4.w};
        const float hz[4] = {hz4.x, hz4.y, hz4.z, hz4.w};
        const float hn[4] = {hn4.x, hn4.y, hn4.z, hn4.w};
        const float ho[4] = {h4.x, h4.y, h4.z, h4.w};
#pragma unroll
        for (int i = 0; i < 4; i++) {
            float rr = 1.f / (1.f + expf(-(ir[i] + hr[i])));
            float zz = 1.f / (1.f + expf(-(iz[i] + hz[i])));
            float nn = tanhf(in_[i] + rr * hn[i]);
            hv[i] = (1.f - zz) * nn + zz * ho[i];
        }

        if (mode == 2) {
            *(float4*)hp = make_float4(hv[0], hv[1], hv[2], hv[3]);
            if (do_split) {
                write_split_pair(hs_out, m, j,     hv[0], hv[1]);
                write_split_pair(hs_out, m, j + 2, hv[2], hv[3]);
            }
        } else {
            int b = g_batch[m];
            float* mp = &g_pool[b * 400 + j];
            int*   xp = (int*)&g_pool[b * 400 + 200 + j];
#pragma unroll
            for (int i = 0; i < 4; i++) {
                int jj = j + i;
                float v = fmaxf(hv[i] * g_scale[HID + jj] + g_shift[HID + jj], 0.f);
                atomicAdd(mp + i, v);
                atomicMax(xp + i, __float_as_int(v));
            }
            if (jc == 0) atomicAdd(&g_cnt[b], 1.0f);
        }
    }
}

// ---------------- small SIMT GEMM (fc1/fc2/Wc precompute) -------------------
#define BM 64
#define BN 64
#define BK 16
__global__ void k_gemm(const float* __restrict__ A, const float* __restrict__ B,
                       float* __restrict__ C, int M, int N, int K, int transB,
                       const float* __restrict__ bias,
                       const float* __restrict__ scale,
                       const float* __restrict__ shift, int relu) {
    __shared__ float As[BK][BM];
    __shared__ float Bs[BK][BN + 4];
    const int m0 = blockIdx.y * BM;
    const int n0 = blockIdx.x * BN;
    const int tid = threadIdx.x;
    const int tm = tid >> 4;
    const int tn = tid & 15;
    float acc[4][4];
#pragma unroll
    for (int i = 0; i < 4; i++)
#pragma unroll
        for (int j = 0; j < 4; j++) acc[i][j] = 0.f;

    for (int k0 = 0; k0 < K; k0 += BK) {
        {
            int ar = tid >> 2;
            int ac = (tid & 3) * 4;
            int m = m0 + ar;
#pragma unroll
            for (int i = 0; i < 4; i++) {
                int k = k0 + ac + i;
                As[ac + i][ar] = (m < M && k < K) ? A[(size_t)m * K + k] : 0.f;
            }
        }
        if (!transB) {
            int br = tid >> 4;
            int bc = (tid & 15) * 4;
            int k = k0 + br;
#pragma unroll
            for (int i = 0; i < 4; i++) {
                int n = n0 + bc + i;
                Bs[br][bc + i] = (k < K && n < N) ? B[(size_t)k * N + n] : 0.f;
            }
        } else {
            int br = tid >> 2;
            int bc = (tid & 3) * 4;
            int n = n0 + br;
#pragma unroll
            for (int i = 0; i < 4; i++) {
                int k = k0 + bc + i;
                Bs[bc + i][br] = (n < N && k < K) ? B[(size_t)n * K + k] : 0.f;
            }
        }
        __syncthreads();
#pragma unroll
        for (int k = 0; k < BK; k++) {
            float a[4], b[4];
#pragma unroll
            for (int i = 0; i < 4; i++) a[i] = As[k][tm * 4 + i];
#pragma unroll
            for (int j = 0; j < 4; j++) b[j] = Bs[k][tn * 4 + j];
#pragma unroll
            for (int i = 0; i < 4; i++)
#pragma unroll
                for (int j = 0; j < 4; j++) acc[i][j] += a[i] * b[j];
        }
        __syncthreads();
    }
#pragma unroll
    for (int i = 0; i < 4; i++) {
        int m = m0 + tm * 4 + i;
        if (m >= M) continue;
#pragma unroll
        for (int j = 0; j < 4; j++) {
            int n = n0 + tn * 4 + j;
            if (n >= N) continue;
            float v = acc[i][j];
            if (bias)  v += bias[n];
            if (scale) v = v * scale[n] + shift[n];
            if (relu)  v = fmaxf(v, 0.f);
            C[(size_t)m * N + n] = v;
        }
    }
}

// ---------------- zero helper ----------------
__global__ void k_zero(float* __restrict__ p, int n) {
    int i = blockIdx.x * blockDim.x + threadIdx.x;
    if (i < n) p[i] = 0.f;
}

__global__ void k_pool_fin() {
    int idx = blockIdx.x * blockDim.x + threadIdx.x;
    if (idx >= NG * HID) return;
    int g = idx / HID;
    int j = idx - g * HID;
    g_pool[g * 400 + j] *= 1.f / fmaxf(g_cnt[g], 1.f);
}

// ---------------- host launch ----------------
static inline int cdiv(int a, int b) { return (a + b - 1) / b; }

extern "C" void kernel_launch(void* const* d_in, const int* in_sizes, int n_in,
                              void* d_out, int out_size) {
    static bool init = false;
    static float *p_h, *p_gi, *p_pool, *p_cnt, *p_fc1, *p_scale, *p_shift;
    static int *p_deg, *p_tmp;
    static __nv_bfloat16 *p_xs, *p_hs, *p_as, *p_Bproj, *p_BWc, *p_Bwhh;
    if (!init) {
        cudaGetSymbolAddress((void**)&p_h, g_h);
        cudaGetSymbolAddress((void**)&p_gi, g_gi);
        cudaGetSymbolAddress((void**)&p_pool, g_pool);
        cudaGetSymbolAddress((void**)&p_cnt, g_cnt);
        cudaGetSymbolAddress((void**)&p_fc1, g_fc1);
        cudaGetSymbolAddress((void**)&p_scale, g_scale);
        cudaGetSymbolAddress((void**)&p_shift, g_shift);
        cudaGetSymbolAddress((void**)&p_deg, g_deg);
        cudaGetSymbolAddress((void**)&p_tmp, g_tmp);
        cudaGetSymbolAddress((void**)&p_xs, g_xs);
        cudaGetSymbolAddress((void**)&p_hs, g_hs);
        cudaGetSymbolAddress((void**)&p_as, g_as);
        cudaGetSymbolAddress((void**)&p_Bproj, g_Bproj);
        cudaGetSymbolAddress((void**)&p_BWc, g_BWc);
        cudaGetSymbolAddress((void**)&p_Bwhh, g_Bwhh);
        cudaFuncSetAttribute(k_tgemm, cudaFuncAttributeMaxDynamicSharedMemorySize, SMEM_DYN);
        cudaFuncSetAttribute(k_tg64, cudaFuncAttributeMaxDynamicSharedMemorySize, T64_SMEM);
        init = true;
    }

    const float *x, *projW, *projb;
    const void  *edge, *batch;
    const float *bn1g, *bn1b, *bn1m, *bn1v;
    const float *bn2g, *bn2b, *bn2m, *bn2v;
    const float *bnfg, *bnfb, *bnfm, *bnfv;
    const float *ggcW, *wih, *whh, *bih, *bhh, *fc1W, *fc1b, *fc2W, *fc2b;

    x     = (const float*)d_in[0];
    edge  = d_in[1];
    batch = d_in[2];
    projW = (const float*)d_in[3];
    projb = (const float*)d_in[4];
    bn1g = (const float*)d_in[5]; bn1b = (const float*)d_in[6];
    bn1m = (const float*)d_in[7]; bn1v = (const float*)d_in[8];

    if (in_sizes[9] == 120000) {
        ggcW = (const float*)d_in[9];
        wih  = (const float*)d_in[10]; whh = (const float*)d_in[11];
        bih  = (const float*)d_in[12]; bhh = (const float*)d_in[13];
        bn2g = (const float*)d_in[14]; bn2b = (const float*)d_in[15];
        bn2m = (const float*)d_in[16]; bn2v = (const float*)d_in[17];
        fc1W = (const float*)d_in[18]; fc1b = (const float*)d_in[19];
        bnfg = (const float*)d_in[20]; bnfb = (const float*)d_in[21];
        bnfm = (const float*)d_in[22]; bnfv = (const float*)d_in[23];
        fc2W = (const float*)d_in[24]; fc2b = (const float*)d_in[25];
    } else {
        bn2g = (const float*)d_in[9];  bn2b = (const float*)d_in[10];
        bn2m = (const float*)d_in[11]; bn2v = (const float*)d_in[12];
        bnfg = (const float*)d_in[13]; bnfb = (const float*)d_in[14];
        bnfm = (const float*)d_in[15]; bnfv = (const float*)d_in[16];
        ggcW = (const float*)d_in[17];
        wih  = (const float*)d_in[18]; whh = (const float*)d_in[19];
        bih  = (const float*)d_in[20]; bhh = (const float*)d_in[21];
        fc1W = (const float*)d_in[22]; fc1b = (const float*)d_in[23];
        fc2W = (const float*)d_in[24]; fc2b = (const float*)d_in[25];
    }

    const int T = 256;
    const int MT  = cdiv(NN, 128);   // 782
    const int MT64 = cdiv(NN, 64);   // 1563

    k_splitB<<<cdiv(NSTEP * 256 * 2, T), T>>>(projW, p_Bproj, HID, 256, INDIM, 1);
    k_bnprep_all<<<1, 640>>>(bn1g, bn1b, bn1m, bn1v,
                             bn2g, bn2b, bn2m, bn2v,
                             bnfg, bnfb, bnfm, bnfv);
    k_splitA<<<cdiv(NSTEP * NN * 2, T), T>>>(x, p_xs, INDIM);
    // h = relu(bn1(x @ projW^T + projb)); epilogue also writes hs split
    k_tgemm<<<dim3(1, MT), 512, SMEM_DYN>>>(p_xs, p_Bproj, p_h, NN, HID, 256,
                                            projb, p_scale, p_shift, 1, p_hs);

    // Wc_i = ggcW_i @ wih^T folded weights: Wc[n][k] = sum_j ggcW_i[k][j]*wih[n][j]
    // fp32 scratch = head of g_gi (unused until first tg64 mode1)
    for (int i = 0; i < 3; i++) {
        k_gemm<<<dim3(cdiv(HID, BN), cdiv(H3, BM)), T>>>(
            wih, ggcW + (size_t)i * HID * HID, p_gi, H3, HID, HID, 1,
            nullptr, nullptr, nullptr, 0);
        k_splitB<<<cdiv(NSTEP * 640 * 2, T), T>>>(p_gi, p_BWc + (size_t)i * NSTEP * 640 * HW16,
                                                  H3, 640, HID, 1);
    }

    // edge preprocessing + CSR build (once)
    k_detect<<<1, 32>>>((const int*)edge, (const int*)batch);
    k_conv_edges<<<cdiv(2 * NE, T), T>>>(edge);
    k_conv_batch<<<cdiv(NN, T), T>>>(batch);
    k_zero<<<cdiv(NN, T), T>>>((float*)p_deg, NN);
    k_hist<<<cdiv(NE, T), T>>>();
    k_scan<<<1, 1024>>>();
    k_zero<<<cdiv(NN, T), T>>>((float*)p_tmp, NN);
    k_fill<<<cdiv(NE, T), T>>>();

    k_splitB<<<cdiv(NSTEP * 768 * 2, T), T>>>(whh, p_Bwhh, H3, 768, HID, 1);

    // pool buffers zeroed before the loop (mode-3 tail writes them)
    k_zero<<<cdiv(NG * 400, T), T>>>(p_pool, NG * 400);
    k_zero<<<cdiv(NG, T), T>>>(p_cnt, NG);

    for (int it = 0; it < 3; it++) {
        // aggH = CSR gather-sum of h; writes bf16 split (g_as) directly
        k_agg<<<cdiv(NN * 50, T), T>>>();
        // gi = aggH @ Wc_it^T + bih   (ggc GEMM folded into the weight)
        k_tg64<<<dim3(1, MT64), 512, T64_SMEM>>>(
            p_as, p_BWc + (size_t)it * NSTEP * 640 * HW16, 640, bih,
            p_gi, nullptr, nullptr, nullptr, 1, 0);
        // gh = h @ whh^T + bhh, fused GRU; last iter also fuses bn2+relu+pool
        int mode = (it < 2) ? 2 : 3;
        k_tg64<<<dim3(1, MT64), 512, T64_SMEM>>>(p_hs, p_Bwhh, 768, bhh,
                                                 nullptr, p_gi, p_h, p_hs, mode,
                                                 it < 2 ? 1 : 0);
    }

    k_pool_fin<<<cdiv(NG * HID, T), T>>>();

    {
        dim3 grid(cdiv(HID, BN), cdiv(NG, BM));
        k_gemm<<<grid, T>>>(p_pool, fc1W, p_fc1, NG, HID, 2 * HID, 1,
                            fc1b, p_scale + 2 * HID, p_shift + 2 * HID, 1);
    }
    {
        dim3 grid(cdiv(2, BN), cdiv(NG, BM));
        k_gemm<<<grid, T>>>(p_fc1, fc2W, (float*)d_out, NG, 2, HID, 1,
                            fc2b, nullptr, nullptr, 0);
    }
}

// round 16
// speedup vs baseline: 2.2064x; 1.0401x over previous
#include <cuda_runtime.h>
#include <cuda_bf16.h>
#include <stdint.h>
#include <math.h>

#define NN    100000
#define NE    1600000
#define NG    512
#define HID   200
#define H3    600
#define INDIM 205

#define KP    208
#define K3    624
#define NSTEP 39        // K3/16
#define MPAD  100096    // >= 1563*64
#define HW16  16        // halfwords per row per k-step (packed, swizzled)

// ---------------- scratch ----------------
__device__ float g_h  [(size_t)NN * HID];
__device__ float g_gi [(size_t)NN * H3];   // head also used as Wc fp32 scratch pre-loop
__device__ float g_pool[NG * 2 * HID];
__device__ float g_cnt [NG];
__device__ float g_fc1 [NG * HID];
__device__ float g_scale[3 * HID];
__device__ float g_shift[3 * HID];
__device__ int   g_src[NE];
__device__ int   g_dst[NE];
__device__ int   g_batch[NN];
__device__ int   g_flag_e;
__device__ int   g_flag_b;
// CSR (built once; graph identical across iterations)
__device__ int   g_deg [NN];
__device__ int   g_tmp [NN];
__device__ int   g_rptr[NN + 1];
__device__ int   g_csr [NE];

// packed k-blocked bf16 buffers, swizzle baked into gmem layout:
// element (ks,row,kk) at ((ks*ROWS+row)*16) + ((kk>>3) ^ ((row>>2)&1))*8 + (kk&7)
__device__ __nv_bfloat16 g_xs[(size_t)NSTEP * MPAD * HW16];
__device__ __nv_bfloat16 g_hs[(size_t)NSTEP * MPAD * HW16];
__device__ __nv_bfloat16 g_as[(size_t)NSTEP * MPAD * HW16];
__device__ __nv_bfloat16 g_Bproj[(size_t)NSTEP * 256 * HW16];
__device__ __nv_bfloat16 g_BWc [3][(size_t)NSTEP * 640 * HW16];   // (ggcW_i @ wih^T) split
__device__ __nv_bfloat16 g_Bwhh[(size_t)NSTEP * 768 * HW16];

// ---------------- dtype detection ----------------
__global__ void k_detect(const int* __restrict__ ew, const int* __restrict__ bw) {
    int lane = threadIdx.x;
    int bad_e = 0, bad_b = 0;
    for (int w = 2 * NE - 255 + 2 * lane; w < 2 * NE; w += 64)
        if (ew[w] != 0) bad_e = 1;
    for (int w = NN - 255 + 2 * lane; w < NN; w += 64)
        if (bw[w] != 0) bad_b = 1;
    unsigned me = __ballot_sync(0xFFFFFFFFu, bad_e);
    unsigned mb = __ballot_sync(0xFFFFFFFFu, bad_b);
    if (lane == 0) { g_flag_e = (me == 0); g_flag_b = (mb == 0); }
}

__global__ void k_conv_edges(const void* __restrict__ e) {
    int i = blockIdx.x * blockDim.x + threadIdx.x;
    if (i >= 2 * NE) return;
    int v = g_flag_e ? (int)((const long long*)e)[i] : ((const int*)e)[i];
    if (i < NE) g_src[i] = v; else g_dst[i - NE] = v;
}

__global__ void k_conv_batch(const void* __restrict__ b) {
    int i = blockIdx.x * blockDim.x + threadIdx.x;
    if (i >= NN) return;
    g_batch[i] = g_flag_b ? (int)((const long long*)b)[i] : ((const int*)b)[i];
}

// ---------------- CSR build (once) ----------------
__global__ void k_hist() {
    int i = blockIdx.x * blockDim.x + threadIdx.x;
    if (i < NE) atomicAdd(&g_deg[g_dst[i]], 1);
}

__global__ void k_scan() {   // single block, 1024 threads
    __shared__ int buf[1024];
    __shared__ int carry;
    int tid = threadIdx.x;
    if (tid == 0) carry = 0;
    __syncthreads();
    for (int base = 0; base < NN; base += 1024) {
        int v = (base + tid < NN) ? g_deg[base + tid] : 0;
        buf[tid] = v;
        __syncthreads();
        for (int off = 1; off < 1024; off <<= 1) {
            int t = (tid >= off) ? buf[tid - off] : 0;
            __syncthreads();
            buf[tid] += t;
            __syncthreads();
        }
        if (base + tid < NN) g_rptr[base + tid] = buf[tid] - v + carry;
        __syncthreads();
        if (tid == 0) carry += buf[1023];
        __syncthreads();
    }
    if (tid == 0) g_rptr[NN] = carry;
}

__global__ void k_fill() {
    int i = blockIdx.x * blockDim.x + threadIdx.x;
    if (i >= NE) return;
    int d = g_dst[i];
    int pos = g_rptr[d] + atomicAdd(&g_tmp[d], 1);
    g_csr[pos] = g_src[i];
}

// ---------------- split-pair writer (device helper) ----------------
__device__ __forceinline__ void write_split_pair(
    __nv_bfloat16* __restrict__ hs, int m, int j /*even*/, float v0, float v1) {
    __nv_bfloat16 h0 = __float2bfloat16(v0), h1 = __float2bfloat16(v1);
    __nv_bfloat16 l0 = __float2bfloat16(v0 - __bfloat162float(h0));
    __nv_bfloat16 l1 = __float2bfloat16(v1 - __bfloat162float(h1));
    uint32_t hi2 = ((uint32_t)*(uint16_t*)&h1 << 16) | *(uint16_t*)&h0;
    uint32_t lo2 = ((uint32_t)*(uint16_t*)&l1 << 16) | *(uint16_t*)&l0;
    int c = j >> 3, ksl = c >> 1, half = c & 1, off = j & 7;
    int swz = (half ^ ((m >> 2) & 1)) << 3;
    *(uint32_t*)(hs + ((size_t)(ksl)      * MPAD + m) * HW16 + swz + off) = hi2;
    *(uint32_t*)(hs + ((size_t)(13 + ksl) * MPAD + m) * HW16 + swz + off) = lo2;
    *(uint32_t*)(hs + ((size_t)(26 + ksl) * MPAD + m) * HW16 + swz + off) = hi2;
}

// ---------------- CSR gather-sum of h, fused bf16 split output --------------
__global__ void k_agg() {
    int idx = blockIdx.x * blockDim.x + threadIdx.x;
    if (idx >= NN * 50) return;
    int n = idx / 50, c = idx - n * 50;
    int e0 = g_rptr[n], e1 = g_rptr[n + 1];
    float ax = 0.f, ay = 0.f, az = 0.f, aw = 0.f;
    for (int e = e0; e < e1; e++) {
        int s = g_csr[e];
        const float4 v = *(const float4*)&g_h[(size_t)s * HID + c * 4];
        ax += v.x; ay += v.y; az += v.z; aw += v.w;
    }
    int j = c * 4;
    write_split_pair(g_as, n, j,     ax, ay);
    write_split_pair(g_as, n, j + 2, az, aw);
}

// ---------------- merged BN param prep ----------------
__global__ void k_bnprep_all(
    const float* g1, const float* b1, const float* m1, const float* v1,
    const float* g2, const float* b2, const float* m2, const float* v2,
    const float* gf, const float* bf, const float* mf, const float* vf) {
    int j = threadIdx.x;
    if (j >= 3 * HID) return;
    int which = j / HID, jj = j - which * HID;
    const float *g, *b, *m, *v;
    if (which == 0)      { g = g1; b = b1; m = m1; v = v1; }
    else if (which == 1) { g = g2; b = b2; m = m2; v = v2; }
    else                 { g = gf; b = bf; m = mf; v = vf; }
    float s = g[jj] * rsqrtf(v[jj] + 1e-5f);
    g_scale[j] = s;
    g_shift[j] = b[jj] - m[jj] * s;
}

// ---------------- bf16 split of activations (coalesced, swizzled) -----------
__global__ void k_splitA(const float* __restrict__ in, __nv_bfloat16* __restrict__ out,
                         int K) {
    int idx = blockIdx.x * blockDim.x + threadIdx.x;
    if (idx >= NSTEP * NN * 2) return;
    int ks   = idx / (NN * 2);
    int rem  = idx - ks * (NN * 2);
    int m    = rem >> 1;
    int half = rem & 1;
    int s  = ks / 13;
    int c  = (ks - s * 13) * 2 + half;
    int k0 = c * 8;
    const float* src = in + (size_t)m * K + k0;
    __nv_bfloat16 o[8];
#pragma unroll
    for (int i = 0; i < 8; i++) {
        float v = (k0 + i < K) ? src[i] : 0.f;
        __nv_bfloat16 hi = __float2bfloat16(v);
        o[i] = (s == 1) ? __float2bfloat16(v - __bfloat162float(hi)) : hi;
    }
    int swz = half ^ ((m >> 2) & 1);
    *(uint4*)(out + ((size_t)ks * MPAD + m) * HW16 + swz * 8) = *(const uint4*)o;
}

// ---------------- bf16 split of weights (swizzled) ----------------
__global__ void k_splitB(const float* __restrict__ W, __nv_bfloat16* __restrict__ out,
                         int N, int Npad, int K, int trans) {
    int idx = blockIdx.x * blockDim.x + threadIdx.x;
    if (idx >= NSTEP * Npad * 2) return;
    int ks   = idx / (Npad * 2);
    int rem  = idx - ks * (Npad * 2);
    int n    = rem >> 1;
    int half = rem & 1;
    int s  = ks / 13;
    int c  = (ks - s * 13) * 2 + half;
    int k0 = c * 8;
    __nv_bfloat16 o[8];
#pragma unroll
    for (int i = 0; i < 8; i++) {
        int k = k0 + i;
        float v = 0.f;
        if (n < N && k < K) v = trans ? W[(size_t)n * K + k] : W[(size_t)k * N + n];
        __nv_bfloat16 hi = __float2bfloat16(v);
        o[i] = (s == 2) ? __float2bfloat16(v - __bfloat162float(hi)) : hi;
    }
    int swz = half ^ ((n >> 2) & 1);
    *(uint4*)(out + ((size_t)ks * Npad + n) * HW16 + swz * 8) = *(const uint4*)o;
}

// ---------------- tensor GEMM A: 128x256 tile, 512 thr ----------------------
#define STAGES       6
#define STAGE_A_HW   (128 * HW16)
#define STAGE_B_HW   (256 * HW16)
#define STAGE_HW     (STAGE_A_HW + STAGE_B_HW)
#define STAGE_BYTES  (STAGE_HW * 2)          // 12288
#define A_BYTES      (STAGE_A_HW * 2)
#define B_BYTES      (STAGE_B_HW * 2)
#define SMEM_DYN     (STAGES * STAGE_BYTES + 64)

__global__ void __launch_bounds__(512, 1)
k_tgemm(const __nv_bfloat16* __restrict__ A, const __nv_bfloat16* __restrict__ B,
        float* __restrict__ C, int M, int N, int NPADB,
        const float* __restrict__ bias,
        const float* __restrict__ scale, const float* __restrict__ shift,
        int relu, __nv_bfloat16* __restrict__ hs_out) {
    extern __shared__ __align__(128) __nv_bfloat16 dsm[];

    const int tid  = threadIdx.x;
    const int warp = tid >> 5, lane = tid & 31;
    const int wm = warp & 3, wn = warp >> 2;       // 4 x 4
    const int m0 = blockIdx.y * 128;
    const int n0 = blockIdx.x * 256;

    const uint32_t smem_base = (uint32_t)__cvta_generic_to_shared(dsm);
    const uint32_t mbar_base = smem_base + STAGES * STAGE_BYTES;

    if (tid == 0) {
        for (int s = 0; s < STAGES; s++)
            asm volatile("mbarrier.init.shared.b64 [%0], 1;" :: "r"(mbar_base + s * 8) : "memory");
        asm volatile("fence.proxy.async.shared::cta;" ::: "memory");
    }
    __syncthreads();

    float acc[2][8][4];
#pragma unroll
    for (int mi = 0; mi < 2; mi++)
#pragma unroll
        for (int ni = 0; ni < 8; ni++)
#pragma unroll
            for (int j = 0; j < 4; j++) acc[mi][ni][j] = 0.f;

#define ISSUE(kf)                                                                \
    do {                                                                         \
        int slot_ = (kf) % STAGES;                                               \
        uint32_t mb_ = mbar_base + slot_ * 8;                                    \
        asm volatile("mbarrier.arrive.expect_tx.shared.b64 _, [%0], %1;"         \
                     :: "r"(mb_), "r"((uint32_t)STAGE_BYTES) : "memory");        \
        uint32_t da_ = smem_base + slot_ * STAGE_BYTES;                          \
        const __nv_bfloat16* sa_ = A + ((size_t)(kf) * MPAD + m0) * HW16;        \
        asm volatile("cp.async.bulk.shared::cta.global.mbarrier::complete_tx::bytes " \
                     "[%0], [%1], %2, [%3];"                                     \
                     :: "r"(da_), "l"(sa_), "r"((uint32_t)A_BYTES), "r"(mb_)     \
                     : "memory");                                                \
        uint32_t db_ = da_ + A_BYTES;                                            \
        const __nv_bfloat16* sb_ = B + ((size_t)(kf) * NPADB + n0) * HW16;       \
        asm volatile("cp.async.bulk.shared::cta.global.mbarrier::complete_tx::bytes " \
                     "[%0], [%1], %2, [%3];"                                     \
                     :: "r"(db_), "l"(sb_), "r"((uint32_t)B_BYTES), "r"(mb_)     \
                     : "memory");                                                \
    } while (0)

    if (tid == 0)
        for (int kf = 0; kf < STAGES - 1 && kf < NSTEP; kf++) ISSUE(kf);

    const int lr = lane & 15;
    const int ch = lane >> 4;
    const int xa = (lane >> 2) & 1;
    // B non-trans ldmatrix x2: lanes 0-7 -> logical chunk0 (k0-7), 8-15 -> chunk1
    const int brow   = (lane & 7);
    const int bchunk = ((lane >> 3) & 1) ^ ((lane >> 2) & 1);  // logical ^ bit2(row)

    for (int ks = 0; ks < NSTEP; ks++) {
        __syncthreads();
        if (tid == 0) {
            int kf = ks + STAGES - 1;
            if (kf < NSTEP) ISSUE(kf);
        }
        const int slot = ks % STAGES;
        const uint32_t mb = mbar_base + slot * 8;
        const uint32_t parity = (uint32_t)((ks / STAGES) & 1);
        {
            uint32_t done = 0;
            while (!done) {
                asm volatile(
                    "{\n\t.reg .pred p;\n\t"
                    "mbarrier.try_wait.parity.acquire.cta.shared::cta.b64 p, [%1], %2;\n\t"
                    "selp.b32 %0, 1, 0, p;\n\t}"
                    : "=r"(done) : "r"(mb), "r"(parity) : "memory");
            }
        }

        const uint32_t aBase = smem_base + slot * STAGE_BYTES;
        const uint32_t bBase = aBase + A_BYTES;

        uint32_t a[2][4];
        uint32_t b[8][2];
#pragma unroll
        for (int mi = 0; mi < 2; mi++) {
            int row = wm * 32 + mi * 16 + lr;
            uint32_t addr = aBase + (row * HW16 + ((ch ^ xa) << 3)) * 2;
            asm volatile("ldmatrix.sync.aligned.m8n8.x4.shared.b16 {%0,%1,%2,%3}, [%4];"
                         : "=r"(a[mi][0]), "=r"(a[mi][1]), "=r"(a[mi][2]), "=r"(a[mi][3])
                         : "r"(addr));
        }
        {
            uint32_t baddr = bBase + ((wn * 64 + brow) * HW16 + (bchunk << 3)) * 2;
#pragma unroll
            for (int ni = 0; ni < 8; ni++) {
                asm volatile("ldmatrix.sync.aligned.m8n8.x2.shared.b16 {%0,%1}, [%2];"
                             : "=r"(b[ni][0]), "=r"(b[ni][1])
                             : "r"(baddr + ni * 256));
            }
        }
#pragma unroll
        for (int mi = 0; mi < 2; mi++)
#pragma unroll
            for (int ni = 0; ni < 8; ni++) {
                asm volatile(
                    "mma.sync.aligned.m16n8k16.row.col.f32.bf16.bf16.f32 "
                    "{%0,%1,%2,%3}, {%4,%5,%6,%7}, {%8,%9}, {%0,%1,%2,%3};"
                    : "+f"(acc[mi][ni][0]), "+f"(acc[mi][ni][1]),
                      "+f"(acc[mi][ni][2]), "+f"(acc[mi][ni][3])
                    : "r"(a[mi][0]), "r"(a[mi][1]), "r"(a[mi][2]), "r"(a[mi][3]),
                      "r"(b[ni][0]), "r"(b[ni][1]));
            }
    }
#undef ISSUE

    const int r = lane >> 2;
    const int c = (lane & 3) * 2;
#pragma unroll
    for (int mi = 0; mi < 2; mi++) {
#pragma unroll
        for (int ni = 0; ni < 8; ni++) {
            int n = n0 + wn * 64 + ni * 8 + c;
            if (n >= N) continue;
            float bia0 = 0.f, bia1 = 0.f, sc0 = 1.f, sc1 = 1.f, sh0 = 0.f, sh1 = 0.f;
            bool n1ok = (n + 1 < N);
            if (bias)  { bia0 = bias[n]; if (n1ok) bia1 = bias[n + 1]; }
            if (scale) { sc0 = scale[n]; sh0 = shift[n];
                         if (n1ok) { sc1 = scale[n + 1]; sh1 = shift[n + 1]; } }
#pragma unroll
            for (int half = 0; half < 2; half++) {
                int m = m0 + wm * 32 + mi * 16 + half * 8 + r;
                if (m >= M) continue;
                float v0 = acc[mi][ni][half * 2 + 0] + bia0;
                float v1 = acc[mi][ni][half * 2 + 1] + bia1;
                if (scale) { v0 = v0 * sc0 + sh0; v1 = v1 * sc1 + sh1; }
                if (relu)  { v0 = fmaxf(v0, 0.f); v1 = fmaxf(v1, 0.f); }
                float* p = C + (size_t)m * N + n;
                p[0] = v0;
                if (n1ok) p[1] = v1;
                if (hs_out && n1ok) write_split_pair(hs_out, m, n, v0, v1);
            }
        }
    }
}

// ---------------- tensor GEMM B: 64 x 640 tile, fused GRU / tail ------------
// mode 1: C[m,600] = A@B^T + bias
// mode 2: gh = A@B^T + bias, fused GRU -> h (+ optional hs split)
// mode 3: gh = A@B^T + bias, fused GRU -> bn2+relu -> pool atomics (no h write)
#define T64S        4
#define T64_A_B     (64 * 32)                 // 2048
#define T64_B_B     (640 * 32)                // 20480
#define T64_ST_B    (T64_A_B + T64_B_B)       // 22528
#define T64_EPI_STR 608
#define T64_EPI_B   (64 * T64_EPI_STR * 4)    // 155648
#define T64_SMEM    (T64_EPI_B + 64)

__global__ void __launch_bounds__(512, 1)
k_tg64(const __nv_bfloat16* __restrict__ A, const __nv_bfloat16* __restrict__ B,
       int NPADB, const float* __restrict__ bias,
       float* __restrict__ C,
       const float* __restrict__ gi_in, float* __restrict__ h_io,
       __nv_bfloat16* __restrict__ hs_out, int mode, int do_split) {
    extern __shared__ __align__(128) __nv_bfloat16 dsm[];

    const int tid  = threadIdx.x;
    const int warp = tid >> 5, lane = tid & 31;
    const int wm = warp & 1, wn = warp >> 1;       // 2 x 8
    const int m0 = blockIdx.y * 64;

    const uint32_t smem_base = (uint32_t)__cvta_generic_to_shared(dsm);
    const uint32_t mbar_base = smem_base + T64_EPI_B;

    if (tid == 0) {
        for (int s = 0; s < T64S; s++)
            asm volatile("mbarrier.init.shared.b64 [%0], 1;" :: "r"(mbar_base + s * 8) : "memory");
        asm volatile("fence.proxy.async.shared::cta;" ::: "memory");
    }
    __syncthreads();

    float acc[2][10][4];
#pragma unroll
    for (int mi = 0; mi < 2; mi++)
#pragma unroll
        for (int ni = 0; ni < 10; ni++)
#pragma unroll
            for (int j = 0; j < 4; j++) acc[mi][ni][j] = 0.f;

#define ISSUE64(kf)                                                              \
    do {                                                                         \
        int slot_ = (kf) % T64S;                                                 \
        uint32_t mb_ = mbar_base + slot_ * 8;                                    \
        asm volatile("mbarrier.arrive.expect_tx.shared.b64 _, [%0], %1;"         \
                     :: "r"(mb_), "r"((uint32_t)T64_ST_B) : "memory");           \
        uint32_t da_ = smem_base + slot_ * T64_ST_B;                             \
        const __nv_bfloat16* sa_ = A + ((size_t)(kf) * MPAD + m0) * HW16;        \
        asm volatile("cp.async.bulk.shared::cta.global.mbarrier::complete_tx::bytes " \
                     "[%0], [%1], %2, [%3];"                                     \
                     :: "r"(da_), "l"(sa_), "r"((uint32_t)T64_A_B), "r"(mb_)     \
                     : "memory");                                                \
        uint32_t db_ = da_ + T64_A_B;                                            \
        const __nv_bfloat16* sb_ = B + (size_t)(kf) * NPADB * HW16;              \
        asm volatile("cp.async.bulk.shared::cta.global.mbarrier::complete_tx::bytes " \
                     "[%0], [%1], %2, [%3];"                                     \
                     :: "r"(db_), "l"(sb_), "r"((uint32_t)T64_B_B), "r"(mb_)     \
                     : "memory");                                                \
    } while (0)

    if (tid == 0)
        for (int kf = 0; kf < T64S - 1 && kf < NSTEP; kf++) ISSUE64(kf);

    const int lr = lane & 15;
    const int ch = lane >> 4;
    const int xa = (lane >> 2) & 1;
    const int brow   = (lane & 7);
    const int bchunk = ((lane >> 3) & 1) ^ ((lane >> 2) & 1);

    for (int ks = 0; ks < NSTEP; ks++) {
        __syncthreads();
        if (tid == 0) {
            int kf = ks + T64S - 1;
            if (kf < NSTEP) ISSUE64(kf);
        }
        const int slot = ks % T64S;
        const uint32_t mb = mbar_base + slot * 8;
        const uint32_t parity = (uint32_t)((ks / T64S) & 1);
        {
            uint32_t done = 0;
            while (!done) {
                asm volatile(
                    "{\n\t.reg .pred p;\n\t"
                    "mbarrier.try_wait.parity.acquire.cta.shared::cta.b64 p, [%1], %2;\n\t"
                    "selp.b32 %0, 1, 0, p;\n\t}"
                    : "=r"(done) : "r"(mb), "r"(parity) : "memory");
            }
        }

        const uint32_t aBase = smem_base + slot * T64_ST_B;
        const uint32_t bBase = aBase + T64_A_B;

        uint32_t a[2][4];
        uint32_t b[10][2];
#pragma unroll
        for (int mi = 0; mi < 2; mi++) {
            int row = wm * 32 + mi * 16 + lr;
            uint32_t addr = aBase + (row * HW16 + ((ch ^ xa) << 3)) * 2;
            asm volatile("ldmatrix.sync.aligned.m8n8.x4.shared.b16 {%0,%1,%2,%3}, [%4];"
                         : "=r"(a[mi][0]), "=r"(a[mi][1]), "=r"(a[mi][2]), "=r"(a[mi][3])
                         : "r"(addr));
        }
        {
            uint32_t baddr = bBase + ((wn * 80 + brow) * HW16 + (bchunk << 3)) * 2;
#pragma unroll
            for (int ni = 0; ni < 10; ni++) {
                asm volatile("ldmatrix.sync.aligned.m8n8.x2.shared.b16 {%0,%1}, [%2];"
                             : "=r"(b[ni][0]), "=r"(b[ni][1])
                             : "r"(baddr + ni * 256));
            }
        }
#pragma unroll
        for (int mi = 0; mi < 2; mi++)
#pragma unroll
            for (int ni = 0; ni < 10; ni++) {
                asm volatile(
                    "mma.sync.aligned.m16n8k16.row.col.f32.bf16.bf16.f32 "
                    "{%0,%1,%2,%3}, {%4,%5,%6,%7}, {%8,%9}, {%0,%1,%2,%3};"
                    : "+f"(acc[mi][ni][0]), "+f"(acc[mi][ni][1]),
                      "+f"(acc[mi][ni][2]), "+f"(acc[mi][ni][3])
                    : "r"(a[mi][0]), "r"(a[mi][1]), "r"(a[mi][2]), "r"(a[mi][3]),
                      "r"(b[ni][0]), "r"(b[ni][1]));
            }
    }
#undef ISSUE64

    const int r = lane >> 2;
    const int c = (lane & 3) * 2;

    if (mode == 1) {
#pragma unroll
        for (int mi = 0; mi < 2; mi++)
#pragma unroll
            for (int ni = 0; ni < 10; ni++) {
                int n = wn * 80 + ni * 8 + c;
                if (n >= H3) continue;
                float bia0 = bias ? bias[n] : 0.f;
                float bia1 = bias ? bias[n + 1] : 0.f;
#pragma unroll
                for (int half = 0; half < 2; half++) {
                    int m = m0 + wm * 32 + mi * 16 + half * 8 + r;
                    if (m >= NN) continue;
                    float* p = C + (size_t)m * H3 + n;
                    p[0] = acc[mi][ni][half * 2 + 0] + bia0;
                    p[1] = acc[mi][ni][half * 2 + 1] + bia1;
                }
            }
        return;
    }

    // modes 2/3: stage gh = acc + bhh to smem, then fused GRU (+tail)
    __syncthreads();
    float* sg = (float*)dsm;
#pragma unroll
    for (int mi = 0; mi < 2; mi++)
#pragma unroll
        for (int ni = 0; ni < 10; ni++) {
            int n = wn * 80 + ni * 8 + c;
            if (n >= H3) continue;
            float bia0 = bias[n], bia1 = bias[n + 1];
#pragma unroll
            for (int half = 0; half < 2; half++) {
                int row = wm * 32 + mi * 16 + half * 8 + r;
                sg[row * T64_EPI_STR + n]     = acc[mi][ni][half * 2 + 0] + bia0;
                sg[row * T64_EPI_STR + n + 1] = acc[mi][ni][half * 2 + 1] + bia1;
            }
        }
    __syncthreads();

    for (int task = tid; task < 64 * 50; task += 512) {
        int row = task / 50;
        int m = m0 + row;
        if (m >= NN) continue;
        int jc = task - row * 50;
        int j = jc * 4;
        const float* gi = gi_in + (size_t)m * H3;
        float4 ir4 = *(const float4*)(gi + j);
        float4 iz4 = *(const float4*)(gi + j + 200);
        float4 in4 = *(const float4*)(gi + j + 400);
        const float* sgr = sg + row * T64_EPI_STR;
        float4 hr4 = *(const float4*)(sgr + j);
        float4 hz4 = *(const float4*)(sgr + j + 200);
        float4 hn4 = *(const float4*)(sgr + j + 400);
        float* hp = h_io + (size_t)m * HID + j;
        float4 h4 = *(float4*)hp;

        float hv[4];
        const float ir[4] = {ir4.x, ir4.y, ir4.z, ir4.w};
        const float iz[4] = {iz4.x, iz4.y, iz4.z, iz4.w};
        const float in_[4] = {in4.x, in4.y, in4.z, in4.w};
        const float hr[4] = {hr4.x, hr4.y, hr4.z, hr4.w};
        const float hz[4] = {hz4.x, hz4.y, hz4.z, hz4.w};
        const float hn[4] = {hn4.x, hn4.y, hn4.z, hn4.w};
        const float ho[4] = {h4.x, h4.y, h4.z, h4.w};
#pragma unroll
        for (int i = 0; i < 4; i++) {
            float rr = 1.f / (1.f + expf(-(ir[i] + hr[i])));
            float zz = 1.f / (1.f + expf(-(iz[i] + hz[i])));
            float nn = tanhf(in_[i] + rr * hn[i]);
            hv[i] = (1.f - zz) * nn + zz * ho[i];
        }

        if (mode == 2) {
            *(float4*)hp = make_float4(hv[0], hv[1], hv[2], hv[3]);
            if (do_split) {
                write_split_pair(hs_out, m, j,     hv[0], hv[1]);
                write_split_pair(hs_out, m, j + 2, hv[2], hv[3]);
            }
        } else {
            int b = g_batch[m];
            float* mp = &g_pool[b * 400 + j];
            int*   xp = (int*)&g_pool[b * 400 + 200 + j];
#pragma unroll
            for (int i = 0; i < 4; i++) {
                int jj = j + i;
                float v = fmaxf(hv[i] * g_scale[HID + jj] + g_shift[HID + jj], 0.f);
                atomicAdd(mp + i, v);
                atomicMax(xp + i, __float_as_int(v));
            }
            if (jc == 0) atomicAdd(&g_cnt[b], 1.0f);
        }
    }
}

// ---------------- small SIMT GEMM (fc1/fc2/Wc precompute) -------------------
#define BM 64
#define BN 64
#define BK 16
__global__ void k_gemm(const float* __restrict__ A, const float* __restrict__ B,
                       float* __restrict__ C, int M, int N, int K, int transB,
                       const float* __restrict__ bias,
                       const float* __restrict__ scale,
                       const float* __restrict__ shift, int relu) {
    __shared__ float As[BK][BM];
    __shared__ float Bs[BK][BN + 4];
    const int m0 = blockIdx.y * BM;
    const int n0 = blockIdx.x * BN;
    const int tid = threadIdx.x;
    const int tm = tid >> 4;
    const int tn = tid & 15;
    float acc[4][4];
#pragma unroll
    for (int i = 0; i < 4; i++)
#pragma unroll
        for (int j = 0; j < 4; j++) acc[i][j] = 0.f;

    for (int k0 = 0; k0 < K; k0 += BK) {
        {
            int ar = tid >> 2;
            int ac = (tid & 3) * 4;
            int m = m0 + ar;
#pragma unroll
            for (int i = 0; i < 4; i++) {
                int k = k0 + ac + i;
                As[ac + i][ar] = (m < M && k < K) ? A[(size_t)m * K + k] : 0.f;
            }
        }
        if (!transB) {
            int br = tid >> 4;
            int bc = (tid & 15) * 4;
            int k = k0 + br;
#pragma unroll
            for (int i = 0; i < 4; i++) {
                int n = n0 + bc + i;
                Bs[br][bc + i] = (k < K && n < N) ? B[(size_t)k * N + n] : 0.f;
            }
        } else {
            int br = tid >> 2;
            int bc = (tid & 3) * 4;
            int n = n0 + br;
#pragma unroll
            for (int i = 0; i < 4; i++) {
                int k = k0 + bc + i;
                Bs[bc + i][br] = (n < N && k < K) ? B[(size_t)n * K + k] : 0.f;
            }
        }
        __syncthreads();
#pragma unroll
        for (int k = 0; k < BK; k++) {
            float a[4], b[4];
#pragma unroll
            for (int i = 0; i < 4; i++) a[i] = As[k][tm * 4 + i];
#pragma unroll
            for (int j = 0; j < 4; j++) b[j] = Bs[k][tn * 4 + j];
#pragma unroll
            for (int i = 0; i < 4; i++)
#pragma unroll
                for (int j = 0; j < 4; j++) acc[i][j] += a[i] * b[j];
        }
        __syncthreads();
    }
#pragma unroll
    for (int i = 0; i < 4; i++) {
        int m = m0 + tm * 4 + i;
        if (m >= M) continue;
#pragma unroll
        for (int j = 0; j < 4; j++) {
            int n = n0 + tn * 4 + j;
            if (n >= N) continue;
            float v = acc[i][j];
            if (bias)  v += bias[n];
            if (scale) v = v * scale[n] + shift[n];
            if (relu)  v = fmaxf(v, 0.f);
            C[(size_t)m * N + n] = v;
        }
    }
}

// ---------------- zero helper ----------------
__global__ void k_zero(float* __restrict__ p, int n) {
    int i = blockIdx.x * blockDim.x + threadIdx.x;
    if (i < n) p[i] = 0.f;
}

__global__ void k_pool_fin() {
    int idx = blockIdx.x * blockDim.x + threadIdx.x;
    if (idx >= NG * HID) return;
    int g = idx / HID;
    int j = idx - g * HID;
    g_pool[g * 400 + j] *= 1.f / fmaxf(g_cnt[g], 1.f);
}

// ---------------- host launch ----------------
static inline int cdiv(int a, int b) { return (a + b - 1) / b; }

extern "C" void kernel_launch(void* const* d_in, const int* in_sizes, int n_in,
                              void* d_out, int out_size) {
    static bool init = false;
    static float *p_h, *p_gi, *p_pool, *p_cnt, *p_fc1, *p_scale, *p_shift;
    static int *p_deg, *p_tmp;
    static __nv_bfloat16 *p_xs, *p_hs, *p_as, *p_Bproj, *p_BWc, *p_Bwhh;
    if (!init) {
        cudaGetSymbolAddress((void**)&p_h, g_h);
        cudaGetSymbolAddress((void**)&p_gi, g_gi);
        cudaGetSymbolAddress((void**)&p_pool, g_pool);
        cudaGetSymbolAddress((void**)&p_cnt, g_cnt);
        cudaGetSymbolAddress((void**)&p_fc1, g_fc1);
        cudaGetSymbolAddress((void**)&p_scale, g_scale);
        cudaGetSymbolAddress((void**)&p_shift, g_shift);
        cudaGetSymbolAddress((void**)&p_deg, g_deg);
        cudaGetSymbolAddress((void**)&p_tmp, g_tmp);
        cudaGetSymbolAddress((void**)&p_xs, g_xs);
        cudaGetSymbolAddress((void**)&p_hs, g_hs);
        cudaGetSymbolAddress((void**)&p_as, g_as);
        cudaGetSymbolAddress((void**)&p_Bproj, g_Bproj);
        cudaGetSymbolAddress((void**)&p_BWc, g_BWc);
        cudaGetSymbolAddress((void**)&p_Bwhh, g_Bwhh);
        cudaFuncSetAttribute(k_tgemm, cudaFuncAttributeMaxDynamicSharedMemorySize, SMEM_DYN);
        cudaFuncSetAttribute(k_tg64, cudaFuncAttributeMaxDynamicSharedMemorySize, T64_SMEM);
        init = true;
    }

    const float *x, *projW, *projb;
    const void  *edge, *batch;
    const float *bn1g, *bn1b, *bn1m, *bn1v;
    const float *bn2g, *bn2b, *bn2m, *bn2v;
    const float *bnfg, *bnfb, *bnfm, *bnfv;
    const float *ggcW, *wih, *whh, *bih, *bhh, *fc1W, *fc1b, *fc2W, *fc2b;

    x     = (const float*)d_in[0];
    edge  = d_in[1];
    batch = d_in[2];
    projW = (const float*)d_in[3];
    projb = (const float*)d_in[4];
    bn1g = (const float*)d_in[5]; bn1b = (const float*)d_in[6];
    bn1m = (const float*)d_in[7]; bn1v = (const float*)d_in[8];

    if (in_sizes[9] == 120000) {
        ggcW = (const float*)d_in[9];
        wih  = (const float*)d_in[10]; whh = (const float*)d_in[11];
        bih  = (const float*)d_in[12]; bhh = (const float*)d_in[13];
        bn2g = (const float*)d_in[14]; bn2b = (const float*)d_in[15];
        bn2m = (const float*)d_in[16]; bn2v = (const float*)d_in[17];
        fc1W = (const float*)d_in[18]; fc1b = (const float*)d_in[19];
        bnfg = (const float*)d_in[20]; bnfb = (const float*)d_in[21];
        bnfm = (const float*)d_in[22]; bnfv = (const float*)d_in[23];
        fc2W = (const float*)d_in[24]; fc2b = (const float*)d_in[25];
    } else {
        bn2g = (const float*)d_in[9];  bn2b = (const float*)d_in[10];
        bn2m = (const float*)d_in[11]; bn2v = (const float*)d_in[12];
        bnfg = (const float*)d_in[13]; bnfb = (const float*)d_in[14];
        bnfm = (const float*)d_in[15]; bnfv = (const float*)d_in[16];
        ggcW = (const float*)d_in[17];
        wih  = (const float*)d_in[18]; whh = (const float*)d_in[19];
        bih  = (const float*)d_in[20]; bhh = (const float*)d_in[21];
        fc1W = (const float*)d_in[22]; fc1b = (const float*)d_in[23];
        fc2W = (const float*)d_in[24]; fc2b = (const float*)d_in[25];
    }

    const int T = 256;
    const int MT  = cdiv(NN, 128);   // 782
    const int MT64 = cdiv(NN, 64);   // 1563

    k_splitB<<<cdiv(NSTEP * 256 * 2, T), T>>>(projW, p_Bproj, HID, 256, INDIM, 1);
    k_bnprep_all<<<1, 640>>>(bn1g, bn1b, bn1m, bn1v,
                             bn2g, bn2b, bn2m, bn2v,
                             bnfg, bnfb, bnfm, bnfv);
    k_splitA<<<cdiv(NSTEP * NN * 2, T), T>>>(x, p_xs, INDIM);
    // h = relu(bn1(x @ projW^T + projb)); epilogue also writes hs split
    k_tgemm<<<dim3(1, MT), 512, SMEM_DYN>>>(p_xs, p_Bproj, p_h, NN, HID, 256,
                                            projb, p_scale, p_shift, 1, p_hs);

    // Wc_i = ggcW_i @ wih^T folded weights
    for (int i = 0; i < 3; i++) {
        k_gemm<<<dim3(cdiv(HID, BN), cdiv(H3, BM)), T>>>(
            wih, ggcW + (size_t)i * HID * HID, p_gi, H3, HID, HID, 1,
            nullptr, nullptr, nullptr, 0);
        k_splitB<<<cdiv(NSTEP * 640 * 2, T), T>>>(p_gi, p_BWc + (size_t)i * NSTEP * 640 * HW16,
                                                  H3, 640, HID, 1);
    }

    // edge preprocessing + CSR build (once)
    k_detect<<<1, 32>>>((const int*)edge, (const int*)batch);
    k_conv_edges<<<cdiv(2 * NE, T), T>>>(edge);
    k_conv_batch<<<cdiv(NN, T), T>>>(batch);
    k_zero<<<cdiv(NN, T), T>>>((float*)p_deg, NN);
    k_hist<<<cdiv(NE, T), T>>>();
    k_scan<<<1, 1024>>>();
    k_zero<<<cdiv(NN, T), T>>>((float*)p_tmp, NN);
    k_fill<<<cdiv(NE, T), T>>>();

    k_splitB<<<cdiv(NSTEP * 768 * 2, T), T>>>(whh, p_Bwhh, H3, 768, HID, 1);

    // pool buffers zeroed before the loop (mode-3 tail writes them)
    k_zero<<<cdiv(NG * 400, T), T>>>(p_pool, NG * 400);
    k_zero<<<cdiv(NG, T), T>>>(p_cnt, NG);

    for (int it = 0; it < 3; it++) {
        // aggH = CSR gather-sum of h; writes bf16 split (g_as) directly
        k_agg<<<cdiv(NN * 50, T), T>>>();
        // gi = aggH @ Wc_it^T + bih
        k_tg64<<<dim3(1, MT64), 512, T64_SMEM>>>(
            p_as, p_BWc + (size_t)it * NSTEP * 640 * HW16, 640, bih,
            p_gi, nullptr, nullptr, nullptr, 1, 0);
        // gh = h @ whh^T + bhh, fused GRU; last iter also fuses bn2+relu+pool
        int mode = (it < 2) ? 2 : 3;
        k_tg64<<<dim3(1, MT64), 512, T64_SMEM>>>(p_hs, p_Bwhh, 768, bhh,
                                                 nullptr, p_gi, p_h, p_hs, mode,
                                                 it < 2 ? 1 : 0);
    }

    k_pool_fin<<<cdiv(NG * HID, T), T>>>();

    {
        dim3 grid(cdiv(HID, BN), cdiv(NG, BM));
        k_gemm<<<grid, T>>>(p_pool, fc1W, p_fc1, NG, HID, 2 * HID, 1,
                            fc1b, p_scale + 2 * HID, p_shift + 2 * HID, 1);
    }
    {
        dim3 grid(cdiv(2, BN), cdiv(NG, BM));
        k_gemm<<<grid, T>>>(p_fc1, fc2W, (float*)d_out, NG, 2, HID, 1,
                            fc2b, nullptr, nullptr, 0);
    }
}

// round 17
// speedup vs baseline: 2.2688x; 1.0283x over previous
#include <cuda_runtime.h>
#include <cuda_bf16.h>
#include <stdint.h>
#include <math.h>

#define NN    100000
#define NE    1600000
#define NG    512
#define HID   200
#define H3    600
#define INDIM 205

#define KP    208
#define K3    624
#define NSTEP 39        // logical k-steps (K3/16)
#define NPHYS 26        // physical k-blocks stored (13 hi + 13 lo); dedup of 39
#define MPAD  100096    // >= 1563*64
#define HW16  16        // halfwords per row per k-step (packed, swizzled)

// logical->physical k-step remap:
//  A layout [hi|lo|hi]: kf>=26 aliases kf-26
//  B layout [hi|hi|lo]: kf>=13 aliases kf-13 (s1==s0; s2=lo stored at 13..25)
#define APHYS(kf) ((kf) < 26 ? (kf) : (kf) - 26)
#define BPHYS(kf) ((kf) < 13 ? (kf) : (kf) - 13)

// ---------------- scratch ----------------
__device__ float g_h  [(size_t)NN * HID];
__device__ float g_gi [(size_t)NN * H3];   // head also used as Wc fp32 scratch pre-loop
__device__ float g_pool[NG * 2 * HID];
__device__ float g_cnt [NG];
__device__ float g_fc1 [NG * HID];
__device__ float g_scale[3 * HID];
__device__ float g_shift[3 * HID];
__device__ int   g_src[NE];
__device__ int   g_dst[NE];
__device__ int   g_batch[NN];
__device__ int   g_flag_e;
__device__ int   g_flag_b;
// CSR (built once; graph identical across iterations)
__device__ int   g_deg [NN];
__device__ int   g_tmp [NN];
__device__ int   g_rptr[NN + 1];
__device__ int   g_csr [NE];

// packed k-blocked bf16 buffers (NPHYS blocks), swizzle baked into gmem layout:
// element (p,row,kk) at ((p*ROWS+row)*16) + ((kk>>3) ^ ((row>>2)&1))*8 + (kk&7)
__device__ __nv_bfloat16 g_xs[(size_t)NPHYS * MPAD * HW16];
__device__ __nv_bfloat16 g_hs[(size_t)NPHYS * MPAD * HW16];
__device__ __nv_bfloat16 g_as[(size_t)NPHYS * MPAD * HW16];
__device__ __nv_bfloat16 g_Bproj[(size_t)NPHYS * 256 * HW16];
__device__ __nv_bfloat16 g_BWc [3][(size_t)NPHYS * 640 * HW16];
__device__ __nv_bfloat16 g_Bwhh[(size_t)NPHYS * 768 * HW16];

// ---------------- dtype detection ----------------
__global__ void k_detect(const int* __restrict__ ew, const int* __restrict__ bw) {
    int lane = threadIdx.x;
    int bad_e = 0, bad_b = 0;
    for (int w = 2 * NE - 255 + 2 * lane; w < 2 * NE; w += 64)
        if (ew[w] != 0) bad_e = 1;
    for (int w = NN - 255 + 2 * lane; w < NN; w += 64)
        if (bw[w] != 0) bad_b = 1;
    unsigned me = __ballot_sync(0xFFFFFFFFu, bad_e);
    unsigned mb = __ballot_sync(0xFFFFFFFFu, bad_b);
    if (lane == 0) { g_flag_e = (me == 0); g_flag_b = (mb == 0); }
}

__global__ void k_conv_edges(const void* __restrict__ e) {
    int i = blockIdx.x * blockDim.x + threadIdx.x;
    if (i >= 2 * NE) return;
    int v = g_flag_e ? (int)((const long long*)e)[i] : ((const int*)e)[i];
    if (i < NE) g_src[i] = v; else g_dst[i - NE] = v;
}

__global__ void k_conv_batch(const void* __restrict__ b) {
    int i = blockIdx.x * blockDim.x + threadIdx.x;
    if (i >= NN) return;
    g_batch[i] = g_flag_b ? (int)((const long long*)b)[i] : ((const int*)b)[i];
}

// ---------------- CSR build (once) ----------------
__global__ void k_hist() {
    int i = blockIdx.x * blockDim.x + threadIdx.x;
    if (i < NE) atomicAdd(&g_deg[g_dst[i]], 1);
}

__global__ void k_scan() {   // single block, 1024 threads
    __shared__ int buf[1024];
    __shared__ int carry;
    int tid = threadIdx.x;
    if (tid == 0) carry = 0;
    __syncthreads();
    for (int base = 0; base < NN; base += 1024) {
        int v = (base + tid < NN) ? g_deg[base + tid] : 0;
        buf[tid] = v;
        __syncthreads();
        for (int off = 1; off < 1024; off <<= 1) {
            int t = (tid >= off) ? buf[tid - off] : 0;
            __syncthreads();
            buf[tid] += t;
            __syncthreads();
        }
        if (base + tid < NN) g_rptr[base + tid] = buf[tid] - v + carry;
        __syncthreads();
        if (tid == 0) carry += buf[1023];
        __syncthreads();
    }
    if (tid == 0) g_rptr[NN] = carry;
}

__global__ void k_fill() {
    int i = blockIdx.x * blockDim.x + threadIdx.x;
    if (i >= NE) return;
    int d = g_dst[i];
    int pos = g_rptr[d] + atomicAdd(&g_tmp[d], 1);
    g_csr[pos] = g_src[i];
}

// ---------------- split-pair writer: hi at block ksl, lo at block 13+ksl ----
__device__ __forceinline__ void write_split_pair(
    __nv_bfloat16* __restrict__ hs, int m, int j /*even*/, float v0, float v1) {
    __nv_bfloat16 h0 = __float2bfloat16(v0), h1 = __float2bfloat16(v1);
    __nv_bfloat16 l0 = __float2bfloat16(v0 - __bfloat162float(h0));
    __nv_bfloat16 l1 = __float2bfloat16(v1 - __bfloat162float(h1));
    uint32_t hi2 = ((uint32_t)*(uint16_t*)&h1 << 16) | *(uint16_t*)&h0;
    uint32_t lo2 = ((uint32_t)*(uint16_t*)&l1 << 16) | *(uint16_t*)&l0;
    int c = j >> 3, ksl = c >> 1, half = c & 1, off = j & 7;
    int swz = (half ^ ((m >> 2) & 1)) << 3;
    *(uint32_t*)(hs + ((size_t)(ksl)      * MPAD + m) * HW16 + swz + off) = hi2;
    *(uint32_t*)(hs + ((size_t)(13 + ksl) * MPAD + m) * HW16 + swz + off) = lo2;
}

// ---------------- CSR gather-sum of h, fused bf16 split output --------------
__global__ void k_agg() {
    int idx = blockIdx.x * blockDim.x + threadIdx.x;
    if (idx >= NN * 50) return;
    int n = idx / 50, c = idx - n * 50;
    int e0 = g_rptr[n], e1 = g_rptr[n + 1];
    float ax = 0.f, ay = 0.f, az = 0.f, aw = 0.f;
    for (int e = e0; e < e1; e++) {
        int s = g_csr[e];
        const float4 v = *(const float4*)&g_h[(size_t)s * HID + c * 4];
        ax += v.x; ay += v.y; az += v.z; aw += v.w;
    }
    int j = c * 4;
    write_split_pair(g_as, n, j,     ax, ay);
    write_split_pair(g_as, n, j + 2, az, aw);
}

// ---------------- merged BN param prep ----------------
__global__ void k_bnprep_all(
    const float* g1, const float* b1, const float* m1, const float* v1,
    const float* g2, const float* b2, const float* m2, const float* v2,
    const float* gf, const float* bf, const float* mf, const float* vf) {
    int j = threadIdx.x;
    if (j >= 3 * HID) return;
    int which = j / HID, jj = j - which * HID;
    const float *g, *b, *m, *v;
    if (which == 0)      { g = g1; b = b1; m = m1; v = v1; }
    else if (which == 1) { g = g2; b = b2; m = m2; v = v2; }
    else                 { g = gf; b = bf; m = mf; v = vf; }
    float s = g[jj] * rsqrtf(v[jj] + 1e-5f);
    g_scale[j] = s;
    g_shift[j] = b[jj] - m[jj] * s;
}

// ---------------- bf16 split of activations (26 physical blocks) ------------
// phys block p: p<13 -> hi values, p>=13 -> lo values; chunk c = (p%13)*2+half
__global__ void k_splitA(const float* __restrict__ in, __nv_bfloat16* __restrict__ out,
                         int K) {
    int idx = blockIdx.x * blockDim.x + threadIdx.x;
    if (idx >= NPHYS * NN * 2) return;
    int p    = idx / (NN * 2);
    int rem  = idx - p * (NN * 2);
    int m    = rem >> 1;
    int half = rem & 1;
    int lo_sec = (p >= 13);
    int c  = (p - lo_sec * 13) * 2 + half;   // 0..25
    int k0 = c * 8;
    const float* src = in + (size_t)m * K + k0;
    __nv_bfloat16 o[8];
#pragma unroll
    for (int i = 0; i < 8; i++) {
        float v = (k0 + i < K) ? src[i] : 0.f;
        __nv_bfloat16 hi = __float2bfloat16(v);
        o[i] = lo_sec ? __float2bfloat16(v - __bfloat162float(hi)) : hi;
    }
    int swz = half ^ ((m >> 2) & 1);
    *(uint4*)(out + ((size_t)p * MPAD + m) * HW16 + swz * 8) = *(const uint4*)o;
}

// ---------------- bf16 split of weights (26 physical blocks) ----------------
__global__ void k_splitB(const float* __restrict__ W, __nv_bfloat16* __restrict__ out,
                         int N, int Npad, int K, int trans) {
    int idx = blockIdx.x * blockDim.x + threadIdx.x;
    if (idx >= NPHYS * Npad * 2) return;
    int p    = idx / (Npad * 2);
    int rem  = idx - p * (Npad * 2);
    int n    = rem >> 1;
    int half = rem & 1;
    int lo_sec = (p >= 13);
    int c  = (p - lo_sec * 13) * 2 + half;
    int k0 = c * 8;
    __nv_bfloat16 o[8];
#pragma unroll
    for (int i = 0; i < 8; i++) {
        int k = k0 + i;
        float v = 0.f;
        if (n < N && k < K) v = trans ? W[(size_t)n * K + k] : W[(size_t)k * N + n];
        __nv_bfloat16 hi = __float2bfloat16(v);
        o[i] = lo_sec ? __float2bfloat16(v - __bfloat162float(hi)) : hi;
    }
    int swz = half ^ ((n >> 2) & 1);
    *(uint4*)(out + ((size_t)p * Npad + n) * HW16 + swz * 8) = *(const uint4*)o;
}

// ---------------- tensor GEMM A: 128x256 tile, 512 thr ----------------------
#define STAGES       6
#define STAGE_A_HW   (128 * HW16)
#define STAGE_B_HW   (256 * HW16)
#define STAGE_HW     (STAGE_A_HW + STAGE_B_HW)
#define STAGE_BYTES  (STAGE_HW * 2)          // 12288
#define A_BYTES      (STAGE_A_HW * 2)
#define B_BYTES      (STAGE_B_HW * 2)
#define SMEM_DYN     (STAGES * STAGE_BYTES + 64)

__global__ void __launch_bounds__(512, 1)
k_tgemm(const __nv_bfloat16* __restrict__ A, const __nv_bfloat16* __restrict__ B,
        float* __restrict__ C, int M, int N, int NPADB,
        const float* __restrict__ bias,
        const float* __restrict__ scale, const float* __restrict__ shift,
        int relu, __nv_bfloat16* __restrict__ hs_out) {
    extern __shared__ __align__(128) __nv_bfloat16 dsm[];

    const int tid  = threadIdx.x;
    const int warp = tid >> 5, lane = tid & 31;
    const int wm = warp & 3, wn = warp >> 2;       // 4 x 4
    const int m0 = blockIdx.y * 128;
    const int n0 = blockIdx.x * 256;

    const uint32_t smem_base = (uint32_t)__cvta_generic_to_shared(dsm);
    const uint32_t mbar_base = smem_base + STAGES * STAGE_BYTES;

    if (tid == 0) {
        for (int s = 0; s < STAGES; s++)
            asm volatile("mbarrier.init.shared.b64 [%0], 1;" :: "r"(mbar_base + s * 8) : "memory");
        asm volatile("fence.proxy.async.shared::cta;" ::: "memory");
    }
    __syncthreads();

    float acc[2][8][4];
#pragma unroll
    for (int mi = 0; mi < 2; mi++)
#pragma unroll
        for (int ni = 0; ni < 8; ni++)
#pragma unroll
            for (int j = 0; j < 4; j++) acc[mi][ni][j] = 0.f;

#define ISSUE(kf)                                                                \
    do {                                                                         \
        int slot_ = (kf) % STAGES;                                               \
        int ap_ = APHYS(kf), bp_ = BPHYS(kf);                                    \
        uint32_t mb_ = mbar_base + slot_ * 8;                                    \
        asm volatile("mbarrier.arrive.expect_tx.shared.b64 _, [%0], %1;"         \
                     :: "r"(mb_), "r"((uint32_t)STAGE_BYTES) : "memory");        \
        uint32_t da_ = smem_base + slot_ * STAGE_BYTES;                          \
        const __nv_bfloat16* sa_ = A + ((size_t)ap_ * MPAD + m0) * HW16;         \
        asm volatile("cp.async.bulk.shared::cta.global.mbarrier::complete_tx::bytes " \
                     "[%0], [%1], %2, [%3];"                                     \
                     :: "r"(da_), "l"(sa_), "r"((uint32_t)A_BYTES), "r"(mb_)     \
                     : "memory");                                                \
        uint32_t db_ = da_ + A_BYTES;                                            \
        const __nv_bfloat16* sb_ = B + ((size_t)bp_ * NPADB + n0) * HW16;        \
        asm volatile("cp.async.bulk.shared::cta.global.mbarrier::complete_tx::bytes " \
                     "[%0], [%1], %2, [%3];"                                     \
                     :: "r"(db_), "l"(sb_), "r"((uint32_t)B_BYTES), "r"(mb_)     \
                     : "memory");                                                \
    } while (0)

    if (tid == 0)
        for (int kf = 0; kf < STAGES - 1 && kf < NSTEP; kf++) ISSUE(kf);

    const int lr = lane & 15;
    const int ch = lane >> 4;
    const int xa = (lane >> 2) & 1;
    const int brow   = (lane & 7);
    const int bchunk = ((lane >> 3) & 1) ^ ((lane >> 2) & 1);

    for (int ks = 0; ks < NSTEP; ks++) {
        __syncthreads();
        if (tid == 0) {
            int kf = ks + STAGES - 1;
            if (kf < NSTEP) ISSUE(kf);
        }
        const int slot = ks % STAGES;
        const uint32_t mb = mbar_base + slot * 8;
        const uint32_t parity = (uint32_t)((ks / STAGES) & 1);
        {
            uint32_t done = 0;
            while (!done) {
                asm volatile(
                    "{\n\t.reg .pred p;\n\t"
                    "mbarrier.try_wait.parity.acquire.cta.shared::cta.b64 p, [%1], %2;\n\t"
                    "selp.b32 %0, 1, 0, p;\n\t}"
                    : "=r"(done) : "r"(mb), "r"(parity) : "memory");
            }
        }

        const uint32_t aBase = smem_base + slot * STAGE_BYTES;
        const uint32_t bBase = aBase + A_BYTES;

        uint32_t a[2][4];
        uint32_t b[8][2];
#pragma unroll
        for (int mi = 0; mi < 2; mi++) {
            int row = wm * 32 + mi * 16 + lr;
            uint32_t addr = aBase + (row * HW16 + ((ch ^ xa) << 3)) * 2;
            asm volatile("ldmatrix.sync.aligned.m8n8.x4.shared.b16 {%0,%1,%2,%3}, [%4];"
                         : "=r"(a[mi][0]), "=r"(a[mi][1]), "=r"(a[mi][2]), "=r"(a[mi][3])
                         : "r"(addr));
        }
        {
            uint32_t baddr = bBase + ((wn * 64 + brow) * HW16 + (bchunk << 3)) * 2;
#pragma unroll
            for (int ni = 0; ni < 8; ni++) {
                asm volatile("ldmatrix.sync.aligned.m8n8.x2.shared.b16 {%0,%1}, [%2];"
                             : "=r"(b[ni][0]), "=r"(b[ni][1])
                             : "r"(baddr + ni * 256));
            }
        }
#pragma unroll
        for (int mi = 0; mi < 2; mi++)
#pragma unroll
            for (int ni = 0; ni < 8; ni++) {
                asm volatile(
                    "mma.sync.aligned.m16n8k16.row.col.f32.bf16.bf16.f32 "
                    "{%0,%1,%2,%3}, {%4,%5,%6,%7}, {%8,%9}, {%0,%1,%2,%3};"
                    : "+f"(acc[mi][ni][0]), "+f"(acc[mi][ni][1]),
                      "+f"(acc[mi][ni][2]), "+f"(acc[mi][ni][3])
                    : "r"(a[mi][0]), "r"(a[mi][1]), "r"(a[mi][2]), "r"(a[mi][3]),
                      "r"(b[ni][0]), "r"(b[ni][1]));
            }
    }
#undef ISSUE

    const int r = lane >> 2;
    const int c = (lane & 3) * 2;
#pragma unroll
    for (int mi = 0; mi < 2; mi++) {
#pragma unroll
        for (int ni = 0; ni < 8; ni++) {
            int n = n0 + wn * 64 + ni * 8 + c;
            if (n >= N) continue;
            float bia0 = 0.f, bia1 = 0.f, sc0 = 1.f, sc1 = 1.f, sh0 = 0.f, sh1 = 0.f;
            bool n1ok = (n + 1 < N);
            if (bias)  { bia0 = bias[n]; if (n1ok) bia1 = bias[n + 1]; }
            if (scale) { sc0 = scale[n]; sh0 = shift[n];
                         if (n1ok) { sc1 = scale[n + 1]; sh1 = shift[n + 1]; } }
#pragma unroll
            for (int half = 0; half < 2; half++) {
                int m = m0 + wm * 32 + mi * 16 + half * 8 + r;
                if (m >= M) continue;
                float v0 = acc[mi][ni][half * 2 + 0] + bia0;
                float v1 = acc[mi][ni][half * 2 + 1] + bia1;
                if (scale) { v0 = v0 * sc0 + sh0; v1 = v1 * sc1 + sh1; }
                if (relu)  { v0 = fmaxf(v0, 0.f); v1 = fmaxf(v1, 0.f); }
                float* p = C + (size_t)m * N + n;
                p[0] = v0;
                if (n1ok) p[1] = v1;
                if (hs_out && n1ok) write_split_pair(hs_out, m, n, v0, v1);
            }
        }
    }
}

// ---------------- tensor GEMM B: 64 x 640 tile, fused GRU / tail ------------
// mode 1: C[m,600] = A@B^T + bias
// mode 2: gh = A@B^T + bias, fused GRU -> h (+ optional hs split)
// mode 3: gh = A@B^T + bias, fused GRU -> bn2+relu -> pool atomics (no h write)
#define T64S        4
#define T64_A_B     (64 * 32)                 // 2048
#define T64_B_B     (640 * 32)                // 20480
#define T64_ST_B    (T64_A_B + T64_B_B)       // 22528
#define T64_EPI_STR 608
#define T64_EPI_B   (64 * T64_EPI_STR * 4)    // 155648
#define T64_SMEM    (T64_EPI_B + 64)

__global__ void __launch_bounds__(512, 1)
k_tg64(const __nv_bfloat16* __restrict__ A, const __nv_bfloat16* __restrict__ B,
       int NPADB, const float* __restrict__ bias,
       float* __restrict__ C,
       const float* __restrict__ gi_in, float* __restrict__ h_io,
       __nv_bfloat16* __restrict__ hs_out, int mode, int do_split) {
    extern __shared__ __align__(128) __nv_bfloat16 dsm[];

    const int tid  = threadIdx.x;
    const int warp = tid >> 5, lane = tid & 31;
    const int wm = warp & 1, wn = warp >> 1;       // 2 x 8
    const int m0 = blockIdx.y * 64;

    const uint32_t smem_base = (uint32_t)__cvta_generic_to_shared(dsm);
    const uint32_t mbar_base = smem_base + T64_EPI_B;

    if (tid == 0) {
        for (int s = 0; s < T64S; s++)
            asm volatile("mbarrier.init.shared.b64 [%0], 1;" :: "r"(mbar_base + s * 8) : "memory");
        asm volatile("fence.proxy.async.shared::cta;" ::: "memory");
    }
    __syncthreads();

    float acc[2][10][4];
#pragma unroll
    for (int mi = 0; mi < 2; mi++)
#pragma unroll
        for (int ni = 0; ni < 10; ni++)
#pragma unroll
            for (int j = 0; j < 4; j++) acc[mi][ni][j] = 0.f;

#define ISSUE64(kf)                                                              \
    do {                                                                         \
        int slot_ = (kf) % T64S;                                                 \
        int ap_ = APHYS(kf), bp_ = BPHYS(kf);                                    \
        uint32_t mb_ = mbar_base + slot_ * 8;                                    \
        asm volatile("mbarrier.arrive.expect_tx.shared.b64 _, [%0], %1;"         \
                     :: "r"(mb_), "r"((uint32_t)T64_ST_B) : "memory");           \
        uint32_t da_ = smem_base + slot_ * T64_ST_B;                             \
        const __nv_bfloat16* sa_ = A + ((size_t)ap_ * MPAD + m0) * HW16;         \
        asm volatile("cp.async.bulk.shared::cta.global.mbarrier::complete_tx::bytes " \
                     "[%0], [%1], %2, [%3];"                                     \
                     :: "r"(da_), "l"(sa_), "r"((uint32_t)T64_A_B), "r"(mb_)     \
                     : "memory");                                                \
        uint32_t db_ = da_ + T64_A_B;                                            \
        const __nv_bfloat16* sb_ = B + (size_t)bp_ * NPADB * HW16;               \
        asm volatile("cp.async.bulk.shared::cta.global.mbarrier::complete_tx::bytes " \
                     "[%0], [%1], %2, [%3];"                                     \
                     :: "r"(db_), "l"(sb_), "r"((uint32_t)T64_B_B), "r"(mb_)     \
                     : "memory");                                                \
    } while (0)

    if (tid == 0)
        for (int kf = 0; kf < T64S - 1 && kf < NSTEP; kf++) ISSUE64(kf);

    const int lr = lane & 15;
    const int ch = lane >> 4;
    const int xa = (lane >> 2) & 1;
    const int brow   = (lane & 7);
    const int bchunk = ((lane >> 3) & 1) ^ ((lane >> 2) & 1);

    for (int ks = 0; ks < NSTEP; ks++) {
        __syncthreads();
        if (tid == 0) {
            int kf = ks + T64S - 1;
            if (kf < NSTEP) ISSUE64(kf);
        }
        const int slot = ks % T64S;
        const uint32_t mb = mbar_base + slot * 8;
        const uint32_t parity = (uint32_t)((ks / T64S) & 1);
        {
            uint32_t done = 0;
            while (!done) {
                asm volatile(
                    "{\n\t.reg .pred p;\n\t"
                    "mbarrier.try_wait.parity.acquire.cta.shared::cta.b64 p, [%1], %2;\n\t"
                    "selp.b32 %0, 1, 0, p;\n\t}"
                    : "=r"(done) : "r"(mb), "r"(parity) : "memory");
            }
        }

        const uint32_t aBase = smem_base + slot * T64_ST_B;
        const uint32_t bBase = aBase + T64_A_B;

        uint32_t a[2][4];
        uint32_t b[10][2];
#pragma unroll
        for (int mi = 0; mi < 2; mi++) {
            int row = wm * 32 + mi * 16 + lr;
            uint32_t addr = aBase + (row * HW16 + ((ch ^ xa) << 3)) * 2;
            asm volatile("ldmatrix.sync.aligned.m8n8.x4.shared.b16 {%0,%1,%2,%3}, [%4];"
                         : "=r"(a[mi][0]), "=r"(a[mi][1]), "=r"(a[mi][2]), "=r"(a[mi][3])
                         : "r"(addr));
        }
        {
            uint32_t baddr = bBase + ((wn * 80 + brow) * HW16 + (bchunk << 3)) * 2;
#pragma unroll
            for (int ni = 0; ni < 10; ni++) {
                asm volatile("ldmatrix.sync.aligned.m8n8.x2.shared.b16 {%0,%1}, [%2];"
                             : "=r"(b[ni][0]), "=r"(b[ni][1])
                             : "r"(baddr + ni * 256));
            }
        }
#pragma unroll
        for (int mi = 0; mi < 2; mi++)
#pragma unroll
            for (int ni = 0; ni < 10; ni++) {
                asm volatile(
                    "mma.sync.aligned.m16n8k16.row.col.f32.bf16.bf16.f32 "
                    "{%0,%1,%2,%3}, {%4,%5,%6,%7}, {%8,%9}, {%0,%1,%2,%3};"
                    : "+f"(acc[mi][ni][0]), "+f"(acc[mi][ni][1]),
                      "+f"(acc[mi][ni][2]), "+f"(acc[mi][ni][3])
                    : "r"(a[mi][0]), "r"(a[mi][1]), "r"(a[mi][2]), "r"(a[mi][3]),
                      "r"(b[ni][0]), "r"(b[ni][1]));
            }
    }
#undef ISSUE64

    const int r = lane >> 2;
    const int c = (lane & 3) * 2;

    if (mode == 1) {
#pragma unroll
        for (int mi = 0; mi < 2; mi++)
#pragma unroll
            for (int ni = 0; ni < 10; ni++) {
                int n = wn * 80 + ni * 8 + c;
                if (n >= H3) continue;
                float bia0 = bias ? bias[n] : 0.f;
                float bia1 = bias ? bias[n + 1] : 0.f;
#pragma unroll
                for (int half = 0; half < 2; half++) {
                    int m = m0 + wm * 32 + mi * 16 + half * 8 + r;
                    if (m >= NN) continue;
                    float* p = C + (size_t)m * H3 + n;
                    p[0] = acc[mi][ni][half * 2 + 0] + bia0;
                    p[1] = acc[mi][ni][half * 2 + 1] + bia1;
                }
            }
        return;
    }

    // modes 2/3: stage gh = acc + bhh to smem, then fused GRU (+tail)
    __syncthreads();
    float* sg = (float*)dsm;
#pragma unroll
    for (int mi = 0; mi < 2; mi++)
#pragma unroll
        for (int ni = 0; ni < 10; ni++) {
            int n = wn * 80 + ni * 8 + c;
            if (n >= H3) continue;
            float bia0 = bias[n], bia1 = bias[n + 1];
#pragma unroll
            for (int half = 0; half < 2; half++) {
                int row = wm * 32 + mi * 16 + half * 8 + r;
                sg[row * T64_EPI_STR + n]     = acc[mi][ni][half * 2 + 0] + bia0;
                sg[row * T64_EPI_STR + n + 1] = acc[mi][ni][half * 2 + 1] + bia1;
            }
        }
    __syncthreads();

    for (int task = tid; task < 64 * 50; task += 512) {
        int row = task / 50;
        int m = m0 + row;
        if (m >= NN) continue;
        int jc = task - row * 50;
        int j = jc * 4;
        const float* gi = gi_in + (size_t)m * H3;
        float4 ir4 = *(const float4*)(gi + j);
        float4 iz4 = *(const float4*)(gi + j + 200);
        float4 in4 = *(const float4*)(gi + j + 400);
        const float* sgr = sg + row * T64_EPI_STR;
        float4 hr4 = *(const float4*)(sgr + j);
        float4 hz4 = *(const float4*)(sgr + j + 200);
        float4 hn4 = *(const float4*)(sgr + j + 400);
        float* hp = h_io + (size_t)m * HID + j;
        float4 h4 = *(float4*)hp;

        float hv[4];
        const float ir[4] = {ir4.x, ir4.y, ir4.z, ir4.w};
        const float iz[4] = {iz4.x, iz4.y, iz4.z, iz4.w};
        const float in_[4] = {in4.x, in4.y, in4.z, in4.w};
        const float hr[4] = {hr4.x, hr4.y, hr4.z, hr4.w};
        const float hz[4] = {hz4.x, hz4.y, hz4.z, hz4.w};
        const float hn[4] = {hn4.x, hn4.y, hn4.z, hn4.w};
        const float ho[4] = {h4.x, h4.y, h4.z, h4.w};
#pragma unroll
        for (int i = 0; i < 4; i++) {
            float rr = 1.f / (1.f + expf(-(ir[i] + hr[i])));
            float zz = 1.f / (1.f + expf(-(iz[i] + hz[i])));
            float nn = tanhf(in_[i] + rr * hn[i]);
            hv[i] = (1.f - zz) * nn + zz * ho[i];
        }

        if (mode == 2) {
            *(float4*)hp = make_float4(hv[0], hv[1], hv[2], hv[3]);
            if (do_split) {
                write_split_pair(hs_out, m, j,     hv[0], hv[1]);
                write_split_pair(hs_out, m, j + 2, hv[2], hv[3]);
            }
        } else {
            int b = g_batch[m];
            float* mp = &g_pool[b * 400 + j];
            int*   xp = (int*)&g_pool[b * 400 + 200 + j];
#pragma unroll
            for (int i = 0; i < 4; i++) {
                int jj = j + i;
                float v = fmaxf(hv[i] * g_scale[HID + jj] + g_shift[HID + jj], 0.f);
                atomicAdd(mp + i, v);
                atomicMax(xp + i, __float_as_int(v));
            }
            if (jc == 0) atomicAdd(&g_cnt[b], 1.0f);
        }
    }
}

// ---------------- small SIMT GEMM (fc1/fc2/Wc precompute) -------------------
#define BM 64
#define BN 64
#define BK 16
__global__ void k_gemm(const float* __restrict__ A, const float* __restrict__ B,
                       float* __restrict__ C, int M, int N, int K, int transB,
                       const float* __restrict__ bias,
                       const float* __restrict__ scale,
                       const float* __restrict__ shift, int relu) {
    __shared__ float As[BK][BM];
    __shared__ float Bs[BK][BN + 4];
    const int m0 = blockIdx.y * BM;
    const int n0 = blockIdx.x * BN;
    const int tid = threadIdx.x;
    const int tm = tid >> 4;
    const int tn = tid & 15;
    float acc[4][4];
#pragma unroll
    for (int i = 0; i < 4; i++)
#pragma unroll
        for (int j = 0; j < 4; j++) acc[i][j] = 0.f;

    for (int k0 = 0; k0 < K; k0 += BK) {
        {
            int ar = tid >> 2;
            int ac = (tid & 3) * 4;
            int m = m0 + ar;
#pragma unroll
            for (int i = 0; i < 4; i++) {
                int k = k0 + ac + i;
                As[ac + i][ar] = (m < M && k < K) ? A[(size_t)m * K + k] : 0.f;
            }
        }
        if (!transB) {
            int br = tid >> 4;
            int bc = (tid & 15) * 4;
            int k = k0 + br;
#pragma unroll
            for (int i = 0; i < 4; i++) {
                int n = n0 + bc + i;
                Bs[br][bc + i] = (k < K && n < N) ? B[(size_t)k * N + n] : 0.f;
            }
        } else {
            int br = tid >> 2;
            int bc = (tid & 3) * 4;
            int n = n0 + br;
#pragma unroll
            for (int i = 0; i < 4; i++) {
                int k = k0 + bc + i;
                Bs[bc + i][br] = (n < N && k < K) ? B[(size_t)n * K + k] : 0.f;
            }
        }
        __syncthreads();
#pragma unroll
        for (int k = 0; k < BK; k++) {
            float a[4], b[4];
#pragma unroll
            for (int i = 0; i < 4; i++) a[i] = As[k][tm * 4 + i];
#pragma unroll
            for (int j = 0; j < 4; j++) b[j] = Bs[k][tn * 4 + j];
#pragma unroll
            for (int i = 0; i < 4; i++)
#pragma unroll
                for (int j = 0; j < 4; j++) acc[i][j] += a[i] * b[j];
        }
        __syncthreads();
    }
#pragma unroll
    for (int i = 0; i < 4; i++) {
        int m = m0 + tm * 4 + i;
        if (m >= M) continue;
#pragma unroll
        for (int j = 0; j < 4; j++) {
            int n = n0 + tn * 4 + j;
            if (n >= N) continue;
            float v = acc[i][j];
            if (bias)  v += bias[n];
            if (scale) v = v * scale[n] + shift[n];
            if (relu)  v = fmaxf(v, 0.f);
            C[(size_t)m * N + n] = v;
        }
    }
}

// ---------------- zero helper ----------------
__global__ void k_zero(float* __restrict__ p, int n) {
    int i = blockIdx.x * blockDim.x + threadIdx.x;
    if (i < n) p[i] = 0.f;
}

__global__ void k_pool_fin() {
    int idx = blockIdx.x * blockDim.x + threadIdx.x;
    if (idx >= NG * HID) return;
    int g = idx / HID;
    int j = idx - g * HID;
    g_pool[g * 400 + j] *= 1.f / fmaxf(g_cnt[g], 1.f);
}

// ---------------- host launch ----------------
static inline int cdiv(int a, int b) { return (a + b - 1) / b; }

extern "C" void kernel_launch(void* const* d_in, const int* in_sizes, int n_in,
                              void* d_out, int out_size) {
    static bool init = false;
    static float *p_h, *p_gi, *p_pool, *p_cnt, *p_fc1, *p_scale, *p_shift;
    static int *p_deg, *p_tmp;
    static __nv_bfloat16 *p_xs, *p_hs, *p_as, *p_Bproj, *p_BWc, *p_Bwhh;
    if (!init) {
        cudaGetSymbolAddress((void**)&p_h, g_h);
        cudaGetSymbolAddress((void**)&p_gi, g_gi);
        cudaGetSymbolAddress((void**)&p_pool, g_pool);
        cudaGetSymbolAddress((void**)&p_cnt, g_cnt);
        cudaGetSymbolAddress((void**)&p_fc1, g_fc1);
        cudaGetSymbolAddress((void**)&p_scale, g_scale);
        cudaGetSymbolAddress((void**)&p_shift, g_shift);
        cudaGetSymbolAddress((void**)&p_deg, g_deg);
        cudaGetSymbolAddress((void**)&p_tmp, g_tmp);
        cudaGetSymbolAddress((void**)&p_xs, g_xs);
        cudaGetSymbolAddress((void**)&p_hs, g_hs);
        cudaGetSymbolAddress((void**)&p_as, g_as);
        cudaGetSymbolAddress((void**)&p_Bproj, g_Bproj);
        cudaGetSymbolAddress((void**)&p_BWc, g_BWc);
        cudaGetSymbolAddress((void**)&p_Bwhh, g_Bwhh);
        cudaFuncSetAttribute(k_tgemm, cudaFuncAttributeMaxDynamicSharedMemorySize, SMEM_DYN);
        cudaFuncSetAttribute(k_tg64, cudaFuncAttributeMaxDynamicSharedMemorySize, T64_SMEM);
        init = true;
    }

    const float *x, *projW, *projb;
    const void  *edge, *batch;
    const float *bn1g, *bn1b, *bn1m, *bn1v;
    const float *bn2g, *bn2b, *bn2m, *bn2v;
    const float *bnfg, *bnfb, *bnfm, *bnfv;
    const float *ggcW, *wih, *whh, *bih, *bhh, *fc1W, *fc1b, *fc2W, *fc2b;

    x     = (const float*)d_in[0];
    edge  = d_in[1];
    batch = d_in[2];
    projW = (const float*)d_in[3];
    projb = (const float*)d_in[4];
    bn1g = (const float*)d_in[5]; bn1b = (const float*)d_in[6];
    bn1m = (const float*)d_in[7]; bn1v = (const float*)d_in[8];

    if (in_sizes[9] == 120000) {
        ggcW = (const float*)d_in[9];
        wih  = (const float*)d_in[10]; whh = (const float*)d_in[11];
        bih  = (const float*)d_in[12]; bhh = (const float*)d_in[13];
        bn2g = (const float*)d_in[14]; bn2b = (const float*)d_in[15];
        bn2m = (const float*)d_in[16]; bn2v = (const float*)d_in[17];
        fc1W = (const float*)d_in[18]; fc1b = (const float*)d_in[19];
        bnfg = (const float*)d_in[20]; bnfb = (const float*)d_in[21];
        bnfm = (const float*)d_in[22]; bnfv = (const float*)d_in[23];
        fc2W = (const float*)d_in[24]; fc2b = (const float*)d_in[25];
    } else {
        bn2g = (const float*)d_in[9];  bn2b = (const float*)d_in[10];
        bn2m = (const float*)d_in[11]; bn2v = (const float*)d_in[12];
        bnfg = (const float*)d_in[13]; bnfb = (const float*)d_in[14];
        bnfm = (const float*)d_in[15]; bnfv = (const float*)d_in[16];
        ggcW = (const float*)d_in[17];
        wih  = (const float*)d_in[18]; whh = (const float*)d_in[19];
        bih  = (const float*)d_in[20]; bhh = (const float*)d_in[21];
        fc1W = (const float*)d_in[22]; fc1b = (const float*)d_in[23];
        fc2W = (const float*)d_in[24]; fc2b = (const float*)d_in[25];
    }

    const int T = 256;
    const int MT  = cdiv(NN, 128);   // 782
    const int MT64 = cdiv(NN, 64);   // 1563

    k_splitB<<<cdiv(NPHYS * 256 * 2, T), T>>>(projW, p_Bproj, HID, 256, INDIM, 1);
    k_bnprep_all<<<1, 640>>>(bn1g, bn1b, bn1m, bn1v,
                             bn2g, bn2b, bn2m, bn2v,
                             bnfg, bnfb, bnfm, bnfv);
    k_splitA<<<cdiv(NPHYS * NN * 2, T), T>>>(x, p_xs, INDIM);
    // h = relu(bn1(x @ projW^T + projb)); epilogue also writes hs split
    k_tgemm<<<dim3(1, MT), 512, SMEM_DYN>>>(p_xs, p_Bproj, p_h, NN, HID, 256,
                                            projb, p_scale, p_shift, 1, p_hs);

    // Wc_i = ggcW_i @ wih^T folded weights
    for (int i = 0; i < 3; i++) {
        k_gemm<<<dim3(cdiv(HID, BN), cdiv(H3, BM)), T>>>(
            wih, ggcW + (size_t)i * HID * HID, p_gi, H3, HID, HID, 1,
            nullptr, nullptr, nullptr, 0);
        k_splitB<<<cdiv(NPHYS * 640 * 2, T), T>>>(p_gi, p_BWc + (size_t)i * NPHYS * 640 * HW16,
                                                  H3, 640, HID, 1);
    }

    // edge preprocessing + CSR build (once)
    k_detect<<<1, 32>>>((const int*)edge, (const int*)batch);
    k_conv_edges<<<cdiv(2 * NE, T), T>>>(edge);
    k_conv_batch<<<cdiv(NN, T), T>>>(batch);
    k_zero<<<cdiv(NN, T), T>>>((float*)p_deg, NN);
    k_hist<<<cdiv(NE, T), T>>>();
    k_scan<<<1, 1024>>>();
    k_zero<<<cdiv(NN, T), T>>>((float*)p_tmp, NN);
    k_fill<<<cdiv(NE, T), T>>>();

    k_splitB<<<cdiv(NPHYS * 768 * 2, T), T>>>(whh, p_Bwhh, H3, 768, HID, 1);

    // pool buffers zeroed before the loop (mode-3 tail writes them)
    k_zero<<<cdiv(NG * 400, T), T>>>(p_pool, NG * 400);
    k_zero<<<cdiv(NG, T), T>>>(p_cnt, NG);

    for (int it = 0; it < 3; it++) {
        // aggH = CSR gather-sum of h; writes bf16 split (g_as) directly
        k_agg<<<cdiv(NN * 50, T), T>>>();
        // gi = aggH @ Wc_it^T + bih
        k_tg64<<<dim3(1, MT64), 512, T64_SMEM>>>(
            p_as, p_BWc + (size_t)it * NPHYS * 640 * HW16, 640, bih,
            p_gi, nullptr, nullptr, nullptr, 1, 0);
        // gh = h @ whh^T + bhh, fused GRU; last iter also fuses bn2+relu+pool
        int mode = (it < 2) ? 2 : 3;
        k_tg64<<<dim3(1, MT64), 512, T64_SMEM>>>(p_hs, p_Bwhh, 768, bhh,
                                                 nullptr, p_gi, p_h, p_hs, mode,
                                                 it < 2 ? 1 : 0);
    }

    k_pool_fin<<<cdiv(NG * HID, T), T>>>();

    {
        dim3 grid(cdiv(HID, BN), cdiv(NG, BM));
        k_gemm<<<grid, T>>>(p_pool, fc1W, p_fc1, NG, HID, 2 * HID, 1,
                            fc1b, p_scale + 2 * HID, p_shift + 2 * HID, 1);
    }
    {
        dim3 grid(cdiv(2, BN), cdiv(NG, BM));
        k_gemm<<<grid, T>>>(p_fc1, fc2W, (float*)d_out, NG, 2, HID, 1,
                            fc2b, nullptr, nullptr, 0);
    }
}